// round 1
// baseline (speedup 1.0000x reference)
#include <cuda_runtime.h>
#include <math.h>

#define Bb    2
#define Ss    2048
#define Dd    2048
#define Hh    32
#define KVHh  8
#define HDd   64
#define Gg    4
#define QKVN  3072          // D + 2*KVH*HD
#define Mrows (Bb*Ss)       // 4096
#define OUTOFF ((size_t)Bb*Ss*Dd)  // 8388608
#define ATT_SCALE 0.125f

// ---------------- scratch (device globals; no allocation allowed) ----------
__device__ float g_x[(size_t)Mrows*Dd];        // LN1 output
__device__ float g_qkv[(size_t)Mrows*QKVN];    // clipped qkv
__device__ float g_q[(size_t)Bb*Hh*Ss*HDd];    // roped Q, [B,H,S,HD]
__device__ float g_k[(size_t)Bb*KVHh*Ss*HDd];  // roped K, [B,KVH,S,HD]
__device__ float g_v[(size_t)Bb*KVHh*Ss*HDd];  // V,       [B,KVH,S,HD]
__device__ float g_attn[(size_t)Mrows*Dd];     // attention output [B,S,D]

// ---------------- LayerNorm ------------------------------------------------
__global__ __launch_bounds__(256) void ln_kernel(
    const float* __restrict__ in, const float* __restrict__ sc,
    float* __restrict__ out)
{
    int row = blockIdx.x;
    const float* x = in + (size_t)row * Dd;
    float s = 0.f, s2 = 0.f;
    for (int i = threadIdx.x; i < Dd; i += 256) { float v = x[i]; s += v; s2 += v*v; }
    #pragma unroll
    for (int o = 16; o; o >>= 1) {
        s  += __shfl_xor_sync(0xffffffffu, s,  o);
        s2 += __shfl_xor_sync(0xffffffffu, s2, o);
    }
    __shared__ float ws[8], ws2[8];
    int w = threadIdx.x >> 5, l = threadIdx.x & 31;
    if (l == 0) { ws[w] = s; ws2[w] = s2; }
    __syncthreads();
    if (threadIdx.x < 32) {
        s  = (l < 8) ? ws[l]  : 0.f;
        s2 = (l < 8) ? ws2[l] : 0.f;
        #pragma unroll
        for (int o = 4; o; o >>= 1) {
            s  += __shfl_xor_sync(0xffffffffu, s,  o);
            s2 += __shfl_xor_sync(0xffffffffu, s2, o);
        }
        if (l == 0) { ws[0] = s; ws2[0] = s2; }
    }
    __syncthreads();
    float mean = ws[0] * (1.f / Dd);
    float var  = ws2[0] * (1.f / Dd) - mean * mean;
    float inv  = rsqrtf(var + 1e-6f);
    float* o_ = out + (size_t)row * Dd;
    for (int i = threadIdx.x; i < Dd; i += 256)
        o_[i] = (x[i] - mean) * inv * sc[i];
}

// ---------------- SGEMM 128x128x16, 8x8 per thread -------------------------
// mode 0: C = clip(A*B, -8, 8)
// mode 1: C = A*B + resid
#define BM 128
#define BN 128
#define BK 16
__global__ __launch_bounds__(256) void sgemm_kernel(
    const float* __restrict__ A, const float* __restrict__ Bw,
    float* __restrict__ C, int M, int N, int K, int mode,
    const float* __restrict__ resid)
{
    __shared__ float As[BK][BM];
    __shared__ float Bs[BK][BN + 4];
    int row0 = blockIdx.y * BM, col0 = blockIdx.x * BN;
    int t = threadIdx.x;
    int tx = t & 15, ty = t >> 4;
    float acc[8][8];
    #pragma unroll
    for (int i = 0; i < 8; i++)
        #pragma unroll
        for (int j = 0; j < 8; j++) acc[i][j] = 0.f;

    for (int k0 = 0; k0 < K; k0 += BK) {
        #pragma unroll
        for (int i = 0; i < 2; i++) {
            int idx4 = t * 2 + i;
            int m = idx4 >> 2, kq = idx4 & 3;
            float4 v = *(const float4*)(A + (size_t)(row0 + m) * K + k0 + kq * 4);
            As[kq*4+0][m] = v.x; As[kq*4+1][m] = v.y;
            As[kq*4+2][m] = v.z; As[kq*4+3][m] = v.w;
        }
        #pragma unroll
        for (int i = 0; i < 2; i++) {
            int idx4 = t * 2 + i;
            int kr = idx4 >> 5, c4 = idx4 & 31;
            *(float4*)&Bs[kr][c4 * 4] =
                *(const float4*)(Bw + (size_t)(k0 + kr) * N + col0 + c4 * 4);
        }
        __syncthreads();
        #pragma unroll
        for (int kk = 0; kk < BK; kk++) {
            float a[8], b[8];
            *(float4*)(a)     = *(const float4*)&As[kk][ty * 8];
            *(float4*)(a + 4) = *(const float4*)&As[kk][ty * 8 + 4];
            *(float4*)(b)     = *(const float4*)&Bs[kk][tx * 8];
            *(float4*)(b + 4) = *(const float4*)&Bs[kk][tx * 8 + 4];
            #pragma unroll
            for (int i = 0; i < 8; i++)
                #pragma unroll
                for (int j = 0; j < 8; j++) acc[i][j] += a[i] * b[j];
        }
        __syncthreads();
    }
    #pragma unroll
    for (int i = 0; i < 8; i++) {
        size_t roff = (size_t)(row0 + ty * 8 + i) * N + col0 + tx * 8;
        #pragma unroll
        for (int j = 0; j < 8; j += 4) {
            float4 v;
            v.x = acc[i][j]; v.y = acc[i][j+1]; v.z = acc[i][j+2]; v.w = acc[i][j+3];
            if (mode == 0) {
                v.x = fminf(fmaxf(v.x, -8.f), 8.f);
                v.y = fminf(fmaxf(v.y, -8.f), 8.f);
                v.z = fminf(fmaxf(v.z, -8.f), 8.f);
                v.w = fminf(fmaxf(v.w, -8.f), 8.f);
            } else {
                float4 rv = *(const float4*)(resid + roff + j);
                v.x += rv.x; v.y += rv.y; v.z += rv.z; v.w += rv.w;
            }
            *(float4*)(C + roff + j) = v;
        }
    }
}

// ---------------- RoPE (double trig: safe under fast-math) -----------------
__global__ void rope_q_kernel(const int* __restrict__ pid)
{
    int idx = blockIdx.x * 256 + threadIdx.x;     // B*S*H*32
    if (idx >= Bb * Ss * Hh * 32) return;
    int i = idx & 31;
    int h = (idx >> 5) & (Hh - 1);
    int s = (idx >> 10) & (Ss - 1);
    int b = idx >> 21;
    double pos = (double)pid[b * Ss + s];
    double inv = exp(-((double)(2 * i) / 64.0) * log(500000.0));
    double ang = pos * inv;
    float c = (float)cos(ang), sn = (float)sin(ang);
    const float* src = g_qkv + (size_t)(b * Ss + s) * QKVN + h * HDd;
    float x1 = src[i], x2 = src[i + 32];
    float* dst = g_q + ((size_t)(b * Hh + h) * Ss + s) * HDd;
    dst[i]      = x1 * c - x2 * sn;
    dst[i + 32] = x2 * c + x1 * sn;
}

__global__ void rope_k_kernel(const int* __restrict__ pid)
{
    int idx = blockIdx.x * 256 + threadIdx.x;     // B*S*KVH*32
    if (idx >= Bb * Ss * KVHh * 32) return;
    int i = idx & 31;
    int kvh = (idx >> 5) & (KVHh - 1);
    int s = (idx >> 8) & (Ss - 1);
    int b = idx >> 19;
    double pos = (double)pid[b * Ss + s];
    double inv = exp(-((double)(2 * i) / 64.0) * log(500000.0));
    double ang = pos * inv;
    float c = (float)cos(ang), sn = (float)sin(ang);
    const float* src = g_qkv + (size_t)(b * Ss + s) * QKVN + Dd + kvh * HDd;
    float x1 = src[i], x2 = src[i + 32];
    float* dst = g_k + ((size_t)(b * KVHh + kvh) * Ss + s) * HDd;
    dst[i]      = x1 * c - x2 * sn;
    dst[i + 32] = x2 * c + x1 * sn;
}

__global__ void copy_v_kernel()
{
    int idx = blockIdx.x * 256 + threadIdx.x;     // B*S*KVH*HD
    if (idx >= Bb * Ss * KVHh * HDd) return;
    int d = idx & 63;
    int kvh = (idx >> 6) & (KVHh - 1);
    int s = (idx >> 9) & (Ss - 1);
    int b = idx >> 20;
    g_v[((size_t)(b * KVHh + kvh) * Ss + s) * HDd + d] =
        g_qkv[(size_t)(b * Ss + s) * QKVN + Dd + KVHh * HDd + kvh * HDd + d];
}

// ---------------- Flash attention (64x64 tiles, fp32) ----------------------
// smem: Qs[64][65] | KsPs[64][65] (K tile, reused for P) | Vs[64][64] | mask[64]
__global__ __launch_bounds__(256) void attn_kernel(const int* __restrict__ amask)
{
    extern __shared__ float sm[];
    float* Qs   = sm;                 // 64*65 = 4160
    float* KsPs = sm + 64 * 65;       // 4160
    float* Vs   = sm + 2 * 64 * 65;   // 64*64 = 4096
    int*   maskS = (int*)(sm + 2 * 64 * 65 + 64 * 64);

    int qt = blockIdx.x, h = blockIdx.y, b = blockIdx.z;
    int kvh = h >> 2;
    int q0 = qt * 64;
    int t = threadIdx.x;
    int tr = t >> 4, tc = t & 15;     // row group / col group

    const float* Qg = g_q + ((size_t)(b * Hh + h) * Ss + q0) * HDd;
    #pragma unroll
    for (int i = 0; i < 4; i++) {
        int idx4 = i * 256 + t;       // 0..1023 float4's
        int row = idx4 >> 4, c4 = idx4 & 15;
        float4 v = *(const float4*)(Qg + row * 64 + c4 * 4);
        float* dq = &Qs[row * 65 + c4 * 4];
        dq[0] = v.x; dq[1] = v.y; dq[2] = v.z; dq[3] = v.w;
    }

    float m[4], l[4], o[4][4];
    #pragma unroll
    for (int ii = 0; ii < 4; ii++) {
        m[ii] = -1e30f; l[ii] = 0.f;
        #pragma unroll
        for (int jj = 0; jj < 4; jj++) o[ii][jj] = 0.f;
    }

    const float* Kg = g_k + (size_t)(b * KVHh + kvh) * Ss * HDd;
    const float* Vg = g_v + (size_t)(b * KVHh + kvh) * Ss * HDd;

    int ktiles = qt + 1;
    for (int kt = 0; kt < ktiles; kt++) {
        int k0 = kt * 64;
        __syncthreads();  // prior tile's reads done (also guards Q load, iter 0)
        #pragma unroll
        for (int i = 0; i < 4; i++) {
            int idx4 = i * 256 + t;
            int row = idx4 >> 4, c4 = idx4 & 15;
            float4 kv = *(const float4*)(Kg + (size_t)(k0 + row) * 64 + c4 * 4);
            float* dk = &KsPs[row * 65 + c4 * 4];
            dk[0] = kv.x; dk[1] = kv.y; dk[2] = kv.z; dk[3] = kv.w;
            *(float4*)&Vs[row * 64 + c4 * 4] =
                *(const float4*)(Vg + (size_t)(k0 + row) * 64 + c4 * 4);
        }
        if (t < 64) maskS[t] = amask[b * Ss + k0 + t];
        __syncthreads();

        // ---- S = Q K^T (4x4 micro-tile, strided lanes: conflict-free) ----
        float sc[4][4];
        #pragma unroll
        for (int ii = 0; ii < 4; ii++)
            #pragma unroll
            for (int jj = 0; jj < 4; jj++) sc[ii][jj] = 0.f;
        #pragma unroll 4
        for (int d = 0; d < 64; d++) {
            float qv[4], kv[4];
            #pragma unroll
            for (int ii = 0; ii < 4; ii++) qv[ii] = Qs[(tr + 16 * ii) * 65 + d];
            #pragma unroll
            for (int jj = 0; jj < 4; jj++) kv[jj] = KsPs[(tc + 16 * jj) * 65 + d];
            #pragma unroll
            for (int ii = 0; ii < 4; ii++)
                #pragma unroll
                for (int jj = 0; jj < 4; jj++) sc[ii][jj] += qv[ii] * kv[jj];
        }
        // ---- scale + causal/attention mask ----
        #pragma unroll
        for (int ii = 0; ii < 4; ii++) {
            int qg = q0 + tr + 16 * ii;
            #pragma unroll
            for (int jj = 0; jj < 4; jj++) {
                int kg = k0 + tc + 16 * jj;
                float x = sc[ii][jj] * ATT_SCALE;
                if (kg > qg || maskS[tc + 16 * jj] == 0) x = -1e30f;
                sc[ii][jj] = x;
            }
        }
        // ---- online softmax update ----
        #pragma unroll
        for (int ii = 0; ii < 4; ii++) {
            float mt = fmaxf(fmaxf(sc[ii][0], sc[ii][1]),
                             fmaxf(sc[ii][2], sc[ii][3]));
            #pragma unroll
            for (int off = 1; off < 16; off <<= 1)
                mt = fmaxf(mt, __shfl_xor_sync(0xffffffffu, mt, off));
            float mn = fmaxf(m[ii], mt);
            float rs = 0.f;
            #pragma unroll
            for (int jj = 0; jj < 4; jj++) {
                float p = expf(sc[ii][jj] - mn);
                sc[ii][jj] = p;
                rs += p;
            }
            #pragma unroll
            for (int off = 1; off < 16; off <<= 1)
                rs += __shfl_xor_sync(0xffffffffu, rs, off);
            float alpha = expf(m[ii] - mn);
            l[ii] = l[ii] * alpha + rs;
            m[ii] = mn;
            #pragma unroll
            for (int jj = 0; jj < 4; jj++) o[ii][jj] *= alpha;
        }
        __syncthreads();  // all QK reads of K tile done
        // ---- write P over K buffer ----
        #pragma unroll
        for (int ii = 0; ii < 4; ii++)
            #pragma unroll
            for (int jj = 0; jj < 4; jj++)
                KsPs[(tr + 16 * ii) * 65 + tc + 16 * jj] = sc[ii][jj];
        __syncthreads();
        // ---- O += P V ----
        #pragma unroll 4
        for (int k = 0; k < 64; k++) {
            float pv[4], vv[4];
            #pragma unroll
            for (int ii = 0; ii < 4; ii++) pv[ii] = KsPs[(tr + 16 * ii) * 65 + k];
            #pragma unroll
            for (int jj = 0; jj < 4; jj++) vv[jj] = Vs[k * 64 + tc + 16 * jj];
            #pragma unroll
            for (int ii = 0; ii < 4; ii++)
                #pragma unroll
                for (int jj = 0; jj < 4; jj++) o[ii][jj] += pv[ii] * vv[jj];
        }
    }
    // ---- normalize + store [B,S,H,HD] = [B,S,D] ----
    #pragma unroll
    for (int ii = 0; ii < 4; ii++) {
        float invl = (l[ii] > 0.f) ? (1.f / l[ii]) : 0.f;
        int q = q0 + tr + 16 * ii;
        float* dst = g_attn + (size_t)(b * Ss + q) * Dd + h * HDd;
        #pragma unroll
        for (int jj = 0; jj < 4; jj++)
            dst[tc + 16 * jj] = o[ii][jj] * invl;
    }
}

// ---------------- launch ----------------------------------------------------
extern "C" void kernel_launch(void* const* d_in, const int* in_sizes, int n_in,
                              void* d_out, int out_size)
{
    const float* hs   = (const float*)d_in[0];  // hidden_states [B,S,D]
    const int*   am   = (const int*)  d_in[1];  // attention_mask [B,S]
    const int*   pid  = (const int*)  d_in[2];  // position_ids [B,S]
    // d_in[3] = causal_mask (bool) — recomputed arithmetically
    const float* ln1  = (const float*)d_in[4];
    const float* wqkv = (const float*)d_in[5];  // [D, 3072]
    const float* wout = (const float*)d_in[6];  // [D, D]
    const float* ln2  = (const float*)d_in[7];
    float* out = (float*)d_out;

    float *px, *pqkv, *pattn;
    cudaGetSymbolAddress((void**)&px,    g_x);
    cudaGetSymbolAddress((void**)&pqkv,  g_qkv);
    cudaGetSymbolAddress((void**)&pattn, g_attn);

    const int ATTN_SMEM = (2 * 64 * 65 + 64 * 64) * 4 + 64 * 4;  // 49920 B
    cudaFuncSetAttribute(attn_kernel,
                         cudaFuncAttributeMaxDynamicSharedMemorySize, ATTN_SMEM);

    // 1. x = LN1(hidden)
    ln_kernel<<<Mrows, 256>>>(hs, ln1, px);
    // 2. qkv = clip(x @ w_qkv)
    sgemm_kernel<<<dim3(QKVN / BN, Mrows / BM), 256>>>(
        px, wqkv, pqkv, Mrows, QKVN, Dd, 0, nullptr);
    // 3. RoPE + layout transform
    rope_q_kernel<<<(Bb * Ss * Hh * 32) / 256, 256>>>(pid);
    rope_k_kernel<<<(Bb * Ss * KVHh * 32) / 256, 256>>>(pid);
    copy_v_kernel<<<(Bb * Ss * KVHh * HDd) / 256, 256>>>();
    // 4. attention
    attn_kernel<<<dim3(Ss / 64, Hh, Bb), 256, ATTN_SMEM>>>(am);
    // 5. residual2 = attn @ w_out + hidden  -> d_out[0:B*S*D]
    sgemm_kernel<<<dim3(Dd / BN, Mrows / BM), 256>>>(
        pattn, wout, out, Mrows, Dd, Dd, 1, hs);
    // 6. hidden = LN2(residual2)            -> d_out[B*S*D:]
    ln_kernel<<<Mrows, 256>>>(out, ln2, out + OUTOFF);
}

// round 2
// speedup vs baseline: 2.8758x; 2.8758x over previous
#include <cuda_runtime.h>
#include <math.h>
#include <stdint.h>

#define Bb    2
#define Ss    2048
#define Dd    2048
#define Hh    32
#define KVHh  8
#define HDd   64
#define QKVN  3072          // D + 2*KVH*HD
#define Mrows (Bb*Ss)       // 4096
#define OUTOFF ((size_t)Bb*Ss*Dd)
#define ATT_SCALE 0.125f

// ---------------- scratch ----------------------------------------------------
__device__ float g_x[(size_t)Mrows*Dd];
__device__ float g_qkv[(size_t)Mrows*QKVN];
__device__ float g_q[(size_t)Bb*Hh*Ss*HDd];
__device__ float g_k[(size_t)Bb*KVHh*Ss*HDd];
__device__ float g_v[(size_t)Bb*KVHh*Ss*HDd];
__device__ float g_attn[(size_t)Mrows*Dd];
__device__ float g_cos[(size_t)Bb*Ss*32];
__device__ float g_sin[(size_t)Bb*Ss*32];

// ---------------- LayerNorm --------------------------------------------------
__global__ __launch_bounds__(256) void ln_kernel(
    const float* __restrict__ in, const float* __restrict__ sc,
    float* __restrict__ out)
{
    int row = blockIdx.x;
    const float* x = in + (size_t)row * Dd;
    float s = 0.f, s2 = 0.f;
    for (int i = threadIdx.x; i < Dd; i += 256) { float v = x[i]; s += v; s2 += v*v; }
    #pragma unroll
    for (int o = 16; o; o >>= 1) {
        s  += __shfl_xor_sync(0xffffffffu, s,  o);
        s2 += __shfl_xor_sync(0xffffffffu, s2, o);
    }
    __shared__ float ws[8], ws2[8];
    int w = threadIdx.x >> 5, l = threadIdx.x & 31;
    if (l == 0) { ws[w] = s; ws2[w] = s2; }
    __syncthreads();
    if (threadIdx.x < 32) {
        s  = (l < 8) ? ws[l]  : 0.f;
        s2 = (l < 8) ? ws2[l] : 0.f;
        #pragma unroll
        for (int o = 4; o; o >>= 1) {
            s  += __shfl_xor_sync(0xffffffffu, s,  o);
            s2 += __shfl_xor_sync(0xffffffffu, s2, o);
        }
        if (l == 0) { ws[0] = s; ws2[0] = s2; }
    }
    __syncthreads();
    float mean = ws[0] * (1.f / Dd);
    float var  = ws2[0] * (1.f / Dd) - mean * mean;
    float inv  = rsqrtf(var + 1e-6f);
    float* o_ = out + (size_t)row * Dd;
    for (int i = threadIdx.x; i < Dd; i += 256)
        o_[i] = (x[i] - mean) * inv * sc[i];
}

// ---------------- TF32 tensor-core GEMM 128x128x32 ---------------------------
// C[M,N] = A[M,K] @ B[K,N]; mode 0: clip(+-8); mode 1: + resid
#define BM 128
#define BN 128
#define BK 32
#define AS_STRIDE 36    // 128 rows x 36 (pad 4): conflict-free frag loads
#define BS_STRIDE 136   // 32 rows  x 136 (pad 8): conflict-free frag loads
#define AS_FLOATS (BM * AS_STRIDE)
#define BS_FLOATS (BK * BS_STRIDE)

__device__ __forceinline__ uint32_t f2tf32(float f) {
    uint32_t u;
    asm("cvt.rna.tf32.f32 %0, %1;" : "=r"(u) : "f"(f));
    return u;
}
__device__ __forceinline__ void mma_tf32(float c[4], uint32_t a0, uint32_t a1,
                                         uint32_t a2, uint32_t a3,
                                         uint32_t b0, uint32_t b1)
{
    asm volatile(
        "mma.sync.aligned.m16n8k8.row.col.f32.tf32.tf32.f32 "
        "{%0,%1,%2,%3}, {%4,%5,%6,%7}, {%8,%9}, {%0,%1,%2,%3};"
        : "+f"(c[0]), "+f"(c[1]), "+f"(c[2]), "+f"(c[3])
        : "r"(a0), "r"(a1), "r"(a2), "r"(a3), "r"(b0), "r"(b1));
}

__global__ __launch_bounds__(256) void gemm_tf32_kernel(
    const float* __restrict__ A, const float* __restrict__ Bw,
    float* __restrict__ C, int M, int N, int K, int mode,
    const float* __restrict__ resid)
{
    extern __shared__ float sm[];
    // two stages: [stage]{As, Bs}
    float* As[2] = { sm, sm + AS_FLOATS + BS_FLOATS };
    float* Bs[2] = { sm + AS_FLOATS, sm + 2 * AS_FLOATS + BS_FLOATS };

    int row0 = blockIdx.y * BM, col0 = blockIdx.x * BN;
    int t = threadIdx.x;
    int w = t >> 5, l = t & 31;
    int warpM = w >> 1, warpN = w & 1;   // 4 x 2 warps -> 32x64 per warp
    int lr = l >> 2, lc = l & 3;

    float acc[2][8][4];
    #pragma unroll
    for (int mf = 0; mf < 2; mf++)
        #pragma unroll
        for (int nf = 0; nf < 8; nf++)
            #pragma unroll
            for (int r = 0; r < 4; r++) acc[mf][nf][r] = 0.f;

    float4 ar[4], br[4];
    // prologue: load tile 0
    #pragma unroll
    for (int i = 0; i < 4; i++) {
        int idx = i * 256 + t;
        int arow = idx >> 3, ac4 = idx & 7;
        ar[i] = *(const float4*)(A + (size_t)(row0 + arow) * K + ac4 * 4);
        int brow = idx >> 5, bc4 = idx & 31;
        br[i] = *(const float4*)(Bw + (size_t)brow * N + col0 + bc4 * 4);
    }
    #pragma unroll
    for (int i = 0; i < 4; i++) {
        int idx = i * 256 + t;
        int arow = idx >> 3, ac4 = idx & 7;
        uint32_t* da = (uint32_t*)&As[0][arow * AS_STRIDE + ac4 * 4];
        da[0] = f2tf32(ar[i].x); da[1] = f2tf32(ar[i].y);
        da[2] = f2tf32(ar[i].z); da[3] = f2tf32(ar[i].w);
        int brow = idx >> 5, bc4 = idx & 31;
        uint32_t* db = (uint32_t*)&Bs[0][brow * BS_STRIDE + bc4 * 4];
        db[0] = f2tf32(br[i].x); db[1] = f2tf32(br[i].y);
        db[2] = f2tf32(br[i].z); db[3] = f2tf32(br[i].w);
    }
    __syncthreads();

    int nk = K / BK;
    for (int kt = 0; kt < nk; kt++) {
        int cur = kt & 1;
        // prefetch next tile into regs
        if (kt + 1 < nk) {
            int k0n = (kt + 1) * BK;
            #pragma unroll
            for (int i = 0; i < 4; i++) {
                int idx = i * 256 + t;
                int arow = idx >> 3, ac4 = idx & 7;
                ar[i] = *(const float4*)(A + (size_t)(row0 + arow) * K + k0n + ac4 * 4);
                int brow = idx >> 5, bc4 = idx & 31;
                br[i] = *(const float4*)(Bw + (size_t)(k0n + brow) * N + col0 + bc4 * 4);
            }
        }
        // compute current tile
        const uint32_t* as = (const uint32_t*)As[cur];
        const uint32_t* bs = (const uint32_t*)Bs[cur];
        #pragma unroll
        for (int ks = 0; ks < BK / 8; ks++) {
            uint32_t af[2][4];
            #pragma unroll
            for (int mf = 0; mf < 2; mf++) {
                int arow = warpM * 32 + mf * 16 + lr;
                int acol = ks * 8 + lc;
                af[mf][0] = as[arow * AS_STRIDE + acol];
                af[mf][1] = as[(arow + 8) * AS_STRIDE + acol];
                af[mf][2] = as[arow * AS_STRIDE + acol + 4];
                af[mf][3] = as[(arow + 8) * AS_STRIDE + acol + 4];
            }
            #pragma unroll
            for (int nf = 0; nf < 8; nf++) {
                int bn = warpN * 64 + nf * 8 + lr;
                int bk = ks * 8 + lc;
                uint32_t b0 = bs[bk * BS_STRIDE + bn];
                uint32_t b1 = bs[(bk + 4) * BS_STRIDE + bn];
                mma_tf32(acc[0][nf], af[0][0], af[0][1], af[0][2], af[0][3], b0, b1);
                mma_tf32(acc[1][nf], af[1][0], af[1][1], af[1][2], af[1][3], b0, b1);
            }
        }
        __syncthreads();
        // store prefetched regs into other stage
        if (kt + 1 < nk) {
            int nxt = cur ^ 1;
            #pragma unroll
            for (int i = 0; i < 4; i++) {
                int idx = i * 256 + t;
                int arow = idx >> 3, ac4 = idx & 7;
                uint32_t* da = (uint32_t*)&As[nxt][arow * AS_STRIDE + ac4 * 4];
                da[0] = f2tf32(ar[i].x); da[1] = f2tf32(ar[i].y);
                da[2] = f2tf32(ar[i].z); da[3] = f2tf32(ar[i].w);
                int brow = idx >> 5, bc4 = idx & 31;
                uint32_t* db = (uint32_t*)&Bs[nxt][brow * BS_STRIDE + bc4 * 4];
                db[0] = f2tf32(br[i].x); db[1] = f2tf32(br[i].y);
                db[2] = f2tf32(br[i].z); db[3] = f2tf32(br[i].w);
            }
            __syncthreads();
        }
    }

    // epilogue
    #pragma unroll
    for (int mf = 0; mf < 2; mf++) {
        #pragma unroll
        for (int half = 0; half < 2; half++) {
            int row = row0 + warpM * 32 + mf * 16 + lr + half * 8;
            #pragma unroll
            for (int nf = 0; nf < 8; nf++) {
                int col = col0 + warpN * 64 + nf * 8 + 2 * lc;
                float2 v;
                v.x = acc[mf][nf][half * 2 + 0];
                v.y = acc[mf][nf][half * 2 + 1];
                size_t off = (size_t)row * N + col;
                if (mode == 0) {
                    v.x = fminf(fmaxf(v.x, -8.f), 8.f);
                    v.y = fminf(fmaxf(v.y, -8.f), 8.f);
                } else {
                    float2 rv = *(const float2*)(resid + off);
                    v.x += rv.x; v.y += rv.y;
                }
                *(float2*)(C + off) = v;
            }
        }
    }
}

// ---------------- RoPE table (double trig once per (b,s,i)) ------------------
__global__ void rope_table_kernel(const int* __restrict__ pid)
{
    int idx = blockIdx.x * 256 + threadIdx.x;   // B*S*32
    if (idx >= Bb * Ss * 32) return;
    int i = idx & 31;
    int s = (idx >> 5) & (Ss - 1);
    int b = idx >> 16;
    double pos = (double)pid[b * Ss + s];
    double inv = exp(-((double)(2 * i) / 64.0) * log(500000.0));
    double ang = pos * inv;
    g_cos[idx] = (float)cos(ang);
    g_sin[idx] = (float)sin(ang);
}

// ---------------- RoPE apply + layout ----------------------------------------
__global__ void rope_q_kernel()
{
    int idx = blockIdx.x * 256 + threadIdx.x;   // B*S*H*32
    if (idx >= Bb * Ss * Hh * 32) return;
    int i = idx & 31;
    int h = (idx >> 5) & (Hh - 1);
    int s = (idx >> 10) & (Ss - 1);
    int b = idx >> 21;
    int tidx = (b << 16) + (s << 5) + i;
    float c = g_cos[tidx], sn = g_sin[tidx];
    const float* src = g_qkv + (size_t)(b * Ss + s) * QKVN + h * HDd;
    float x1 = src[i], x2 = src[i + 32];
    float* dst = g_q + ((size_t)(b * Hh + h) * Ss + s) * HDd;
    dst[i]      = x1 * c - x2 * sn;
    dst[i + 32] = x2 * c + x1 * sn;
}

__global__ void rope_k_kernel()
{
    int idx = blockIdx.x * 256 + threadIdx.x;   // B*S*KVH*32
    if (idx >= Bb * Ss * KVHh * 32) return;
    int i = idx & 31;
    int kvh = (idx >> 5) & (KVHh - 1);
    int s = (idx >> 8) & (Ss - 1);
    int b = idx >> 19;
    int tidx = (b << 16) + (s << 5) + i;
    float c = g_cos[tidx], sn = g_sin[tidx];
    const float* src = g_qkv + (size_t)(b * Ss + s) * QKVN + Dd + kvh * HDd;
    float x1 = src[i], x2 = src[i + 32];
    float* dst = g_k + ((size_t)(b * KVHh + kvh) * Ss + s) * HDd;
    dst[i]      = x1 * c - x2 * sn;
    dst[i + 32] = x2 * c + x1 * sn;
}

__global__ void copy_v_kernel()
{
    int idx = blockIdx.x * 256 + threadIdx.x;   // B*S*KVH*HD
    if (idx >= Bb * Ss * KVHh * HDd) return;
    int d = idx & 63;
    int kvh = (idx >> 6) & (KVHh - 1);
    int s = (idx >> 9) & (Ss - 1);
    int b = idx >> 20;
    g_v[((size_t)(b * KVHh + kvh) * Ss + s) * HDd + d] =
        g_qkv[(size_t)(b * Ss + s) * QKVN + Dd + KVHh * HDd + kvh * HDd + d];
}

// ---------------- Flash attention (64x64 tiles, fp32) ------------------------
__global__ __launch_bounds__(256) void attn_kernel(const int* __restrict__ amask)
{
    extern __shared__ float sm[];
    float* Qs   = sm;
    float* KsPs = sm + 64 * 65;
    float* Vs   = sm + 2 * 64 * 65;
    int*   maskS = (int*)(sm + 2 * 64 * 65 + 64 * 64);

    int qt = blockIdx.x, h = blockIdx.y, b = blockIdx.z;
    int kvh = h >> 2;
    int q0 = qt * 64;
    int t = threadIdx.x;
    int tr = t >> 4, tc = t & 15;

    const float* Qg = g_q + ((size_t)(b * Hh + h) * Ss + q0) * HDd;
    #pragma unroll
    for (int i = 0; i < 4; i++) {
        int idx4 = i * 256 + t;
        int row = idx4 >> 4, c4 = idx4 & 15;
        float4 v = *(const float4*)(Qg + row * 64 + c4 * 4);
        float* dq = &Qs[row * 65 + c4 * 4];
        dq[0] = v.x; dq[1] = v.y; dq[2] = v.z; dq[3] = v.w;
    }

    float m[4], l[4], o[4][4];
    #pragma unroll
    for (int ii = 0; ii < 4; ii++) {
        m[ii] = -1e30f; l[ii] = 0.f;
        #pragma unroll
        for (int jj = 0; jj < 4; jj++) o[ii][jj] = 0.f;
    }

    const float* Kg = g_k + (size_t)(b * KVHh + kvh) * Ss * HDd;
    const float* Vg = g_v + (size_t)(b * KVHh + kvh) * Ss * HDd;

    int ktiles = qt + 1;
    for (int kt = 0; kt < ktiles; kt++) {
        int k0 = kt * 64;
        __syncthreads();
        #pragma unroll
        for (int i = 0; i < 4; i++) {
            int idx4 = i * 256 + t;
            int row = idx4 >> 4, c4 = idx4 & 15;
            float4 kv = *(const float4*)(Kg + (size_t)(k0 + row) * 64 + c4 * 4);
            float* dk = &KsPs[row * 65 + c4 * 4];
            dk[0] = kv.x; dk[1] = kv.y; dk[2] = kv.z; dk[3] = kv.w;
            *(float4*)&Vs[row * 64 + c4 * 4] =
                *(const float4*)(Vg + (size_t)(k0 + row) * 64 + c4 * 4);
        }
        if (t < 64) maskS[t] = amask[b * Ss + k0 + t];
        __syncthreads();

        float sc[4][4];
        #pragma unroll
        for (int ii = 0; ii < 4; ii++)
            #pragma unroll
            for (int jj = 0; jj < 4; jj++) sc[ii][jj] = 0.f;
        #pragma unroll 4
        for (int d = 0; d < 64; d++) {
            float qv[4], kv[4];
            #pragma unroll
            for (int ii = 0; ii < 4; ii++) qv[ii] = Qs[(tr + 16 * ii) * 65 + d];
            #pragma unroll
            for (int jj = 0; jj < 4; jj++) kv[jj] = KsPs[(tc + 16 * jj) * 65 + d];
            #pragma unroll
            for (int ii = 0; ii < 4; ii++)
                #pragma unroll
                for (int jj = 0; jj < 4; jj++) sc[ii][jj] += qv[ii] * kv[jj];
        }
        #pragma unroll
        for (int ii = 0; ii < 4; ii++) {
            int qg = q0 + tr + 16 * ii;
            #pragma unroll
            for (int jj = 0; jj < 4; jj++) {
                int kg = k0 + tc + 16 * jj;
                float x = sc[ii][jj] * ATT_SCALE;
                if (kg > qg || maskS[tc + 16 * jj] == 0) x = -1e30f;
                sc[ii][jj] = x;
            }
        }
        #pragma unroll
        for (int ii = 0; ii < 4; ii++) {
            float mt = fmaxf(fmaxf(sc[ii][0], sc[ii][1]),
                             fmaxf(sc[ii][2], sc[ii][3]));
            #pragma unroll
            for (int off = 1; off < 16; off <<= 1)
                mt = fmaxf(mt, __shfl_xor_sync(0xffffffffu, mt, off));
            float mn = fmaxf(m[ii], mt);
            float rs = 0.f;
            #pragma unroll
            for (int jj = 0; jj < 4; jj++) {
                float p = expf(sc[ii][jj] - mn);
                sc[ii][jj] = p;
                rs += p;
            }
            #pragma unroll
            for (int off = 1; off < 16; off <<= 1)
                rs += __shfl_xor_sync(0xffffffffu, rs, off);
            float alpha = expf(m[ii] - mn);
            l[ii] = l[ii] * alpha + rs;
            m[ii] = mn;
            #pragma unroll
            for (int jj = 0; jj < 4; jj++) o[ii][jj] *= alpha;
        }
        __syncthreads();
        #pragma unroll
        for (int ii = 0; ii < 4; ii++)
            #pragma unroll
            for (int jj = 0; jj < 4; jj++)
                KsPs[(tr + 16 * ii) * 65 + tc + 16 * jj] = sc[ii][jj];
        __syncthreads();
        #pragma unroll 4
        for (int k = 0; k < 64; k++) {
            float pv[4], vv[4];
            #pragma unroll
            for (int ii = 0; ii < 4; ii++) pv[ii] = KsPs[(tr + 16 * ii) * 65 + k];
            #pragma unroll
            for (int jj = 0; jj < 4; jj++) vv[jj] = Vs[k * 64 + tc + 16 * jj];
            #pragma unroll
            for (int ii = 0; ii < 4; ii++)
                #pragma unroll
                for (int jj = 0; jj < 4; jj++) o[ii][jj] += pv[ii] * vv[jj];
        }
    }
    #pragma unroll
    for (int ii = 0; ii < 4; ii++) {
        float invl = (l[ii] > 0.f) ? (1.f / l[ii]) : 0.f;
        int q = q0 + tr + 16 * ii;
        float* dst = g_attn + (size_t)(b * Ss + q) * Dd + h * HDd;
        #pragma unroll
        for (int jj = 0; jj < 4; jj++)
            dst[tc + 16 * jj] = o[ii][jj] * invl;
    }
}

// ---------------- launch ------------------------------------------------------
extern "C" void kernel_launch(void* const* d_in, const int* in_sizes, int n_in,
                              void* d_out, int out_size)
{
    const float* hs   = (const float*)d_in[0];
    const int*   am   = (const int*)  d_in[1];
    const int*   pid  = (const int*)  d_in[2];
    const float* ln1  = (const float*)d_in[4];
    const float* wqkv = (const float*)d_in[5];
    const float* wout = (const float*)d_in[6];
    const float* ln2  = (const float*)d_in[7];
    float* out = (float*)d_out;

    float *px, *pqkv, *pattn;
    cudaGetSymbolAddress((void**)&px,    g_x);
    cudaGetSymbolAddress((void**)&pqkv,  g_qkv);
    cudaGetSymbolAddress((void**)&pattn, g_attn);

    const int ATTN_SMEM = (2 * 64 * 65 + 64 * 64) * 4 + 64 * 4;
    cudaFuncSetAttribute(attn_kernel,
                         cudaFuncAttributeMaxDynamicSharedMemorySize, ATTN_SMEM);
    const int GEMM_SMEM = 2 * (AS_FLOATS + BS_FLOATS) * 4;   // 71680 B
    cudaFuncSetAttribute(gemm_tf32_kernel,
                         cudaFuncAttributeMaxDynamicSharedMemorySize, GEMM_SMEM);

    // 1. x = LN1(hidden)
    ln_kernel<<<Mrows, 256>>>(hs, ln1, px);
    // 1b. rope table
    rope_table_kernel<<<(Bb * Ss * 32) / 256, 256>>>(pid);
    // 2. qkv = clip(x @ w_qkv)
    gemm_tf32_kernel<<<dim3(QKVN / BN, Mrows / BM), 256, GEMM_SMEM>>>(
        px, wqkv, pqkv, Mrows, QKVN, Dd, 0, nullptr);
    // 3. RoPE + layout transform
    rope_q_kernel<<<(Bb * Ss * Hh * 32) / 256, 256>>>();
    rope_k_kernel<<<(Bb * Ss * KVHh * 32) / 256, 256>>>();
    copy_v_kernel<<<(Bb * Ss * KVHh * HDd) / 256, 256>>>();
    // 4. attention
    attn_kernel<<<dim3(Ss / 64, Hh, Bb), 256, ATTN_SMEM>>>(am);
    // 5. residual2 = attn @ w_out + hidden
    gemm_tf32_kernel<<<dim3(Dd / BN, Mrows / BM), 256, GEMM_SMEM>>>(
        pattn, wout, out, Mrows, Dd, Dd, 1, hs);
    // 6. hidden = LN2(residual2)
    ln_kernel<<<Mrows, 256>>>(out, ln2, out + OUTOFF);
}

// round 3
// speedup vs baseline: 4.1128x; 1.4301x over previous
#include <cuda_runtime.h>
#include <math.h>
#include <stdint.h>

#define Bb    2
#define Ss    2048
#define Dd    2048
#define Hh    32
#define KVHh  8
#define HDd   64
#define QKVN  3072
#define Mrows (Bb*Ss)
#define OUTOFF ((size_t)Bb*Ss*Dd)
#define ATT_SCALE 0.125f

// ---------------- scratch ----------------------------------------------------
__device__ float g_x[(size_t)Mrows*Dd];
__device__ float g_qkv[(size_t)Mrows*QKVN];
__device__ float g_q[(size_t)Bb*Hh*Ss*HDd];
__device__ float g_k[(size_t)Bb*KVHh*Ss*HDd];
__device__ float g_v[(size_t)Bb*KVHh*Ss*HDd];
__device__ float g_attn[(size_t)Mrows*Dd];
__device__ float g_cos[(size_t)Bb*Ss*32];
__device__ float g_sin[(size_t)Bb*Ss*32];

__device__ __forceinline__ uint32_t f2tf32(float f) {
    uint32_t u;
    asm("cvt.rna.tf32.f32 %0, %1;" : "=r"(u) : "f"(f));
    return u;
}
__device__ __forceinline__ void mma_tf32(float c[4], uint32_t a0, uint32_t a1,
                                         uint32_t a2, uint32_t a3,
                                         uint32_t b0, uint32_t b1)
{
    asm volatile(
        "mma.sync.aligned.m16n8k8.row.col.f32.tf32.tf32.f32 "
        "{%0,%1,%2,%3}, {%4,%5,%6,%7}, {%8,%9}, {%0,%1,%2,%3};"
        : "+f"(c[0]), "+f"(c[1]), "+f"(c[2]), "+f"(c[3])
        : "r"(a0), "r"(a1), "r"(a2), "r"(a3), "r"(b0), "r"(b1));
}

// ---------------- LayerNorm --------------------------------------------------
__global__ __launch_bounds__(256) void ln_kernel(
    const float* __restrict__ in, const float* __restrict__ sc,
    float* __restrict__ out)
{
    int row = blockIdx.x;
    const float* x = in + (size_t)row * Dd;
    float s = 0.f, s2 = 0.f;
    for (int i = threadIdx.x; i < Dd; i += 256) { float v = x[i]; s += v; s2 += v*v; }
    #pragma unroll
    for (int o = 16; o; o >>= 1) {
        s  += __shfl_xor_sync(0xffffffffu, s,  o);
        s2 += __shfl_xor_sync(0xffffffffu, s2, o);
    }
    __shared__ float ws[8], ws2[8];
    int w = threadIdx.x >> 5, l = threadIdx.x & 31;
    if (l == 0) { ws[w] = s; ws2[w] = s2; }
    __syncthreads();
    if (threadIdx.x < 32) {
        s  = (l < 8) ? ws[l]  : 0.f;
        s2 = (l < 8) ? ws2[l] : 0.f;
        #pragma unroll
        for (int o = 4; o; o >>= 1) {
            s  += __shfl_xor_sync(0xffffffffu, s,  o);
            s2 += __shfl_xor_sync(0xffffffffu, s2, o);
        }
        if (l == 0) { ws[0] = s; ws2[0] = s2; }
    }
    __syncthreads();
    float mean = ws[0] * (1.f / Dd);
    float var  = ws2[0] * (1.f / Dd) - mean * mean;
    float inv  = rsqrtf(var + 1e-6f);
    float* o_ = out + (size_t)row * Dd;
    for (int i = threadIdx.x; i < Dd; i += 256)
        o_[i] = (x[i] - mean) * inv * sc[i];
}

// ---------------- TF32 tensor-core GEMM 128x128x32 ---------------------------
#define BM 128
#define BN 128
#define BK 32
#define AS_STRIDE 36
#define BS_STRIDE 136
#define AS_FLOATS (BM * AS_STRIDE)
#define BS_FLOATS (BK * BS_STRIDE)

__global__ __launch_bounds__(256) void gemm_tf32_kernel(
    const float* __restrict__ A, const float* __restrict__ Bw,
    float* __restrict__ C, int M, int N, int K, int mode,
    const float* __restrict__ resid)
{
    extern __shared__ float sm[];
    float* As[2] = { sm, sm + AS_FLOATS + BS_FLOATS };
    float* Bs[2] = { sm + AS_FLOATS, sm + 2 * AS_FLOATS + BS_FLOATS };

    int row0 = blockIdx.y * BM, col0 = blockIdx.x * BN;
    int t = threadIdx.x;
    int w = t >> 5, l = t & 31;
    int warpM = w >> 1, warpN = w & 1;
    int lr = l >> 2, lc = l & 3;

    float acc[2][8][4];
    #pragma unroll
    for (int mf = 0; mf < 2; mf++)
        #pragma unroll
        for (int nf = 0; nf < 8; nf++)
            #pragma unroll
            for (int r = 0; r < 4; r++) acc[mf][nf][r] = 0.f;

    float4 ar[4], br[4];
    #pragma unroll
    for (int i = 0; i < 4; i++) {
        int idx = i * 256 + t;
        int arow = idx >> 3, ac4 = idx & 7;
        ar[i] = *(const float4*)(A + (size_t)(row0 + arow) * K + ac4 * 4);
        int brow = idx >> 5, bc4 = idx & 31;
        br[i] = *(const float4*)(Bw + (size_t)brow * N + col0 + bc4 * 4);
    }
    #pragma unroll
    for (int i = 0; i < 4; i++) {
        int idx = i * 256 + t;
        int arow = idx >> 3, ac4 = idx & 7;
        uint32_t* da = (uint32_t*)&As[0][arow * AS_STRIDE + ac4 * 4];
        da[0] = f2tf32(ar[i].x); da[1] = f2tf32(ar[i].y);
        da[2] = f2tf32(ar[i].z); da[3] = f2tf32(ar[i].w);
        int brow = idx >> 5, bc4 = idx & 31;
        uint32_t* db = (uint32_t*)&Bs[0][brow * BS_STRIDE + bc4 * 4];
        db[0] = f2tf32(br[i].x); db[1] = f2tf32(br[i].y);
        db[2] = f2tf32(br[i].z); db[3] = f2tf32(br[i].w);
    }
    __syncthreads();

    int nk = K / BK;
    for (int kt = 0; kt < nk; kt++) {
        int cur = kt & 1;
        if (kt + 1 < nk) {
            int k0n = (kt + 1) * BK;
            #pragma unroll
            for (int i = 0; i < 4; i++) {
                int idx = i * 256 + t;
                int arow = idx >> 3, ac4 = idx & 7;
                ar[i] = *(const float4*)(A + (size_t)(row0 + arow) * K + k0n + ac4 * 4);
                int brow = idx >> 5, bc4 = idx & 31;
                br[i] = *(const float4*)(Bw + (size_t)(k0n + brow) * N + col0 + bc4 * 4);
            }
        }
        const uint32_t* as = (const uint32_t*)As[cur];
        const uint32_t* bs = (const uint32_t*)Bs[cur];
        #pragma unroll
        for (int ks = 0; ks < BK / 8; ks++) {
            uint32_t af[2][4];
            #pragma unroll
            for (int mf = 0; mf < 2; mf++) {
                int arow = warpM * 32 + mf * 16 + lr;
                int acol = ks * 8 + lc;
                af[mf][0] = as[arow * AS_STRIDE + acol];
                af[mf][1] = as[(arow + 8) * AS_STRIDE + acol];
                af[mf][2] = as[arow * AS_STRIDE + acol + 4];
                af[mf][3] = as[(arow + 8) * AS_STRIDE + acol + 4];
            }
            #pragma unroll
            for (int nf = 0; nf < 8; nf++) {
                int bn = warpN * 64 + nf * 8 + lr;
                int bk = ks * 8 + lc;
                uint32_t b0 = bs[bk * BS_STRIDE + bn];
                uint32_t b1 = bs[(bk + 4) * BS_STRIDE + bn];
                mma_tf32(acc[0][nf], af[0][0], af[0][1], af[0][2], af[0][3], b0, b1);
                mma_tf32(acc[1][nf], af[1][0], af[1][1], af[1][2], af[1][3], b0, b1);
            }
        }
        __syncthreads();
        if (kt + 1 < nk) {
            int nxt = cur ^ 1;
            #pragma unroll
            for (int i = 0; i < 4; i++) {
                int idx = i * 256 + t;
                int arow = idx >> 3, ac4 = idx & 7;
                uint32_t* da = (uint32_t*)&As[nxt][arow * AS_STRIDE + ac4 * 4];
                da[0] = f2tf32(ar[i].x); da[1] = f2tf32(ar[i].y);
                da[2] = f2tf32(ar[i].z); da[3] = f2tf32(ar[i].w);
                int brow = idx >> 5, bc4 = idx & 31;
                uint32_t* db = (uint32_t*)&Bs[nxt][brow * BS_STRIDE + bc4 * 4];
                db[0] = f2tf32(br[i].x); db[1] = f2tf32(br[i].y);
                db[2] = f2tf32(br[i].z); db[3] = f2tf32(br[i].w);
            }
            __syncthreads();
        }
    }

    #pragma unroll
    for (int mf = 0; mf < 2; mf++) {
        #pragma unroll
        for (int half = 0; half < 2; half++) {
            int row = row0 + warpM * 32 + mf * 16 + lr + half * 8;
            #pragma unroll
            for (int nf = 0; nf < 8; nf++) {
                int col = col0 + warpN * 64 + nf * 8 + 2 * lc;
                float2 v;
                v.x = acc[mf][nf][half * 2 + 0];
                v.y = acc[mf][nf][half * 2 + 1];
                size_t off = (size_t)row * N + col;
                if (mode == 0) {
                    v.x = fminf(fmaxf(v.x, -8.f), 8.f);
                    v.y = fminf(fmaxf(v.y, -8.f), 8.f);
                } else {
                    float2 rv = *(const float2*)(resid + off);
                    v.x += rv.x; v.y += rv.y;
                }
                *(float2*)(C + off) = v;
            }
        }
    }
}

// ---------------- RoPE table -------------------------------------------------
__global__ void rope_table_kernel(const int* __restrict__ pid)
{
    int idx = blockIdx.x * 256 + threadIdx.x;
    if (idx >= Bb * Ss * 32) return;
    int i = idx & 31;
    int s = (idx >> 5) & (Ss - 1);
    int b = idx >> 16;
    double pos = (double)pid[b * Ss + s];
    double inv = exp(-((double)(2 * i) / 64.0) * log(500000.0));
    double ang = pos * inv;
    g_cos[idx] = (float)cos(ang);
    g_sin[idx] = (float)sin(ang);
}

__global__ void rope_q_kernel()
{
    int idx = blockIdx.x * 256 + threadIdx.x;
    if (idx >= Bb * Ss * Hh * 32) return;
    int i = idx & 31;
    int h = (idx >> 5) & (Hh - 1);
    int s = (idx >> 10) & (Ss - 1);
    int b = idx >> 21;
    int tidx = (b << 16) + (s << 5) + i;
    float c = g_cos[tidx], sn = g_sin[tidx];
    const float* src = g_qkv + (size_t)(b * Ss + s) * QKVN + h * HDd;
    float x1 = src[i], x2 = src[i + 32];
    float* dst = g_q + ((size_t)(b * Hh + h) * Ss + s) * HDd;
    dst[i]      = x1 * c - x2 * sn;
    dst[i + 32] = x2 * c + x1 * sn;
}

// rope K + copy V fused
__global__ void rope_kv_kernel()
{
    int idx = blockIdx.x * 256 + threadIdx.x;
    if (idx >= Bb * Ss * KVHh * 32) return;
    int i = idx & 31;
    int kvh = (idx >> 5) & (KVHh - 1);
    int s = (idx >> 8) & (Ss - 1);
    int b = idx >> 19;
    int tidx = (b << 16) + (s << 5) + i;
    float c = g_cos[tidx], sn = g_sin[tidx];
    const float* srcb = g_qkv + (size_t)(b * Ss + s) * QKVN + Dd;
    const float* srck = srcb + kvh * HDd;
    float x1 = srck[i], x2 = srck[i + 32];
    size_t hoff = ((size_t)(b * KVHh + kvh) * Ss + s) * HDd;
    g_k[hoff + i]      = x1 * c - x2 * sn;
    g_k[hoff + i + 32] = x2 * c + x1 * sn;
    const float* srcv = srcb + KVHh * HDd + kvh * HDd;
    g_v[hoff + i]      = srcv[i];
    g_v[hoff + i + 32] = srcv[i + 32];
}

// ---------------- Tensor-core flash attention --------------------------------
// block: 128 q rows for one (b,h). 8 warps x 16 rows. K tiles of 64.
#define AT_STR 68   // smem stride (floats), conflict-free for frag patterns
__global__ __launch_bounds__(256) void attn_kernel(const int* __restrict__ amask)
{
    extern __shared__ float sm[];
    float* Ks[2] = { sm,              sm + 64 * AT_STR };
    float* Vs[2] = { sm + 2*64*AT_STR, sm + 3*64*AT_STR };
    float* Ps    = sm + 4*64*AT_STR;             // 128 x 68, also Q staging
    int*   maskS = (int*)(sm + 4*64*AT_STR + 128*AT_STR);  // [2][64]

    int qt = blockIdx.x, h = blockIdx.y, b = blockIdx.z;
    int kvh = h >> 2;
    int q0 = qt * 128;
    int t = threadIdx.x;
    int w = t >> 5, l = t & 31;
    int lr = l >> 2, lc = l & 3;

    const float* Qg = g_q + ((size_t)(b * Hh + h) * Ss + q0) * HDd;
    const float* Kg = g_k + (size_t)(b * KVHh + kvh) * Ss * HDd;
    const float* Vg = g_v + (size_t)(b * KVHh + kvh) * Ss * HDd;
    const int*   Mg = amask + b * Ss;

    // ---- stage Q into Ps, convert to tf32 ----
    #pragma unroll
    for (int i = 0; i < 8; i++) {
        int idx = i * 256 + t;                   // 2048 float4
        int row = idx >> 4, c4 = idx & 15;
        float4 v = *(const float4*)(Qg + row * 64 + c4 * 4);
        uint32_t* d = (uint32_t*)&Ps[row * AT_STR + c4 * 4];
        d[0] = f2tf32(v.x); d[1] = f2tf32(v.y);
        d[2] = f2tf32(v.z); d[3] = f2tf32(v.w);
    }
    __syncthreads();
    // ---- extract Q A-frags (warp-private rows) ----
    uint32_t qa[8][4];
    {
        const uint32_t* qs = (const uint32_t*)Ps;
        int r0 = w * 16 + lr;
        #pragma unroll
        for (int ks = 0; ks < 8; ks++) {
            int c = ks * 8 + lc;
            qa[ks][0] = qs[r0 * AT_STR + c];
            qa[ks][1] = qs[(r0 + 8) * AT_STR + c];
            qa[ks][2] = qs[r0 * AT_STR + c + 4];
            qa[ks][3] = qs[(r0 + 8) * AT_STR + c + 4];
        }
    }
    __syncthreads();   // Ps free for P use

    float m0 = -1e30f, m1 = -1e30f, l0 = 0.f, l1 = 0.f;
    float o[8][4];
    #pragma unroll
    for (int nf = 0; nf < 8; nf++)
        #pragma unroll
        for (int r = 0; r < 4; r++) o[nf][r] = 0.f;

    int nkt = 2 * qt + 2;
    // ---- prologue: load tile 0 ----
    {
        #pragma unroll
        for (int i = 0; i < 4; i++) {
            int idx = i * 256 + t;               // 1024 float4 per tensor
            int row = idx >> 4, c4 = idx & 15;
            float4 kv = *(const float4*)(Kg + (size_t)row * 64 + c4 * 4);
            float4 vv = *(const float4*)(Vg + (size_t)row * 64 + c4 * 4);
            uint32_t* dk = (uint32_t*)&Ks[0][row * AT_STR + c4 * 4];
            dk[0] = f2tf32(kv.x); dk[1] = f2tf32(kv.y);
            dk[2] = f2tf32(kv.z); dk[3] = f2tf32(kv.w);
            uint32_t* dv = (uint32_t*)&Vs[0][row * AT_STR + c4 * 4];
            dv[0] = f2tf32(vv.x); dv[1] = f2tf32(vv.y);
            dv[2] = f2tf32(vv.z); dv[3] = f2tf32(vv.w);
        }
        if (t < 64) maskS[t] = Mg[t];
    }
    __syncthreads();

    for (int kt = 0; kt < nkt; kt++) {
        int cur = kt & 1;
        int k0 = kt * 64;
        // prefetch next tile into regs
        float4 kr[4], vr[4]; int mr = 1;
        if (kt + 1 < nkt) {
            int k0n = k0 + 64;
            #pragma unroll
            for (int i = 0; i < 4; i++) {
                int idx = i * 256 + t;
                int row = idx >> 4, c4 = idx & 15;
                kr[i] = *(const float4*)(Kg + (size_t)(k0n + row) * 64 + c4 * 4);
                vr[i] = *(const float4*)(Vg + (size_t)(k0n + row) * 64 + c4 * 4);
            }
            if (t < 64) mr = Mg[k0n + t];
        }

        int qlow = q0 + w * 16;                  // this warp's lowest q row
        bool active = (k0 <= qlow + 15);
        if (active) {
            // ---- S = Q K^T ----
            float s[8][4];
            #pragma unroll
            for (int nf = 0; nf < 8; nf++)
                #pragma unroll
                for (int r = 0; r < 4; r++) s[nf][r] = 0.f;
            const uint32_t* kb = (const uint32_t*)Ks[cur];
            #pragma unroll
            for (int ks = 0; ks < 8; ks++) {
                #pragma unroll
                for (int nf = 0; nf < 8; nf++) {
                    int n = nf * 8 + lr;
                    uint32_t b0 = kb[n * AT_STR + ks * 8 + lc];
                    uint32_t b1 = kb[n * AT_STR + ks * 8 + lc + 4];
                    mma_tf32(s[nf], qa[ks][0], qa[ks][1], qa[ks][2], qa[ks][3], b0, b1);
                }
            }
            // ---- mask + scale ----
            int qr0 = qlow + lr, qr1 = qr0 + 8;
            bool fullvis = (k0 + 63 <= qlow);
            #pragma unroll
            for (int nf = 0; nf < 8; nf++) {
                int kg0 = k0 + nf * 8 + 2 * lc;
                int ms0 = maskS[(cur << 6) + nf * 8 + 2 * lc];
                int ms1 = maskS[(cur << 6) + nf * 8 + 2 * lc + 1];
                s[nf][0] = (ms0 && (fullvis || kg0     <= qr0)) ? s[nf][0] * ATT_SCALE : -1e30f;
                s[nf][1] = (ms1 && (fullvis || kg0 + 1 <= qr0)) ? s[nf][1] * ATT_SCALE : -1e30f;
                s[nf][2] = (ms0 && (fullvis || kg0     <= qr1)) ? s[nf][2] * ATT_SCALE : -1e30f;
                s[nf][3] = (ms1 && (fullvis || kg0 + 1 <= qr1)) ? s[nf][3] * ATT_SCALE : -1e30f;
            }
            // ---- row max (lanes sharing lr: xor 1, xor 2) ----
            float mt0 = -1e30f, mt1 = -1e30f;
            #pragma unroll
            for (int nf = 0; nf < 8; nf++) {
                mt0 = fmaxf(mt0, fmaxf(s[nf][0], s[nf][1]));
                mt1 = fmaxf(mt1, fmaxf(s[nf][2], s[nf][3]));
            }
            mt0 = fmaxf(mt0, __shfl_xor_sync(0xffffffffu, mt0, 1));
            mt0 = fmaxf(mt0, __shfl_xor_sync(0xffffffffu, mt0, 2));
            mt1 = fmaxf(mt1, __shfl_xor_sync(0xffffffffu, mt1, 1));
            mt1 = fmaxf(mt1, __shfl_xor_sync(0xffffffffu, mt1, 2));
            float mn0 = fmaxf(m0, mt0), mn1 = fmaxf(m1, mt1);
            // ---- exp + rowsum ----
            float rs0 = 0.f, rs1 = 0.f;
            #pragma unroll
            for (int nf = 0; nf < 8; nf++) {
                s[nf][0] = expf(s[nf][0] - mn0);
                s[nf][1] = expf(s[nf][1] - mn0);
                s[nf][2] = expf(s[nf][2] - mn1);
                s[nf][3] = expf(s[nf][3] - mn1);
                rs0 += s[nf][0] + s[nf][1];
                rs1 += s[nf][2] + s[nf][3];
            }
            rs0 += __shfl_xor_sync(0xffffffffu, rs0, 1);
            rs0 += __shfl_xor_sync(0xffffffffu, rs0, 2);
            rs1 += __shfl_xor_sync(0xffffffffu, rs1, 1);
            rs1 += __shfl_xor_sync(0xffffffffu, rs1, 2);
            float a0 = expf(m0 - mn0), a1 = expf(m1 - mn1);
            l0 = l0 * a0 + rs0;  l1 = l1 * a1 + rs1;
            m0 = mn0;  m1 = mn1;
            #pragma unroll
            for (int nf = 0; nf < 8; nf++) {
                o[nf][0] *= a0; o[nf][1] *= a0;
                o[nf][2] *= a1; o[nf][3] *= a1;
            }
            // ---- write P to warp-private smem patch (tf32) ----
            {
                uint32_t* pp = (uint32_t*)Ps;
                int r0 = w * 16 + lr;
                #pragma unroll
                for (int nf = 0; nf < 8; nf++) {
                    int c = nf * 8 + 2 * lc;
                    pp[r0 * AT_STR + c]           = f2tf32(s[nf][0]);
                    pp[r0 * AT_STR + c + 1]       = f2tf32(s[nf][1]);
                    pp[(r0 + 8) * AT_STR + c]     = f2tf32(s[nf][2]);
                    pp[(r0 + 8) * AT_STR + c + 1] = f2tf32(s[nf][3]);
                }
            }
            __syncwarp();
            // ---- O += P V ----
            {
                const uint32_t* pp = (const uint32_t*)Ps;
                const uint32_t* vb = (const uint32_t*)Vs[cur];
                int r0 = w * 16 + lr;
                #pragma unroll
                for (int ks = 0; ks < 8; ks++) {
                    int c = ks * 8 + lc;
                    uint32_t pa0 = pp[r0 * AT_STR + c];
                    uint32_t pa1 = pp[(r0 + 8) * AT_STR + c];
                    uint32_t pa2 = pp[r0 * AT_STR + c + 4];
                    uint32_t pa3 = pp[(r0 + 8) * AT_STR + c + 4];
                    #pragma unroll
                    for (int nf = 0; nf < 8; nf++) {
                        uint32_t b0 = vb[(ks * 8 + lc) * AT_STR + nf * 8 + lr];
                        uint32_t b1 = vb[(ks * 8 + lc + 4) * AT_STR + nf * 8 + lr];
                        mma_tf32(o[nf], pa0, pa1, pa2, pa3, b0, b1);
                    }
                }
            }
        }
        __syncthreads();    // all warps done reading stage cur^1 (prev iter)
        if (kt + 1 < nkt) {
            int nxt = cur ^ 1;
            #pragma unroll
            for (int i = 0; i < 4; i++) {
                int idx = i * 256 + t;
                int row = idx >> 4, c4 = idx & 15;
                uint32_t* dk = (uint32_t*)&Ks[nxt][row * AT_STR + c4 * 4];
                dk[0] = f2tf32(kr[i].x); dk[1] = f2tf32(kr[i].y);
                dk[2] = f2tf32(kr[i].z); dk[3] = f2tf32(kr[i].w);
                uint32_t* dv = (uint32_t*)&Vs[nxt][row * AT_STR + c4 * 4];
                dv[0] = f2tf32(vr[i].x); dv[1] = f2tf32(vr[i].y);
                dv[2] = f2tf32(vr[i].z); dv[3] = f2tf32(vr[i].w);
            }
            if (t < 64) maskS[(nxt << 6) + t] = mr;
            __syncthreads();
        }
    }

    // ---- normalize + store ----
    float il0 = (l0 > 0.f) ? (1.f / l0) : 0.f;
    float il1 = (l1 > 0.f) ? (1.f / l1) : 0.f;
    int qr0 = q0 + w * 16 + lr;
    float* d0 = g_attn + (size_t)(b * Ss + qr0) * Dd + h * HDd;
    float* d1 = g_attn + (size_t)(b * Ss + qr0 + 8) * Dd + h * HDd;
    #pragma unroll
    for (int nf = 0; nf < 8; nf++) {
        int c = nf * 8 + 2 * lc;
        float2 v0; v0.x = o[nf][0] * il0; v0.y = o[nf][1] * il0;
        float2 v1; v1.x = o[nf][2] * il1; v1.y = o[nf][3] * il1;
        *(float2*)(d0 + c) = v0;
        *(float2*)(d1 + c) = v1;
    }
}

// ---------------- launch ------------------------------------------------------
extern "C" void kernel_launch(void* const* d_in, const int* in_sizes, int n_in,
                              void* d_out, int out_size)
{
    const float* hs   = (const float*)d_in[0];
    const int*   am   = (const int*)  d_in[1];
    const int*   pid  = (const int*)  d_in[2];
    const float* ln1  = (const float*)d_in[4];
    const float* wqkv = (const float*)d_in[5];
    const float* wout = (const float*)d_in[6];
    const float* ln2  = (const float*)d_in[7];
    float* out = (float*)d_out;

    float *px, *pqkv, *pattn;
    cudaGetSymbolAddress((void**)&px,    g_x);
    cudaGetSymbolAddress((void**)&pqkv,  g_qkv);
    cudaGetSymbolAddress((void**)&pattn, g_attn);

    const int ATTN_SMEM = (4 * 64 * AT_STR + 128 * AT_STR) * 4 + 2 * 64 * 4;
    cudaFuncSetAttribute(attn_kernel,
                         cudaFuncAttributeMaxDynamicSharedMemorySize, ATTN_SMEM);
    const int GEMM_SMEM = 2 * (AS_FLOATS + BS_FLOATS) * 4;
    cudaFuncSetAttribute(gemm_tf32_kernel,
                         cudaFuncAttributeMaxDynamicSharedMemorySize, GEMM_SMEM);

    ln_kernel<<<Mrows, 256>>>(hs, ln1, px);
    rope_table_kernel<<<(Bb * Ss * 32) / 256, 256>>>(pid);
    gemm_tf32_kernel<<<dim3(QKVN / BN, Mrows / BM), 256, GEMM_SMEM>>>(
        px, wqkv, pqkv, Mrows, QKVN, Dd, 0, nullptr);
    rope_q_kernel<<<(Bb * Ss * Hh * 32) / 256, 256>>>();
    rope_kv_kernel<<<(Bb * Ss * KVHh * 32) / 256, 256>>>();
    attn_kernel<<<dim3(Ss / 128, Hh, Bb), 256, ATTN_SMEM>>>(am);
    gemm_tf32_kernel<<<dim3(Dd / BN, Mrows / BM), 256, GEMM_SMEM>>>(
        pattn, wout, out, Mrows, Dd, Dd, 1, hs);
    ln_kernel<<<Mrows, 256>>>(out, ln2, out + OUTOFF);
}

// round 4
// speedup vs baseline: 6.7008x; 1.6292x over previous
#include <cuda_runtime.h>
#include <cuda_fp16.h>
#include <math.h>
#include <stdint.h>

#define Bb    2
#define Ss    2048
#define Dd    2048
#define Hh    32
#define KVHh  8
#define HDd   64
#define QKVN  3072
#define Mrows (Bb*Ss)
#define OUTOFF ((size_t)Bb*Ss*Dd)
#define ATT_SCALE 0.125f

// ---------------- scratch ----------------------------------------------------
__device__ __half g_x[(size_t)Mrows*Dd];
__device__ __half g_qkv[(size_t)Mrows*QKVN];
__device__ __half g_q[(size_t)Bb*Hh*Ss*HDd];
__device__ __half g_k[(size_t)Bb*KVHh*Ss*HDd];
__device__ __half g_v[(size_t)Bb*KVHh*Ss*HDd];
__device__ __half g_attn[(size_t)Mrows*Dd];
__device__ __half g_wqkvh[(size_t)Dd*QKVN];
__device__ __half g_wouth[(size_t)Dd*Dd];
__device__ float g_cos[(size_t)Bb*Ss*32];
__device__ float g_sin[(size_t)Bb*Ss*32];

__device__ __forceinline__ uint32_t pkh2(float x, float y) {
    __half2 h = __floats2half2_rn(x, y);
    return *(uint32_t*)&h;
}
__device__ __forceinline__ void mma_f16(float c[4], uint32_t a0, uint32_t a1,
                                        uint32_t a2, uint32_t a3,
                                        uint32_t b0, uint32_t b1)
{
    asm volatile(
        "mma.sync.aligned.m16n8k16.row.col.f32.f16.f16.f32 "
        "{%0,%1,%2,%3}, {%4,%5,%6,%7}, {%8,%9}, {%0,%1,%2,%3};"
        : "+f"(c[0]), "+f"(c[1]), "+f"(c[2]), "+f"(c[3])
        : "r"(a0), "r"(a1), "r"(a2), "r"(a3), "r"(b0), "r"(b1));
}
__device__ __forceinline__ void ldsm4t(uint32_t& r0, uint32_t& r1,
                                       uint32_t& r2, uint32_t& r3, uint32_t saddr)
{
    asm volatile(
        "ldmatrix.sync.aligned.m8n8.x4.trans.shared.b16 {%0,%1,%2,%3}, [%4];"
        : "=r"(r0), "=r"(r1), "=r"(r2), "=r"(r3) : "r"(saddr));
}

// ---------------- weight fp32 -> fp16 ----------------------------------------
__global__ void cvt_kernel(const float* __restrict__ in, __half* __restrict__ out,
                           int n4)
{
    int i = blockIdx.x * 256 + threadIdx.x;
    if (i >= n4) return;
    float4 v = *(const float4*)(in + (size_t)i * 4);
    uint32_t* d = (uint32_t*)(out + (size_t)i * 4);
    d[0] = pkh2(v.x, v.y);
    d[1] = pkh2(v.z, v.w);
}

// ---------------- LayerNorm (half_out: write __half, else float) --------------
__global__ __launch_bounds__(256) void ln_kernel(
    const float* __restrict__ in, const float* __restrict__ sc,
    void* __restrict__ outp, int half_out)
{
    int row = blockIdx.x;
    const float* x = in + (size_t)row * Dd;
    float s = 0.f, s2 = 0.f;
    for (int i = threadIdx.x; i < Dd; i += 256) { float v = x[i]; s += v; s2 += v*v; }
    #pragma unroll
    for (int o = 16; o; o >>= 1) {
        s  += __shfl_xor_sync(0xffffffffu, s,  o);
        s2 += __shfl_xor_sync(0xffffffffu, s2, o);
    }
    __shared__ float ws[8], ws2[8];
    int w = threadIdx.x >> 5, l = threadIdx.x & 31;
    if (l == 0) { ws[w] = s; ws2[w] = s2; }
    __syncthreads();
    if (threadIdx.x < 32) {
        s  = (l < 8) ? ws[l]  : 0.f;
        s2 = (l < 8) ? ws2[l] : 0.f;
        #pragma unroll
        for (int o = 4; o; o >>= 1) {
            s  += __shfl_xor_sync(0xffffffffu, s,  o);
            s2 += __shfl_xor_sync(0xffffffffu, s2, o);
        }
        if (l == 0) { ws[0] = s; ws2[0] = s2; }
    }
    __syncthreads();
    float mean = ws[0] * (1.f / Dd);
    float var  = ws2[0] * (1.f / Dd) - mean * mean;
    float inv  = rsqrtf(var + 1e-6f);
    if (half_out) {
        __half* o_ = (__half*)outp + (size_t)row * Dd;
        for (int i = threadIdx.x * 2; i < Dd; i += 512) {
            float a = (x[i] - mean) * inv * sc[i];
            float b = (x[i+1] - mean) * inv * sc[i+1];
            *(uint32_t*)(o_ + i) = pkh2(a, b);
        }
    } else {
        float* o_ = (float*)outp + (size_t)row * Dd;
        for (int i = threadIdx.x; i < Dd; i += 256)
            o_[i] = (x[i] - mean) * inv * sc[i];
    }
}

// ---------------- FP16 tensor-core GEMM 128x128x32 ----------------------------
// A half [M,K], B half [K,N]. mode0: C half = clip; mode1: C float = +resid
#define BM 128
#define BN 128
#define BK 32
#define AS_U 20                    // u32 stride (16 data + 4 pad), ≡4 mod 8
#define AS_U32S (BM * AS_U)        // 2560
#define BS_U32S (BK * 64)          // 2048
#define STAGE_U (AS_U32S + BS_U32S)

__global__ __launch_bounds__(256) void gemm_f16_kernel(
    const __half* __restrict__ A, const __half* __restrict__ Bw,
    void* __restrict__ Cp, int M, int N, int K, int mode,
    const float* __restrict__ resid)
{
    extern __shared__ uint32_t smu[];
    uint32_t* As[2] = { smu, smu + STAGE_U };
    uint32_t* Bs[2] = { smu + AS_U32S, smu + STAGE_U + AS_U32S };

    int row0 = blockIdx.y * BM, col0 = blockIdx.x * BN;
    int t = threadIdx.x;
    int w = t >> 5, l = t & 31;
    int warpM = w >> 1, warpN = w & 1;
    int lr = l >> 2, lc = l & 3;

    const uint4* Au = (const uint4*)A;   // 8 halves per uint4
    const uint4* Bu = (const uint4*)Bw;
    int K8 = K >> 3, N8 = N >> 3;

    float acc[2][8][4];
    #pragma unroll
    for (int mf = 0; mf < 2; mf++)
        #pragma unroll
        for (int nf = 0; nf < 8; nf++)
            #pragma unroll
            for (int r = 0; r < 4; r++) acc[mf][nf][r] = 0.f;

    // A: 2 chunks/thread: idx=i*256+t, row=idx>>2, c=idx&3 (8 halves at k=8c)
    // B: 2 chunks/thread: k=idx>>4, c=idx&15 (8 halves at n=8c), swizzled
    uint4 arv[2], brv[2];
    #pragma unroll
    for (int i = 0; i < 2; i++) {
        int idx = i * 256 + t;
        arv[i] = Au[(size_t)(row0 + (idx >> 2)) * K8 + (idx & 3)];
        brv[i] = Bu[(size_t)(idx >> 4) * N8 + (col0 >> 3) + (idx & 15)];
    }
    #pragma unroll
    for (int i = 0; i < 2; i++) {
        int idx = i * 256 + t;
        *(uint4*)&As[0][(idx >> 2) * AS_U + (idx & 3) * 4] = arv[i];
        int k = idx >> 4, c = idx & 15;
        *(uint4*)&Bs[0][k * 64 + ((c * 4) ^ ((k & 7) << 2))] = brv[i];
    }
    __syncthreads();

    uint32_t bsAddr[2];
    bsAddr[0] = (uint32_t)__cvta_generic_to_shared(Bs[0]);
    bsAddr[1] = (uint32_t)__cvta_generic_to_shared(Bs[1]);

    int nk = K / BK;
    for (int kt = 0; kt < nk; kt++) {
        int cur = kt & 1;
        if (kt + 1 < nk) {
            int k0n = (kt + 1) * BK;
            #pragma unroll
            for (int i = 0; i < 2; i++) {
                int idx = i * 256 + t;
                arv[i] = Au[(size_t)(row0 + (idx >> 2)) * K8 + (k0n >> 3) + (idx & 3)];
                brv[i] = Bu[(size_t)(k0n + (idx >> 4)) * N8 + (col0 >> 3) + (idx & 15)];
            }
        }
        const uint32_t* as = As[cur];
        #pragma unroll
        for (int ks = 0; ks < 2; ks++) {
            uint32_t af[2][4];
            #pragma unroll
            for (int mf = 0; mf < 2; mf++) {
                int r = warpM * 32 + mf * 16 + lr;
                af[mf][0] = as[r * AS_U + ks * 8 + lc];
                af[mf][1] = as[(r + 8) * AS_U + ks * 8 + lc];
                af[mf][2] = as[r * AS_U + ks * 8 + lc + 4];
                af[mf][3] = as[(r + 8) * AS_U + ks * 8 + lc + 4];
            }
            #pragma unroll
            for (int nfp = 0; nfp < 4; nfp++) {
                int krow = ks * 16 + (l & 15);
                int col = warpN * 32 + nfp * 8 + ((l >> 4) << 2);
                col ^= (krow & 7) << 2;
                uint32_t b0, b1, b2, b3;
                ldsm4t(b0, b1, b2, b3, bsAddr[cur] + (krow * 64 + col) * 4);
                #pragma unroll
                for (int mf = 0; mf < 2; mf++) {
                    mma_f16(acc[mf][2*nfp],   af[mf][0], af[mf][1], af[mf][2], af[mf][3], b0, b1);
                    mma_f16(acc[mf][2*nfp+1], af[mf][0], af[mf][1], af[mf][2], af[mf][3], b2, b3);
                }
            }
        }
        __syncthreads();
        if (kt + 1 < nk) {
            int nxt = cur ^ 1;
            #pragma unroll
            for (int i = 0; i < 2; i++) {
                int idx = i * 256 + t;
                *(uint4*)&As[nxt][(idx >> 2) * AS_U + (idx & 3) * 4] = arv[i];
                int k = idx >> 4, c = idx & 15;
                *(uint4*)&Bs[nxt][k * 64 + ((c * 4) ^ ((k & 7) << 2))] = brv[i];
            }
            __syncthreads();
        }
    }

    #pragma unroll
    for (int mf = 0; mf < 2; mf++) {
        #pragma unroll
        for (int half = 0; half < 2; half++) {
            int row = row0 + warpM * 32 + mf * 16 + lr + half * 8;
            #pragma unroll
            for (int nf = 0; nf < 8; nf++) {
                int col = col0 + warpN * 64 + nf * 8 + 2 * lc;
                float vx = acc[mf][nf][half * 2 + 0];
                float vy = acc[mf][nf][half * 2 + 1];
                size_t off = (size_t)row * N + col;
                if (mode == 0) {
                    vx = fminf(fmaxf(vx, -8.f), 8.f);
                    vy = fminf(fmaxf(vy, -8.f), 8.f);
                    *(uint32_t*)((__half*)Cp + off) = pkh2(vx, vy);
                } else {
                    float2 rv = *(const float2*)(resid + off);
                    float2 v; v.x = vx + rv.x; v.y = vy + rv.y;
                    *(float2*)((float*)Cp + off) = v;
                }
            }
        }
    }
}

// ---------------- RoPE table -------------------------------------------------
__global__ void rope_table_kernel(const int* __restrict__ pid)
{
    int idx = blockIdx.x * 256 + threadIdx.x;
    if (idx >= Bb * Ss * 32) return;
    int i = idx & 31;
    int s = (idx >> 5) & (Ss - 1);
    int b = idx >> 16;
    double pos = (double)pid[b * Ss + s];
    double inv = exp(-((double)(2 * i) / 64.0) * log(500000.0));
    double ang = pos * inv;
    g_cos[idx] = (float)cos(ang);
    g_sin[idx] = (float)sin(ang);
}

__global__ void rope_q_kernel()
{
    int idx = blockIdx.x * 256 + threadIdx.x;
    if (idx >= Bb * Ss * Hh * 32) return;
    int i = idx & 31;
    int h = (idx >> 5) & (Hh - 1);
    int s = (idx >> 10) & (Ss - 1);
    int b = idx >> 21;
    int tidx = (b << 16) + (s << 5) + i;
    float c = g_cos[tidx], sn = g_sin[tidx];
    const __half* src = g_qkv + (size_t)(b * Ss + s) * QKVN + h * HDd;
    float x1 = __half2float(src[i]), x2 = __half2float(src[i + 32]);
    __half* dst = g_q + ((size_t)(b * Hh + h) * Ss + s) * HDd;
    dst[i]      = __float2half_rn(x1 * c - x2 * sn);
    dst[i + 32] = __float2half_rn(x2 * c + x1 * sn);
}

__global__ void rope_kv_kernel()
{
    int idx = blockIdx.x * 256 + threadIdx.x;
    if (idx >= Bb * Ss * KVHh * 32) return;
    int i = idx & 31;
    int kvh = (idx >> 5) & (KVHh - 1);
    int s = (idx >> 8) & (Ss - 1);
    int b = idx >> 19;
    int tidx = (b << 16) + (s << 5) + i;
    float c = g_cos[tidx], sn = g_sin[tidx];
    const __half* srcb = g_qkv + (size_t)(b * Ss + s) * QKVN + Dd;
    const __half* srck = srcb + kvh * HDd;
    float x1 = __half2float(srck[i]), x2 = __half2float(srck[i + 32]);
    size_t hoff = ((size_t)(b * KVHh + kvh) * Ss + s) * HDd;
    g_k[hoff + i]      = __float2half_rn(x1 * c - x2 * sn);
    g_k[hoff + i + 32] = __float2half_rn(x2 * c + x1 * sn);
    const __half* srcv = srcb + KVHh * HDd + kvh * HDd;
    g_v[hoff + i]      = srcv[i];
    g_v[hoff + i + 32] = srcv[i + 32];
}

// ---------------- FP16 tensor-core flash attention -----------------------------
// 128 q rows/block, 8 warps x 16 rows; K/V tiles of 64, double buffered.
#define QP_U 36      // Q-stage / P stride in u32 (32 data + 4 pad)
#define KS_U 36      // K stride in u32
#define VS_U 32      // V stride (swizzled, no pad)
#define SM_PS 0
#define SM_KS (128 * QP_U)                 // 4608
#define SM_VS (SM_KS + 2 * 64 * KS_U)      // + 4608
#define SM_MASK (SM_VS + 2 * 64 * VS_U)    // + 4096
#define ATT_U32 (SM_MASK + 128)            // + mask 2x64
__global__ __launch_bounds__(256) void attn_kernel(const int* __restrict__ amask)
{
    extern __shared__ uint32_t smu[];
    uint32_t* Ps = smu + SM_PS;
    uint32_t* Ks[2] = { smu + SM_KS, smu + SM_KS + 64 * KS_U };
    uint32_t* Vs[2] = { smu + SM_VS, smu + SM_VS + 64 * VS_U };
    int* maskS = (int*)(smu + SM_MASK);

    int qt = blockIdx.x, h = blockIdx.y, b = blockIdx.z;
    int kvh = h >> 2;
    int q0 = qt * 128;
    int t = threadIdx.x;
    int w = t >> 5, l = t & 31;
    int lr = l >> 2, lc = l & 3;

    const uint4* Qg = (const uint4*)(g_q + ((size_t)(b * Hh + h) * Ss + q0) * HDd);
    const uint4* Kg = (const uint4*)(g_k + (size_t)(b * KVHh + kvh) * Ss * HDd);
    const uint4* Vg = (const uint4*)(g_v + (size_t)(b * KVHh + kvh) * Ss * HDd);
    const int*   Mg = amask + b * Ss;

    // ---- stage Q into Ps (8 uint4 per 64-half row) ----
    #pragma unroll
    for (int i = 0; i < 4; i++) {
        int idx = i * 256 + t;           // 1024 chunks
        int row = idx >> 3, c = idx & 7;
        *(uint4*)&Ps[row * QP_U + c * 4] = Qg[row * 8 + c];
    }
    __syncthreads();
    uint32_t qa[4][4];
    {
        int r0 = w * 16 + lr;
        #pragma unroll
        for (int ks = 0; ks < 4; ks++) {
            qa[ks][0] = Ps[r0 * QP_U + ks * 8 + lc];
            qa[ks][1] = Ps[(r0 + 8) * QP_U + ks * 8 + lc];
            qa[ks][2] = Ps[r0 * QP_U + ks * 8 + lc + 4];
            qa[ks][3] = Ps[(r0 + 8) * QP_U + ks * 8 + lc + 4];
        }
    }
    __syncthreads();

    uint32_t vsAddr[2];
    vsAddr[0] = (uint32_t)__cvta_generic_to_shared(Vs[0]);
    vsAddr[1] = (uint32_t)__cvta_generic_to_shared(Vs[1]);

    float m0 = -1e30f, m1 = -1e30f, l0 = 0.f, l1 = 0.f;
    float o[8][4];
    #pragma unroll
    for (int nf = 0; nf < 8; nf++)
        #pragma unroll
        for (int r = 0; r < 4; r++) o[nf][r] = 0.f;

    int nkt = 2 * qt + 2;
    // ---- prologue tile 0 ----
    #pragma unroll
    for (int i = 0; i < 2; i++) {
        int idx = i * 256 + t;           // 512 chunks each
        int row = idx >> 3, c = idx & 7;
        *(uint4*)&Ks[0][row * KS_U + c * 4] = Kg[row * 8 + c];
        *(uint4*)&Vs[0][row * VS_U + ((c * 4) ^ ((row & 7) << 2))] = Vg[row * 8 + c];
    }
    if (t < 64) maskS[t] = Mg[t];
    __syncthreads();

    for (int kt = 0; kt < nkt; kt++) {
        int cur = kt & 1;
        int k0 = kt * 64;
        uint4 kr[2], vr[2]; int mr = 1;
        if (kt + 1 < nkt) {
            int k0n = k0 + 64;
            #pragma unroll
            for (int i = 0; i < 2; i++) {
                int idx = i * 256 + t;
                int row = idx >> 3, c = idx & 7;
                kr[i] = Kg[(k0n + row) * 8 + c];
                vr[i] = Vg[(k0n + row) * 8 + c];
            }
            if (t < 64) mr = Mg[k0n + t];
        }

        int qlow = q0 + w * 16;
        bool active = (k0 <= qlow + 15);
        if (active) {
            // ---- S = Q K^T ----
            float s[8][4];
            #pragma unroll
            for (int nf = 0; nf < 8; nf++)
                #pragma unroll
                for (int r = 0; r < 4; r++) s[nf][r] = 0.f;
            const uint32_t* kb = Ks[cur];
            #pragma unroll
            for (int ks = 0; ks < 4; ks++) {
                #pragma unroll
                for (int nf = 0; nf < 8; nf++) {
                    int n = nf * 8 + lr;
                    uint32_t b0 = kb[n * KS_U + ks * 8 + lc];
                    uint32_t b1 = kb[n * KS_U + ks * 8 + lc + 4];
                    mma_f16(s[nf], qa[ks][0], qa[ks][1], qa[ks][2], qa[ks][3], b0, b1);
                }
            }
            // ---- mask + scale ----
            int qr0 = qlow + lr, qr1 = qr0 + 8;
            bool fullvis = (k0 + 63 <= qlow);
            #pragma unroll
            for (int nf = 0; nf < 8; nf++) {
                int kg0 = k0 + nf * 8 + 2 * lc;
                int ms0 = maskS[(cur << 6) + nf * 8 + 2 * lc];
                int ms1 = maskS[(cur << 6) + nf * 8 + 2 * lc + 1];
                s[nf][0] = (ms0 && (fullvis || kg0     <= qr0)) ? s[nf][0] * ATT_SCALE : -1e30f;
                s[nf][1] = (ms1 && (fullvis || kg0 + 1 <= qr0)) ? s[nf][1] * ATT_SCALE : -1e30f;
                s[nf][2] = (ms0 && (fullvis || kg0     <= qr1)) ? s[nf][2] * ATT_SCALE : -1e30f;
                s[nf][3] = (ms1 && (fullvis || kg0 + 1 <= qr1)) ? s[nf][3] * ATT_SCALE : -1e30f;
            }
            // ---- online softmax ----
            float mt0 = -1e30f, mt1 = -1e30f;
            #pragma unroll
            for (int nf = 0; nf < 8; nf++) {
                mt0 = fmaxf(mt0, fmaxf(s[nf][0], s[nf][1]));
                mt1 = fmaxf(mt1, fmaxf(s[nf][2], s[nf][3]));
            }
            mt0 = fmaxf(mt0, __shfl_xor_sync(0xffffffffu, mt0, 1));
            mt0 = fmaxf(mt0, __shfl_xor_sync(0xffffffffu, mt0, 2));
            mt1 = fmaxf(mt1, __shfl_xor_sync(0xffffffffu, mt1, 1));
            mt1 = fmaxf(mt1, __shfl_xor_sync(0xffffffffu, mt1, 2));
            float mn0 = fmaxf(m0, mt0), mn1 = fmaxf(m1, mt1);
            float rs0 = 0.f, rs1 = 0.f;
            #pragma unroll
            for (int nf = 0; nf < 8; nf++) {
                s[nf][0] = expf(s[nf][0] - mn0);
                s[nf][1] = expf(s[nf][1] - mn0);
                s[nf][2] = expf(s[nf][2] - mn1);
                s[nf][3] = expf(s[nf][3] - mn1);
                rs0 += s[nf][0] + s[nf][1];
                rs1 += s[nf][2] + s[nf][3];
            }
            rs0 += __shfl_xor_sync(0xffffffffu, rs0, 1);
            rs0 += __shfl_xor_sync(0xffffffffu, rs0, 2);
            rs1 += __shfl_xor_sync(0xffffffffu, rs1, 1);
            rs1 += __shfl_xor_sync(0xffffffffu, rs1, 2);
            float a0 = expf(m0 - mn0), a1 = expf(m1 - mn1);
            l0 = l0 * a0 + rs0;  l1 = l1 * a1 + rs1;
            m0 = mn0;  m1 = mn1;
            #pragma unroll
            for (int nf = 0; nf < 8; nf++) {
                o[nf][0] *= a0; o[nf][1] *= a0;
                o[nf][2] *= a1; o[nf][3] *= a1;
            }
            // ---- P -> warp-private smem (fp16) ----
            {
                int r0 = w * 16 + lr;
                #pragma unroll
                for (int nf = 0; nf < 8; nf++) {
                    Ps[r0 * QP_U + nf * 4 + lc]       = pkh2(s[nf][0], s[nf][1]);
                    Ps[(r0 + 8) * QP_U + nf * 4 + lc] = pkh2(s[nf][2], s[nf][3]);
                }
            }
            __syncwarp();
            // ---- O += P V (V via ldmatrix.trans) ----
            {
                int r0 = w * 16 + lr;
                #pragma unroll
                for (int ks = 0; ks < 4; ks++) {
                    uint32_t pa0 = Ps[r0 * QP_U + ks * 8 + lc];
                    uint32_t pa1 = Ps[(r0 + 8) * QP_U + ks * 8 + lc];
                    uint32_t pa2 = Ps[r0 * QP_U + ks * 8 + lc + 4];
                    uint32_t pa3 = Ps[(r0 + 8) * QP_U + ks * 8 + lc + 4];
                    #pragma unroll
                    for (int nfp = 0; nfp < 4; nfp++) {
                        int key = ks * 16 + (l & 15);
                        int col = nfp * 8 + ((l >> 4) << 2);
                        col ^= (key & 7) << 2;
                        uint32_t b0, b1, b2, b3;
                        ldsm4t(b0, b1, b2, b3, vsAddr[cur] + (key * VS_U + col) * 4);
                        mma_f16(o[2*nfp],   pa0, pa1, pa2, pa3, b0, b1);
                        mma_f16(o[2*nfp+1], pa0, pa1, pa2, pa3, b2, b3);
                    }
                }
            }
        }
        __syncthreads();
        if (kt + 1 < nkt) {
            int nxt = cur ^ 1;
            #pragma unroll
            for (int i = 0; i < 2; i++) {
                int idx = i * 256 + t;
                int row = idx >> 3, c = idx & 7;
                *(uint4*)&Ks[nxt][row * KS_U + c * 4] = kr[i];
                *(uint4*)&Vs[nxt][row * VS_U + ((c * 4) ^ ((row & 7) << 2))] = vr[i];
            }
            if (t < 64) maskS[(nxt << 6) + t] = mr;
            __syncthreads();
        }
    }

    // ---- normalize + store (half) ----
    float il0 = (l0 > 0.f) ? (1.f / l0) : 0.f;
    float il1 = (l1 > 0.f) ? (1.f / l1) : 0.f;
    int qr0 = q0 + w * 16 + lr;
    __half* d0 = g_attn + (size_t)(b * Ss + qr0) * Dd + h * HDd;
    __half* d1 = g_attn + (size_t)(b * Ss + qr0 + 8) * Dd + h * HDd;
    #pragma unroll
    for (int nf = 0; nf < 8; nf++) {
        int c = nf * 8 + 2 * lc;
        *(uint32_t*)(d0 + c) = pkh2(o[nf][0] * il0, o[nf][1] * il0);
        *(uint32_t*)(d1 + c) = pkh2(o[nf][2] * il1, o[nf][3] * il1);
    }
}

// ---------------- launch ------------------------------------------------------
extern "C" void kernel_launch(void* const* d_in, const int* in_sizes, int n_in,
                              void* d_out, int out_size)
{
    const float* hs   = (const float*)d_in[0];
    const int*   am   = (const int*)  d_in[1];
    const int*   pid  = (const int*)  d_in[2];
    const float* ln1  = (const float*)d_in[4];
    const float* wqkv = (const float*)d_in[5];
    const float* wout = (const float*)d_in[6];
    const float* ln2  = (const float*)d_in[7];
    float* out = (float*)d_out;

    __half *px, *pqkv, *pattn, *pwq, *pwo;
    cudaGetSymbolAddress((void**)&px,    g_x);
    cudaGetSymbolAddress((void**)&pqkv,  g_qkv);
    cudaGetSymbolAddress((void**)&pattn, g_attn);
    cudaGetSymbolAddress((void**)&pwq,   g_wqkvh);
    cudaGetSymbolAddress((void**)&pwo,   g_wouth);

    const int ATTN_SMEM = ATT_U32 * 4;               // 54272 B
    cudaFuncSetAttribute(attn_kernel,
                         cudaFuncAttributeMaxDynamicSharedMemorySize, ATTN_SMEM);
    const int GEMM_SMEM = 2 * STAGE_U * 4;           // 36864 B
    cudaFuncSetAttribute(gemm_f16_kernel,
                         cudaFuncAttributeMaxDynamicSharedMemorySize, GEMM_SMEM);

    // weights -> fp16
    cvt_kernel<<<(Dd * QKVN / 4 + 255) / 256, 256>>>(wqkv, pwq, Dd * QKVN / 4);
    cvt_kernel<<<(Dd * Dd / 4 + 255) / 256, 256>>>(wout, pwo, Dd * Dd / 4);
    // LN1 -> half
    ln_kernel<<<Mrows, 256>>>(hs, ln1, px, 1);
    rope_table_kernel<<<(Bb * Ss * 32) / 256, 256>>>(pid);
    // qkv = clip(x @ w_qkv) -> half
    gemm_f16_kernel<<<dim3(QKVN / BN, Mrows / BM), 256, GEMM_SMEM>>>(
        px, pwq, pqkv, Mrows, QKVN, Dd, 0, nullptr);
    rope_q_kernel<<<(Bb * Ss * Hh * 32) / 256, 256>>>();
    rope_kv_kernel<<<(Bb * Ss * KVHh * 32) / 256, 256>>>();
    attn_kernel<<<dim3(Ss / 128, Hh, Bb), 256, ATTN_SMEM>>>(am);
    // residual2 = attn @ w_out + hidden -> fp32 d_out
    gemm_f16_kernel<<<dim3(Dd / BN, Mrows / BM), 256, GEMM_SMEM>>>(
        pattn, pwo, out, Mrows, Dd, Dd, 1, hs);
    // hidden = LN2(residual2) -> fp32
    ln_kernel<<<Mrows, 256>>>(out, ln2, out + OUTOFF, 0);
}

// round 5
// speedup vs baseline: 11.4839x; 1.7138x over previous
#include <cuda_runtime.h>
#include <cuda_fp16.h>
#include <math.h>
#include <stdint.h>

#define Bb    2
#define Ss    2048
#define Dd    2048
#define Hh    32
#define KVHh  8
#define HDd   64
#define QKVN  3072
#define Mrows (Bb*Ss)
#define OUTOFF ((size_t)Bb*Ss*Dd)
#define ATT_SCALE 0.125f

// ---------------- scratch ----------------------------------------------------
__device__ __half g_x[(size_t)Mrows*Dd];
__device__ __half g_qkv[(size_t)Mrows*QKVN];
__device__ __half g_q[(size_t)Bb*Hh*Ss*HDd];
__device__ __half g_k[(size_t)Bb*KVHh*Ss*HDd];
__device__ __half g_v[(size_t)Bb*KVHh*Ss*HDd];
__device__ __half g_attn[(size_t)Mrows*Dd];
__device__ __half g_wqkvh[(size_t)Dd*QKVN];
__device__ __half g_wouth[(size_t)Dd*Dd];
__device__ float g_cos[(size_t)Bb*Ss*32];
__device__ float g_sin[(size_t)Bb*Ss*32];
__device__ double g_invf[32];

__device__ __forceinline__ uint32_t pkh2(float x, float y) {
    __half2 h = __floats2half2_rn(x, y);
    return *(uint32_t*)&h;
}
__device__ __forceinline__ void mma_f16(float c[4], uint32_t a0, uint32_t a1,
                                        uint32_t a2, uint32_t a3,
                                        uint32_t b0, uint32_t b1)
{
    asm volatile(
        "mma.sync.aligned.m16n8k16.row.col.f32.f16.f16.f32 "
        "{%0,%1,%2,%3}, {%4,%5,%6,%7}, {%8,%9}, {%0,%1,%2,%3};"
        : "+f"(c[0]), "+f"(c[1]), "+f"(c[2]), "+f"(c[3])
        : "r"(a0), "r"(a1), "r"(a2), "r"(a3), "r"(b0), "r"(b1));
}
__device__ __forceinline__ void ldsm4t(uint32_t& r0, uint32_t& r1,
                                       uint32_t& r2, uint32_t& r3, uint32_t saddr)
{
    asm volatile(
        "ldmatrix.sync.aligned.m8n8.x4.trans.shared.b16 {%0,%1,%2,%3}, [%4];"
        : "=r"(r0), "=r"(r1), "=r"(r2), "=r"(r3) : "r"(r3), "r"(saddr));
}
// fixed version (above had a typo risk; define properly)
__device__ __forceinline__ void ldsm4t_ok(uint32_t& r0, uint32_t& r1,
                                          uint32_t& r2, uint32_t& r3, uint32_t saddr)
{
    asm volatile(
        "ldmatrix.sync.aligned.m8n8.x4.trans.shared.b16 {%0,%1,%2,%3}, [%4];"
        : "=r"(r0), "=r"(r1), "=r"(r2), "=r"(r3) : "r"(saddr));
}
__device__ __forceinline__ void cpa16(uint32_t smem_addr, const void* gptr) {
    asm volatile("cp.async.cg.shared.global [%0], [%1], 16;"
                 :: "r"(smem_addr), "l"(gptr));
}
__device__ __forceinline__ void cpa_commit() {
    asm volatile("cp.async.commit_group;");
}
template<int N>
__device__ __forceinline__ void cpa_wait() {
    asm volatile("cp.async.wait_group %0;" :: "n"(N));
}

// ---------------- weight fp32 -> fp16 (both tensors, one kernel) --------------
__global__ void cvt2_kernel(const float* __restrict__ w1, __half* __restrict__ o1,
                            int n1, const float* __restrict__ w2,
                            __half* __restrict__ o2, int n2)
{
    int i = blockIdx.x * 256 + threadIdx.x;
    const float* src; __half* dst;
    if (i < n1) { src = w1 + (size_t)i * 4; dst = o1 + (size_t)i * 4; }
    else {
        i -= n1;
        if (i >= n2) return;
        src = w2 + (size_t)i * 4; dst = o2 + (size_t)i * 4;
    }
    float4 v = *(const float4*)src;
    uint32_t* d = (uint32_t*)dst;
    d[0] = pkh2(v.x, v.y);
    d[1] = pkh2(v.z, v.w);
}

// ---------------- LayerNorm ---------------------------------------------------
__global__ __launch_bounds__(256) void ln_kernel(
    const float* __restrict__ in, const float* __restrict__ sc,
    void* __restrict__ outp, int half_out)
{
    int row = blockIdx.x;
    const float* x = in + (size_t)row * Dd;
    float s = 0.f, s2 = 0.f;
    for (int i = threadIdx.x; i < Dd; i += 256) { float v = x[i]; s += v; s2 += v*v; }
    #pragma unroll
    for (int o = 16; o; o >>= 1) {
        s  += __shfl_xor_sync(0xffffffffu, s,  o);
        s2 += __shfl_xor_sync(0xffffffffu, s2, o);
    }
    __shared__ float ws[8], ws2[8];
    int w = threadIdx.x >> 5, l = threadIdx.x & 31;
    if (l == 0) { ws[w] = s; ws2[w] = s2; }
    __syncthreads();
    if (threadIdx.x < 32) {
        s  = (l < 8) ? ws[l]  : 0.f;
        s2 = (l < 8) ? ws2[l] : 0.f;
        #pragma unroll
        for (int o = 4; o; o >>= 1) {
            s  += __shfl_xor_sync(0xffffffffu, s,  o);
            s2 += __shfl_xor_sync(0xffffffffu, s2, o);
        }
        if (l == 0) { ws[0] = s; ws2[0] = s2; }
    }
    __syncthreads();
    float mean = ws[0] * (1.f / Dd);
    float var  = ws2[0] * (1.f / Dd) - mean * mean;
    float inv  = rsqrtf(var + 1e-6f);
    if (half_out) {
        __half* o_ = (__half*)outp + (size_t)row * Dd;
        for (int i = threadIdx.x * 2; i < Dd; i += 512) {
            float a = (x[i] - mean) * inv * sc[i];
            float b = (x[i+1] - mean) * inv * sc[i+1];
            *(uint32_t*)(o_ + i) = pkh2(a, b);
        }
    } else {
        float* o_ = (float*)outp + (size_t)row * Dd;
        for (int i = threadIdx.x; i < Dd; i += 256)
            o_[i] = (x[i] - mean) * inv * sc[i];
    }
}

// ---------------- FP16 GEMM 128x128x32, 3-stage cp.async ----------------------
#define BM 128
#define BN 128
#define BK 32
#define AS_U 20
#define AS_U32S (BM * AS_U)        // 2560
#define BS_U32S (BK * 64)          // 2048
#define STAGE_U (AS_U32S + BS_U32S)
#define NSTG 3

__global__ __launch_bounds__(256) void gemm_f16_kernel(
    const __half* __restrict__ A, const __half* __restrict__ Bw,
    void* __restrict__ Cp, int M, int N, int K, int mode,
    const float* __restrict__ resid)
{
    extern __shared__ uint32_t smu[];
    int row0 = blockIdx.y * BM, col0 = blockIdx.x * BN;
    int t = threadIdx.x;
    int w = t >> 5, l = t & 31;
    int warpM = w >> 1, warpN = w & 1;
    int lr = l >> 2, lc = l & 3;

    const uint4* Au = (const uint4*)A;
    const uint4* Bu = (const uint4*)Bw;
    int K8 = K >> 3, N8 = N >> 3;

    uint32_t stAddr[NSTG];
    #pragma unroll
    for (int sidx = 0; sidx < NSTG; sidx++)
        stAddr[sidx] = (uint32_t)__cvta_generic_to_shared(smu + sidx * STAGE_U);

    // per-thread load slots (2 A chunks, 2 B chunks)
    int aRow[2], aC[2], bK[2], bDst[2];
    #pragma unroll
    for (int i = 0; i < 2; i++) {
        int idx = i * 256 + t;
        aRow[i] = idx >> 2;  aC[i] = idx & 3;
        int k = idx >> 4, c = idx & 15;
        bK[i] = k;
        bDst[i] = k * 64 + ((c * 4) ^ ((k & 7) << 2));
    }
    int bC0 = (col0 >> 3);

    float acc[2][8][4];
    #pragma unroll
    for (int mf = 0; mf < 2; mf++)
        #pragma unroll
        for (int nf = 0; nf < 8; nf++)
            #pragma unroll
            for (int r = 0; r < 4; r++) acc[mf][nf][r] = 0.f;

    int nk = K / BK;
    // issue loads for tile kt into stage stg
    auto issue = [&](int kt, int stg) {
        if (kt < nk) {
            int k0 = kt * BK;
            uint32_t aBase = stAddr[stg];
            uint32_t bBase = stAddr[stg] + AS_U32S * 4;
            #pragma unroll
            for (int i = 0; i < 2; i++) {
                cpa16(aBase + (aRow[i] * AS_U + aC[i] * 4) * 4,
                      Au + (size_t)(row0 + aRow[i]) * K8 + (k0 >> 3) + aC[i]);
                int idx = i * 256 + t;
                cpa16(bBase + bDst[i] * 4,
                      Bu + (size_t)(k0 + bK[i]) * N8 + bC0 + (idx & 15));
            }
        }
        cpa_commit();
    };

    issue(0, 0);
    issue(1, 1);

    for (int kt = 0; kt < nk; kt++) {
        cpa_wait<1>();
        __syncthreads();
        issue(kt + 2, (kt + 2) % NSTG);

        int cur = kt % NSTG;
        const uint32_t* as = smu + cur * STAGE_U;
        uint32_t bsAddr = stAddr[cur] + AS_U32S * 4;
        #pragma unroll
        for (int ks = 0; ks < 2; ks++) {
            uint32_t af[2][4];
            #pragma unroll
            for (int mf = 0; mf < 2; mf++) {
                int r = warpM * 32 + mf * 16 + lr;
                af[mf][0] = as[r * AS_U + ks * 8 + lc];
                af[mf][1] = as[(r + 8) * AS_U + ks * 8 + lc];
                af[mf][2] = as[r * AS_U + ks * 8 + lc + 4];
                af[mf][3] = as[(r + 8) * AS_U + ks * 8 + lc + 4];
            }
            #pragma unroll
            for (int nfp = 0; nfp < 4; nfp++) {
                int krow = ks * 16 + (l & 15);
                int col = warpN * 32 + nfp * 8 + ((l >> 4) << 2);
                col ^= (krow & 7) << 2;
                uint32_t b0, b1, b2, b3;
                ldsm4t_ok(b0, b1, b2, b3, bsAddr + (krow * 64 + col) * 4);
                #pragma unroll
                for (int mf = 0; mf < 2; mf++) {
                    mma_f16(acc[mf][2*nfp],   af[mf][0], af[mf][1], af[mf][2], af[mf][3], b0, b1);
                    mma_f16(acc[mf][2*nfp+1], af[mf][0], af[mf][1], af[mf][2], af[mf][3], b2, b3);
                }
            }
        }
        __syncthreads();
    }

    #pragma unroll
    for (int mf = 0; mf < 2; mf++) {
        #pragma unroll
        for (int half = 0; half < 2; half++) {
            int row = row0 + warpM * 32 + mf * 16 + lr + half * 8;
            #pragma unroll
            for (int nf = 0; nf < 8; nf++) {
                int col = col0 + warpN * 64 + nf * 8 + 2 * lc;
                float vx = acc[mf][nf][half * 2 + 0];
                float vy = acc[mf][nf][half * 2 + 1];
                size_t off = (size_t)row * N + col;
                if (mode == 0) {
                    vx = fminf(fmaxf(vx, -8.f), 8.f);
                    vy = fminf(fmaxf(vy, -8.f), 8.f);
                    *(uint32_t*)((__half*)Cp + off) = pkh2(vx, vy);
                } else {
                    float2 rv = *(const float2*)(resid + off);
                    float2 v; v.x = vx + rv.x; v.y = vy + rv.y;
                    *(float2*)((float*)Cp + off) = v;
                }
            }
        }
    }
}

// ---------------- RoPE: inv_freq (32 threads, FP64 once) ----------------------
__global__ void invf_kernel()
{
    int i = threadIdx.x;
    if (i < 32)
        g_invf[i] = exp(-((double)(2 * i) / 64.0) * log(500000.0));
}

// ---------------- RoPE table: cheap DP range-reduce + SP trig ------------------
__global__ void rope_table_kernel(const int* __restrict__ pid)
{
    int idx = blockIdx.x * 256 + threadIdx.x;
    if (idx >= Bb * Ss * 32) return;
    int i = idx & 31;
    int s = (idx >> 5) & (Ss - 1);
    int b = idx >> 16;
    double pos = (double)pid[b * Ss + s];
    double ang = pos * g_invf[i];
    double k = rint(ang * 0.15915494309189535);      // /(2*pi)
    float r = (float)(ang - k * 6.283185307179586);  // |r| <= pi
    g_cos[idx] = cosf(r);
    g_sin[idx] = sinf(r);
}

// ---------------- RoPE apply (Q + K + V copy, one kernel) ----------------------
__global__ void rope_apply_kernel()
{
    int idx = blockIdx.x * 256 + threadIdx.x;  // B*S*40*32
    int i = idx & 31;
    int tmp = idx >> 5;
    int hh = tmp % 40;
    int bs = tmp / 40;
    int s = bs & (Ss - 1);
    int b = bs >> 11;
    int tidx = (b << 16) + (s << 5) + i;
    float c = g_cos[tidx], sn = g_sin[tidx];
    if (hh < 32) {                   // Q head
        const __half* src = g_qkv + (size_t)(b * Ss + s) * QKVN + hh * HDd;
        float x1 = __half2float(src[i]), x2 = __half2float(src[i + 32]);
        __half* dst = g_q + ((size_t)(b * Hh + hh) * Ss + s) * HDd;
        dst[i]      = __float2half_rn(x1 * c - x2 * sn);
        dst[i + 32] = __float2half_rn(x2 * c + x1 * sn);
    } else {                         // KV head
        int kvh = hh - 32;
        const __half* srcb = g_qkv + (size_t)(b * Ss + s) * QKVN + Dd;
        const __half* srck = srcb + kvh * HDd;
        float x1 = __half2float(srck[i]), x2 = __half2float(srck[i + 32]);
        size_t hoff = ((size_t)(b * KVHh + kvh) * Ss + s) * HDd;
        g_k[hoff + i]      = __float2half_rn(x1 * c - x2 * sn);
        g_k[hoff + i + 32] = __float2half_rn(x2 * c + x1 * sn);
        const __half* srcv = srcb + KVHh * HDd + kvh * HDd;
        g_v[hoff + i]      = srcv[i];
        g_v[hoff + i + 32] = srcv[i + 32];
    }
}

// ---------------- FP16 tensor-core flash attention -----------------------------
#define QP_U 36
#define KS_U 36
#define VS_U 32
#define SM_PS 0
#define SM_KS (128 * QP_U)
#define SM_VS (SM_KS + 2 * 64 * KS_U)
#define SM_MASK (SM_VS + 2 * 64 * VS_U)
#define ATT_U32 (SM_MASK + 128)
__global__ __launch_bounds__(256) void attn_kernel(const int* __restrict__ amask)
{
    extern __shared__ uint32_t smu[];
    uint32_t* Ps = smu + SM_PS;
    uint32_t* Ks[2] = { smu + SM_KS, smu + SM_KS + 64 * KS_U };
    uint32_t* Vs[2] = { smu + SM_VS, smu + SM_VS + 64 * VS_U };
    int* maskS = (int*)(smu + SM_MASK);

    int qt = blockIdx.x, h = blockIdx.y, b = blockIdx.z;
    int kvh = h >> 2;
    int q0 = qt * 128;
    int t = threadIdx.x;
    int w = t >> 5, l = t & 31;
    int lr = l >> 2, lc = l & 3;

    const uint4* Qg = (const uint4*)(g_q + ((size_t)(b * Hh + h) * Ss + q0) * HDd);
    const uint4* Kg = (const uint4*)(g_k + (size_t)(b * KVHh + kvh) * Ss * HDd);
    const uint4* Vg = (const uint4*)(g_v + (size_t)(b * KVHh + kvh) * Ss * HDd);
    const int*   Mg = amask + b * Ss;

    #pragma unroll
    for (int i = 0; i < 4; i++) {
        int idx = i * 256 + t;
        int row = idx >> 3, c = idx & 7;
        *(uint4*)&Ps[row * QP_U + c * 4] = Qg[row * 8 + c];
    }
    __syncthreads();
    uint32_t qa[4][4];
    {
        int r0 = w * 16 + lr;
        #pragma unroll
        for (int ks = 0; ks < 4; ks++) {
            qa[ks][0] = Ps[r0 * QP_U + ks * 8 + lc];
            qa[ks][1] = Ps[(r0 + 8) * QP_U + ks * 8 + lc];
            qa[ks][2] = Ps[r0 * QP_U + ks * 8 + lc + 4];
            qa[ks][3] = Ps[(r0 + 8) * QP_U + ks * 8 + lc + 4];
        }
    }
    __syncthreads();

    uint32_t vsAddr[2];
    vsAddr[0] = (uint32_t)__cvta_generic_to_shared(Vs[0]);
    vsAddr[1] = (uint32_t)__cvta_generic_to_shared(Vs[1]);

    float m0 = -1e30f, m1 = -1e30f, l0 = 0.f, l1 = 0.f;
    float o[8][4];
    #pragma unroll
    for (int nf = 0; nf < 8; nf++)
        #pragma unroll
        for (int r = 0; r < 4; r++) o[nf][r] = 0.f;

    int nkt = 2 * qt + 2;
    #pragma unroll
    for (int i = 0; i < 2; i++) {
        int idx = i * 256 + t;
        int row = idx >> 3, c = idx & 7;
        *(uint4*)&Ks[0][row * KS_U + c * 4] = Kg[row * 8 + c];
        *(uint4*)&Vs[0][row * VS_U + ((c * 4) ^ ((row & 7) << 2))] = Vg[row * 8 + c];
    }
    if (t < 64) maskS[t] = Mg[t];
    __syncthreads();

    for (int kt = 0; kt < nkt; kt++) {
        int cur = kt & 1;
        int k0 = kt * 64;
        uint4 kr[2], vr[2]; int mr = 1;
        if (kt + 1 < nkt) {
            int k0n = k0 + 64;
            #pragma unroll
            for (int i = 0; i < 2; i++) {
                int idx = i * 256 + t;
                int row = idx >> 3, c = idx & 7;
                kr[i] = Kg[(k0n + row) * 8 + c];
                vr[i] = Vg[(k0n + row) * 8 + c];
            }
            if (t < 64) mr = Mg[k0n + t];
        }

        int qlow = q0 + w * 16;
        bool active = (k0 <= qlow + 15);
        if (active) {
            float s[8][4];
            #pragma unroll
            for (int nf = 0; nf < 8; nf++)
                #pragma unroll
                for (int r = 0; r < 4; r++) s[nf][r] = 0.f;
            const uint32_t* kb = Ks[cur];
            #pragma unroll
            for (int ks = 0; ks < 4; ks++) {
                #pragma unroll
                for (int nf = 0; nf < 8; nf++) {
                    int n = nf * 8 + lr;
                    uint32_t b0 = kb[n * KS_U + ks * 8 + lc];
                    uint32_t b1 = kb[n * KS_U + ks * 8 + lc + 4];
                    mma_f16(s[nf], qa[ks][0], qa[ks][1], qa[ks][2], qa[ks][3], b0, b1);
                }
            }
            int qr0 = qlow + lr, qr1 = qr0 + 8;
            bool fullvis = (k0 + 63 <= qlow);
            #pragma unroll
            for (int nf = 0; nf < 8; nf++) {
                int kg0 = k0 + nf * 8 + 2 * lc;
                int ms0 = maskS[(cur << 6) + nf * 8 + 2 * lc];
                int ms1 = maskS[(cur << 6) + nf * 8 + 2 * lc + 1];
                s[nf][0] = (ms0 && (fullvis || kg0     <= qr0)) ? s[nf][0] * ATT_SCALE : -1e30f;
                s[nf][1] = (ms1 && (fullvis || kg0 + 1 <= qr0)) ? s[nf][1] * ATT_SCALE : -1e30f;
                s[nf][2] = (ms0 && (fullvis || kg0     <= qr1)) ? s[nf][2] * ATT_SCALE : -1e30f;
                s[nf][3] = (ms1 && (fullvis || kg0 + 1 <= qr1)) ? s[nf][3] * ATT_SCALE : -1e30f;
            }
            float mt0 = -1e30f, mt1 = -1e30f;
            #pragma unroll
            for (int nf = 0; nf < 8; nf++) {
                mt0 = fmaxf(mt0, fmaxf(s[nf][0], s[nf][1]));
                mt1 = fmaxf(mt1, fmaxf(s[nf][2], s[nf][3]));
            }
            mt0 = fmaxf(mt0, __shfl_xor_sync(0xffffffffu, mt0, 1));
            mt0 = fmaxf(mt0, __shfl_xor_sync(0xffffffffu, mt0, 2));
            mt1 = fmaxf(mt1, __shfl_xor_sync(0xffffffffu, mt1, 1));
            mt1 = fmaxf(mt1, __shfl_xor_sync(0xffffffffu, mt1, 2));
            float mn0 = fmaxf(m0, mt0), mn1 = fmaxf(m1, mt1);
            float rs0 = 0.f, rs1 = 0.f;
            #pragma unroll
            for (int nf = 0; nf < 8; nf++) {
                s[nf][0] = expf(s[nf][0] - mn0);
                s[nf][1] = expf(s[nf][1] - mn0);
                s[nf][2] = expf(s[nf][2] - mn1);
                s[nf][3] = expf(s[nf][3] - mn1);
                rs0 += s[nf][0] + s[nf][1];
                rs1 += s[nf][2] + s[nf][3];
            }
            rs0 += __shfl_xor_sync(0xffffffffu, rs0, 1);
            rs0 += __shfl_xor_sync(0xffffffffu, rs0, 2);
            rs1 += __shfl_xor_sync(0xffffffffu, rs1, 1);
            rs1 += __shfl_xor_sync(0xffffffffu, rs1, 2);
            float a0 = expf(m0 - mn0), a1 = expf(m1 - mn1);
            l0 = l0 * a0 + rs0;  l1 = l1 * a1 + rs1;
            m0 = mn0;  m1 = mn1;
            #pragma unroll
            for (int nf = 0; nf < 8; nf++) {
                o[nf][0] *= a0; o[nf][1] *= a0;
                o[nf][2] *= a1; o[nf][3] *= a1;
            }
            {
                int r0 = w * 16 + lr;
                #pragma unroll
                for (int nf = 0; nf < 8; nf++) {
                    Ps[r0 * QP_U + nf * 4 + lc]       = pkh2(s[nf][0], s[nf][1]);
                    Ps[(r0 + 8) * QP_U + nf * 4 + lc] = pkh2(s[nf][2], s[nf][3]);
                }
            }
            __syncwarp();
            {
                int r0 = w * 16 + lr;
                #pragma unroll
                for (int ks = 0; ks < 4; ks++) {
                    uint32_t pa0 = Ps[r0 * QP_U + ks * 8 + lc];
                    uint32_t pa1 = Ps[(r0 + 8) * QP_U + ks * 8 + lc];
                    uint32_t pa2 = Ps[r0 * QP_U + ks * 8 + lc + 4];
                    uint32_t pa3 = Ps[(r0 + 8) * QP_U + ks * 8 + lc + 4];
                    #pragma unroll
                    for (int nfp = 0; nfp < 4; nfp++) {
                        int key = ks * 16 + (l & 15);
                        int col = nfp * 8 + ((l >> 4) << 2);
                        col ^= (key & 7) << 2;
                        uint32_t b0, b1, b2, b3;
                        ldsm4t_ok(b0, b1, b2, b3, vsAddr[cur] + (key * VS_U + col) * 4);
                        mma_f16(o[2*nfp],   pa0, pa1, pa2, pa3, b0, b1);
                        mma_f16(o[2*nfp+1], pa0, pa1, pa2, pa3, b2, b3);
                    }
                }
            }
        }
        __syncthreads();
        if (kt + 1 < nkt) {
            int nxt = cur ^ 1;
            #pragma unroll
            for (int i = 0; i < 2; i++) {
                int idx = i * 256 + t;
                int row = idx >> 3, c = idx & 7;
                *(uint4*)&Ks[nxt][row * KS_U + c * 4] = kr[i];
                *(uint4*)&Vs[nxt][row * VS_U + ((c * 4) ^ ((row & 7) << 2))] = vr[i];
            }
            if (t < 64) maskS[(nxt << 6) + t] = mr;
            __syncthreads();
        }
    }

    float il0 = (l0 > 0.f) ? (1.f / l0) : 0.f;
    float il1 = (l1 > 0.f) ? (1.f / l1) : 0.f;
    int qr0 = q0 + w * 16 + lr;
    __half* d0 = g_attn + (size_t)(b * Ss + qr0) * Dd + h * HDd;
    __half* d1 = g_attn + (size_t)(b * Ss + qr0 + 8) * Dd + h * HDd;
    #pragma unroll
    for (int nf = 0; nf < 8; nf++) {
        int c = nf * 8 + 2 * lc;
        *(uint32_t*)(d0 + c) = pkh2(o[nf][0] * il0, o[nf][1] * il0);
        *(uint32_t*)(d1 + c) = pkh2(o[nf][2] * il1, o[nf][3] * il1);
    }
}

// ---------------- launch ------------------------------------------------------
extern "C" void kernel_launch(void* const* d_in, const int* in_sizes, int n_in,
                              void* d_out, int out_size)
{
    const float* hs   = (const float*)d_in[0];
    const int*   am   = (const int*)  d_in[1];
    const int*   pid  = (const int*)  d_in[2];
    const float* ln1  = (const float*)d_in[4];
    const float* wqkv = (const float*)d_in[5];
    const float* wout = (const float*)d_in[6];
    const float* ln2  = (const float*)d_in[7];
    float* out = (float*)d_out;

    __half *px, *pqkv, *pattn, *pwq, *pwo;
    cudaGetSymbolAddress((void**)&px,    g_x);
    cudaGetSymbolAddress((void**)&pqkv,  g_qkv);
    cudaGetSymbolAddress((void**)&pattn, g_attn);
    cudaGetSymbolAddress((void**)&pwq,   g_wqkvh);
    cudaGetSymbolAddress((void**)&pwo,   g_wouth);

    const int ATTN_SMEM = ATT_U32 * 4;
    cudaFuncSetAttribute(attn_kernel,
                         cudaFuncAttributeMaxDynamicSharedMemorySize, ATTN_SMEM);
    const int GEMM_SMEM = NSTG * STAGE_U * 4;        // 55296 B
    cudaFuncSetAttribute(gemm_f16_kernel,
                         cudaFuncAttributeMaxDynamicSharedMemorySize, GEMM_SMEM);

    int n1 = Dd * QKVN / 4, n2 = Dd * Dd / 4;
    cvt2_kernel<<<(n1 + n2 + 255) / 256, 256>>>(wqkv, pwq, n1, wout, pwo, n2);
    invf_kernel<<<1, 32>>>();
    ln_kernel<<<Mrows, 256>>>(hs, ln1, px, 1);
    rope_table_kernel<<<(Bb * Ss * 32) / 256, 256>>>(pid);
    gemm_f16_kernel<<<dim3(QKVN / BN, Mrows / BM), 256, GEMM_SMEM>>>(
        px, pwq, pqkv, Mrows, QKVN, Dd, 0, nullptr);
    rope_apply_kernel<<<(Bb * Ss * 40 * 32) / 256, 256>>>();
    attn_kernel<<<dim3(Ss / 128, Hh, Bb), 256, ATTN_SMEM>>>(am);
    gemm_f16_kernel<<<dim3(Dd / BN, Mrows / BM), 256, GEMM_SMEM>>>(
        pattn, pwo, out, Mrows, Dd, Dd, 1, hs);
    ln_kernel<<<Mrows, 256>>>(out, ln2, out + OUTOFF, 0);
}

// round 6
// speedup vs baseline: 13.2328x; 1.1523x over previous
#include <cuda_runtime.h>
#include <cuda_fp16.h>
#include <math.h>
#include <stdint.h>

#define Bb    2
#define Ss    2048
#define Dd    2048
#define Hh    32
#define KVHh  8
#define HDd   64
#define QKVN  3072
#define Mrows (Bb*Ss)
#define OUTOFF ((size_t)Bb*Ss*Dd)
#define ATT_SCALE 0.125f

// ---------------- scratch ----------------------------------------------------
__device__ __half g_x[(size_t)Mrows*Dd];
__device__ __half g_qkv[(size_t)Mrows*QKVN];
__device__ __half g_q[(size_t)Bb*Hh*Ss*HDd];
__device__ __half g_k[(size_t)Bb*KVHh*Ss*HDd];
__device__ __half g_v[(size_t)Bb*KVHh*Ss*HDd];
__device__ __half g_attn[(size_t)Mrows*Dd];
__device__ __half g_wqkvh[(size_t)Dd*QKVN];
__device__ __half g_wouth[(size_t)Dd*Dd];
__device__ float g_cos[(size_t)Bb*Ss*32];
__device__ float g_sin[(size_t)Bb*Ss*32];
__device__ double g_invf[32];

__device__ __forceinline__ uint32_t pkh2(float x, float y) {
    __half2 h = __floats2half2_rn(x, y);
    return *(uint32_t*)&h;
}
__device__ __forceinline__ void mma_f16(float c[4], uint32_t a0, uint32_t a1,
                                        uint32_t a2, uint32_t a3,
                                        uint32_t b0, uint32_t b1)
{
    asm volatile(
        "mma.sync.aligned.m16n8k16.row.col.f32.f16.f16.f32 "
        "{%0,%1,%2,%3}, {%4,%5,%6,%7}, {%8,%9}, {%0,%1,%2,%3};"
        : "+f"(c[0]), "+f"(c[1]), "+f"(c[2]), "+f"(c[3])
        : "r"(a0), "r"(a1), "r"(a2), "r"(a3), "r"(b0), "r"(b1));
}
__device__ __forceinline__ void ldsm4t(uint32_t& r0, uint32_t& r1,
                                       uint32_t& r2, uint32_t& r3, uint32_t saddr)
{
    asm volatile(
        "ldmatrix.sync.aligned.m8n8.x4.trans.shared.b16 {%0,%1,%2,%3}, [%4];"
        : "=r"(r0), "=r"(r1), "=r"(r2), "=r"(r3) : "r"(saddr));
}
__device__ __forceinline__ void cpa16(uint32_t smem_addr, const void* gptr) {
    asm volatile("cp.async.cg.shared.global [%0], [%1], 16;"
                 :: "r"(smem_addr), "l"(gptr));
}
__device__ __forceinline__ void cpa4(uint32_t smem_addr, const void* gptr) {
    asm volatile("cp.async.ca.shared.global [%0], [%1], 4;"
                 :: "r"(smem_addr), "l"(gptr));
}
__device__ __forceinline__ void cpa_commit() {
    asm volatile("cp.async.commit_group;");
}
template<int N>
__device__ __forceinline__ void cpa_wait() {
    asm volatile("cp.async.wait_group %0;" :: "n"(N));
}

// ---------------- weight fp32 -> fp16 -----------------------------------------
__global__ void cvt2_kernel(const float* __restrict__ w1, __half* __restrict__ o1,
                            int n1, const float* __restrict__ w2,
                            __half* __restrict__ o2, int n2)
{
    int i = blockIdx.x * 256 + threadIdx.x;
    const float* src; __half* dst;
    if (i < n1) { src = w1 + (size_t)i * 4; dst = o1 + (size_t)i * 4; }
    else {
        i -= n1;
        if (i >= n2) return;
        src = w2 + (size_t)i * 4; dst = o2 + (size_t)i * 4;
    }
    float4 v = *(const float4*)src;
    uint32_t* d = (uint32_t*)dst;
    d[0] = pkh2(v.x, v.y);
    d[1] = pkh2(v.z, v.w);
}

// ---------------- LayerNorm ---------------------------------------------------
__global__ __launch_bounds__(256) void ln_kernel(
    const float* __restrict__ in, const float* __restrict__ sc,
    void* __restrict__ outp, int half_out)
{
    int row = blockIdx.x;
    const float* x = in + (size_t)row * Dd;
    float s = 0.f, s2 = 0.f;
    for (int i = threadIdx.x; i < Dd; i += 256) { float v = x[i]; s += v; s2 += v*v; }
    #pragma unroll
    for (int o = 16; o; o >>= 1) {
        s  += __shfl_xor_sync(0xffffffffu, s,  o);
        s2 += __shfl_xor_sync(0xffffffffu, s2, o);
    }
    __shared__ float ws[8], ws2[8];
    int w = threadIdx.x >> 5, l = threadIdx.x & 31;
    if (l == 0) { ws[w] = s; ws2[w] = s2; }
    __syncthreads();
    if (threadIdx.x < 32) {
        s  = (l < 8) ? ws[l]  : 0.f;
        s2 = (l < 8) ? ws2[l] : 0.f;
        #pragma unroll
        for (int o = 4; o; o >>= 1) {
            s  += __shfl_xor_sync(0xffffffffu, s,  o);
            s2 += __shfl_xor_sync(0xffffffffu, s2, o);
        }
        if (l == 0) { ws[0] = s; ws2[0] = s2; }
    }
    __syncthreads();
    float mean = ws[0] * (1.f / Dd);
    float var  = ws2[0] * (1.f / Dd) - mean * mean;
    float inv  = rsqrtf(var + 1e-6f);
    if (half_out) {
        __half* o_ = (__half*)outp + (size_t)row * Dd;
        for (int i = threadIdx.x * 2; i < Dd; i += 512) {
            float a = (x[i] - mean) * inv * sc[i];
            float b = (x[i+1] - mean) * inv * sc[i+1];
            *(uint32_t*)(o_ + i) = pkh2(a, b);
        }
    } else {
        float* o_ = (float*)outp + (size_t)row * Dd;
        for (int i = threadIdx.x; i < Dd; i += 256)
            o_[i] = (x[i] - mean) * inv * sc[i];
    }
}

// ---------------- FP16 GEMM 128x128x32, 3-stage cp.async ----------------------
#define BM 128
#define BN 128
#define BK 32
#define AS_U 20
#define AS_U32S (BM * AS_U)
#define BS_U32S (BK * 64)
#define STAGE_U (AS_U32S + BS_U32S)
#define NSTG 3

__global__ __launch_bounds__(256, 2) void gemm_f16_kernel(
    const __half* __restrict__ A, const __half* __restrict__ Bw,
    void* __restrict__ Cp, int M, int N, int K, int mode,
    const float* __restrict__ resid)
{
    extern __shared__ uint32_t smu[];
    int row0 = blockIdx.y * BM, col0 = blockIdx.x * BN;
    int t = threadIdx.x;
    int w = t >> 5, l = t & 31;
    int warpM = w >> 1, warpN = w & 1;
    int lr = l >> 2, lc = l & 3;

    const uint4* Au = (const uint4*)A;
    const uint4* Bu = (const uint4*)Bw;
    int K8 = K >> 3, N8 = N >> 3;

    uint32_t stAddr[NSTG];
    #pragma unroll
    for (int sidx = 0; sidx < NSTG; sidx++)
        stAddr[sidx] = (uint32_t)__cvta_generic_to_shared(smu + sidx * STAGE_U);

    int aRow[2], aC[2], bK[2], bDst[2];
    #pragma unroll
    for (int i = 0; i < 2; i++) {
        int idx = i * 256 + t;
        aRow[i] = idx >> 2;  aC[i] = idx & 3;
        int k = idx >> 4, c = idx & 15;
        bK[i] = k;
        bDst[i] = k * 64 + ((c * 4) ^ ((k & 7) << 2));
    }
    int bC0 = (col0 >> 3);

    float acc[2][8][4];
    #pragma unroll
    for (int mf = 0; mf < 2; mf++)
        #pragma unroll
        for (int nf = 0; nf < 8; nf++)
            #pragma unroll
            for (int r = 0; r < 4; r++) acc[mf][nf][r] = 0.f;

    int nk = K / BK;
    auto issue = [&](int kt, int stg) {
        if (kt < nk) {
            int k0 = kt * BK;
            uint32_t aBase = stAddr[stg];
            uint32_t bBase = stAddr[stg] + AS_U32S * 4;
            #pragma unroll
            for (int i = 0; i < 2; i++) {
                cpa16(aBase + (aRow[i] * AS_U + aC[i] * 4) * 4,
                      Au + (size_t)(row0 + aRow[i]) * K8 + (k0 >> 3) + aC[i]);
                int idx = i * 256 + t;
                cpa16(bBase + bDst[i] * 4,
                      Bu + (size_t)(k0 + bK[i]) * N8 + bC0 + (idx & 15));
            }
        }
        cpa_commit();
    };

    issue(0, 0);
    issue(1, 1);

    for (int kt = 0; kt < nk; kt++) {
        cpa_wait<1>();
        __syncthreads();
        issue(kt + 2, (kt + 2) % NSTG);

        int cur = kt % NSTG;
        const uint32_t* as = smu + cur * STAGE_U;
        uint32_t bsAddr = stAddr[cur] + AS_U32S * 4;
        #pragma unroll
        for (int ks = 0; ks < 2; ks++) {
            uint32_t af[2][4];
            #pragma unroll
            for (int mf = 0; mf < 2; mf++) {
                int r = warpM * 32 + mf * 16 + lr;
                af[mf][0] = as[r * AS_U + ks * 8 + lc];
                af[mf][1] = as[(r + 8) * AS_U + ks * 8 + lc];
                af[mf][2] = as[r * AS_U + ks * 8 + lc + 4];
                af[mf][3] = as[(r + 8) * AS_U + ks * 8 + lc + 4];
            }
            #pragma unroll
            for (int nfp = 0; nfp < 4; nfp++) {
                int krow = ks * 16 + (l & 15);
                int col = warpN * 32 + nfp * 8 + ((l >> 4) << 2);
                col ^= (krow & 7) << 2;
                uint32_t b0, b1, b2, b3;
                ldsm4t(b0, b1, b2, b3, bsAddr + (krow * 64 + col) * 4);
                #pragma unroll
                for (int mf = 0; mf < 2; mf++) {
                    mma_f16(acc[mf][2*nfp],   af[mf][0], af[mf][1], af[mf][2], af[mf][3], b0, b1);
                    mma_f16(acc[mf][2*nfp+1], af[mf][0], af[mf][1], af[mf][2], af[mf][3], b2, b3);
                }
            }
        }
        __syncthreads();
    }

    #pragma unroll
    for (int mf = 0; mf < 2; mf++) {
        #pragma unroll
        for (int half = 0; half < 2; half++) {
            int row = row0 + warpM * 32 + mf * 16 + lr + half * 8;
            #pragma unroll
            for (int nf = 0; nf < 8; nf++) {
                int col = col0 + warpN * 64 + nf * 8 + 2 * lc;
                float vx = acc[mf][nf][half * 2 + 0];
                float vy = acc[mf][nf][half * 2 + 1];
                size_t off = (size_t)row * N + col;
                if (mode == 0) {
                    vx = fminf(fmaxf(vx, -8.f), 8.f);
                    vy = fminf(fmaxf(vy, -8.f), 8.f);
                    *(uint32_t*)((__half*)Cp + off) = pkh2(vx, vy);
                } else {
                    float2 rv = *(const float2*)(resid + off);
                    float2 v; v.x = vx + rv.x; v.y = vy + rv.y;
                    *(float2*)((float*)Cp + off) = v;
                }
            }
        }
    }
}

// ---------------- RoPE --------------------------------------------------------
__global__ void invf_kernel()
{
    int i = threadIdx.x;
    if (i < 32)
        g_invf[i] = exp(-((double)(2 * i) / 64.0) * log(500000.0));
}

__global__ void rope_table_kernel(const int* __restrict__ pid)
{
    int idx = blockIdx.x * 256 + threadIdx.x;
    if (idx >= Bb * Ss * 32) return;
    int i = idx & 31;
    int s = (idx >> 5) & (Ss - 1);
    int b = idx >> 16;
    double pos = (double)pid[b * Ss + s];
    double ang = pos * g_invf[i];
    double k = rint(ang * 0.15915494309189535);
    float r = (float)(ang - k * 6.283185307179586);
    g_cos[idx] = cosf(r);
    g_sin[idx] = sinf(r);
}

__global__ void rope_apply_kernel()
{
    int idx = blockIdx.x * 256 + threadIdx.x;
    int i = idx & 31;
    int tmp = idx >> 5;
    int hh = tmp % 40;
    int bs = tmp / 40;
    int s = bs & (Ss - 1);
    int b = bs >> 11;
    int tidx = (b << 16) + (s << 5) + i;
    float c = g_cos[tidx], sn = g_sin[tidx];
    if (hh < 32) {
        const __half* src = g_qkv + (size_t)(b * Ss + s) * QKVN + hh * HDd;
        float x1 = __half2float(src[i]), x2 = __half2float(src[i + 32]);
        __half* dst = g_q + ((size_t)(b * Hh + hh) * Ss + s) * HDd;
        dst[i]      = __float2half_rn(x1 * c - x2 * sn);
        dst[i + 32] = __float2half_rn(x2 * c + x1 * sn);
    } else {
        int kvh = hh - 32;
        const __half* srcb = g_qkv + (size_t)(b * Ss + s) * QKVN + Dd;
        const __half* srck = srcb + kvh * HDd;
        float x1 = __half2float(srck[i]), x2 = __half2float(srck[i + 32]);
        size_t hoff = ((size_t)(b * KVHh + kvh) * Ss + s) * HDd;
        g_k[hoff + i]      = __float2half_rn(x1 * c - x2 * sn);
        g_k[hoff + i + 32] = __float2half_rn(x2 * c + x1 * sn);
        const __half* srcv = srcb + KVHh * HDd + kvh * HDd;
        g_v[hoff + i]      = srcv[i];
        g_v[hoff + i + 32] = srcv[i + 32];
    }
}

// ---------------- FP16 flash attention, 3-stage cp.async ----------------------
#define QP_U 36
#define KS_U 36
#define VS_U 32
#define NAS  3
#define SM_PS 0
#define SM_KS (128 * QP_U)                     // 4608
#define SM_VS (SM_KS + NAS * 64 * KS_U)        // 4608 + 6912
#define SM_MASK (SM_VS + NAS * 64 * VS_U)      // + 6144
#define ATT_U32 (SM_MASK + NAS * 64)           // + 192  -> 17856 u32 = 71424 B
__global__ __launch_bounds__(256, 2) void attn_kernel(const int* __restrict__ amask)
{
    extern __shared__ uint32_t smu[];
    uint32_t* Ps = smu + SM_PS;
    int* maskS = (int*)(smu + SM_MASK);

    int qt = blockIdx.x, h = blockIdx.y, b = blockIdx.z;
    int kvh = h >> 2;
    int q0 = qt * 128;
    int t = threadIdx.x;
    int w = t >> 5, l = t & 31;
    int lr = l >> 2, lc = l & 3;

    const uint4* Qg = (const uint4*)(g_q + ((size_t)(b * Hh + h) * Ss + q0) * HDd);
    const uint4* Kg = (const uint4*)(g_k + (size_t)(b * KVHh + kvh) * Ss * HDd);
    const uint4* Vg = (const uint4*)(g_v + (size_t)(b * KVHh + kvh) * Ss * HDd);
    const int*   Mg = amask + b * Ss;

    uint32_t ksAddr0 = (uint32_t)__cvta_generic_to_shared(smu + SM_KS);
    uint32_t vsAddr0 = (uint32_t)__cvta_generic_to_shared(smu + SM_VS);
    uint32_t mkAddr0 = (uint32_t)__cvta_generic_to_shared(maskS);

    int nkt = 2 * qt + 2;
    auto issueKV = [&](int kt, int stg) {
        if (kt < nkt) {
            int k0 = kt * 64;
            uint32_t kBase = ksAddr0 + stg * 64 * KS_U * 4;
            uint32_t vBase = vsAddr0 + stg * 64 * VS_U * 4;
            #pragma unroll
            for (int i = 0; i < 2; i++) {
                int idx = i * 256 + t;
                int row = idx >> 3, c = idx & 7;
                cpa16(kBase + (row * KS_U + c * 4) * 4, Kg + (k0 + row) * 8 + c);
                cpa16(vBase + (row * VS_U + ((c * 4) ^ ((row & 7) << 2))) * 4,
                      Vg + (k0 + row) * 8 + c);
            }
            if (t < 64) cpa4(mkAddr0 + (stg * 64 + t) * 4, Mg + k0 + t);
        }
        cpa_commit();
    };

    // kick off K/V tiles 0,1 before Q staging (overlap)
    issueKV(0, 0);
    issueKV(1, 1);

    // ---- stage Q + extract frags ----
    #pragma unroll
    for (int i = 0; i < 4; i++) {
        int idx = i * 256 + t;
        int row = idx >> 3, c = idx & 7;
        *(uint4*)&Ps[row * QP_U + c * 4] = Qg[row * 8 + c];
    }
    __syncthreads();
    uint32_t qa[4][4];
    {
        int r0 = w * 16 + lr;
        #pragma unroll
        for (int ks = 0; ks < 4; ks++) {
            qa[ks][0] = Ps[r0 * QP_U + ks * 8 + lc];
            qa[ks][1] = Ps[(r0 + 8) * QP_U + ks * 8 + lc];
            qa[ks][2] = Ps[r0 * QP_U + ks * 8 + lc + 4];
            qa[ks][3] = Ps[(r0 + 8) * QP_U + ks * 8 + lc + 4];
        }
    }
    __syncthreads();

    float m0 = -1e30f, m1 = -1e30f, l0 = 0.f, l1 = 0.f;
    float o[8][4];
    #pragma unroll
    for (int nf = 0; nf < 8; nf++)
        #pragma unroll
        for (int r = 0; r < 4; r++) o[nf][r] = 0.f;

    for (int kt = 0; kt < nkt; kt++) {
        cpa_wait<1>();
        __syncthreads();
        issueKV(kt + 2, (kt + 2) % NAS);

        int cur = kt % NAS;
        int k0 = kt * 64;
        int qlow = q0 + w * 16;
        bool active = (k0 <= qlow + 15);
        if (active) {
            float s[8][4];
            #pragma unroll
            for (int nf = 0; nf < 8; nf++)
                #pragma unroll
                for (int r = 0; r < 4; r++) s[nf][r] = 0.f;
            const uint32_t* kb = smu + SM_KS + cur * 64 * KS_U;
            #pragma unroll
            for (int ks = 0; ks < 4; ks++) {
                #pragma unroll
                for (int nf = 0; nf < 8; nf++) {
                    int n = nf * 8 + lr;
                    uint32_t b0 = kb[n * KS_U + ks * 8 + lc];
                    uint32_t b1 = kb[n * KS_U + ks * 8 + lc + 4];
                    mma_f16(s[nf], qa[ks][0], qa[ks][1], qa[ks][2], qa[ks][3], b0, b1);
                }
            }
            int qr0 = qlow + lr, qr1 = qr0 + 8;
            bool fullvis = (k0 + 63 <= qlow);
            #pragma unroll
            for (int nf = 0; nf < 8; nf++) {
                int kg0 = k0 + nf * 8 + 2 * lc;
                int ms0 = maskS[(cur << 6) + nf * 8 + 2 * lc];
                int ms1 = maskS[(cur << 6) + nf * 8 + 2 * lc + 1];
                s[nf][0] = (ms0 && (fullvis || kg0     <= qr0)) ? s[nf][0] * ATT_SCALE : -1e30f;
                s[nf][1] = (ms1 && (fullvis || kg0 + 1 <= qr0)) ? s[nf][1] * ATT_SCALE : -1e30f;
                s[nf][2] = (ms0 && (fullvis || kg0     <= qr1)) ? s[nf][2] * ATT_SCALE : -1e30f;
                s[nf][3] = (ms1 && (fullvis || kg0 + 1 <= qr1)) ? s[nf][3] * ATT_SCALE : -1e30f;
            }
            float mt0 = -1e30f, mt1 = -1e30f;
            #pragma unroll
            for (int nf = 0; nf < 8; nf++) {
                mt0 = fmaxf(mt0, fmaxf(s[nf][0], s[nf][1]));
                mt1 = fmaxf(mt1, fmaxf(s[nf][2], s[nf][3]));
            }
            mt0 = fmaxf(mt0, __shfl_xor_sync(0xffffffffu, mt0, 1));
            mt0 = fmaxf(mt0, __shfl_xor_sync(0xffffffffu, mt0, 2));
            mt1 = fmaxf(mt1, __shfl_xor_sync(0xffffffffu, mt1, 1));
            mt1 = fmaxf(mt1, __shfl_xor_sync(0xffffffffu, mt1, 2));
            float mn0 = fmaxf(m0, mt0), mn1 = fmaxf(m1, mt1);
            float rs0 = 0.f, rs1 = 0.f;
            #pragma unroll
            for (int nf = 0; nf < 8; nf++) {
                s[nf][0] = expf(s[nf][0] - mn0);
                s[nf][1] = expf(s[nf][1] - mn0);
                s[nf][2] = expf(s[nf][2] - mn1);
                s[nf][3] = expf(s[nf][3] - mn1);
                rs0 += s[nf][0] + s[nf][1];
                rs1 += s[nf][2] + s[nf][3];
            }
            rs0 += __shfl_xor_sync(0xffffffffu, rs0, 1);
            rs0 += __shfl_xor_sync(0xffffffffu, rs0, 2);
            rs1 += __shfl_xor_sync(0xffffffffu, rs1, 1);
            rs1 += __shfl_xor_sync(0xffffffffu, rs1, 2);
            float a0 = expf(m0 - mn0), a1 = expf(m1 - mn1);
            l0 = l0 * a0 + rs0;  l1 = l1 * a1 + rs1;
            m0 = mn0;  m1 = mn1;
            #pragma unroll
            for (int nf = 0; nf < 8; nf++) {
                o[nf][0] *= a0; o[nf][1] *= a0;
                o[nf][2] *= a1; o[nf][3] *= a1;
            }
            {
                int r0 = w * 16 + lr;
                #pragma unroll
                for (int nf = 0; nf < 8; nf++) {
                    Ps[r0 * QP_U + nf * 4 + lc]       = pkh2(s[nf][0], s[nf][1]);
                    Ps[(r0 + 8) * QP_U + nf * 4 + lc] = pkh2(s[nf][2], s[nf][3]);
                }
            }
            __syncwarp();
            {
                uint32_t vsAddr = vsAddr0 + cur * 64 * VS_U * 4;
                int r0 = w * 16 + lr;
                #pragma unroll
                for (int ks = 0; ks < 4; ks++) {
                    uint32_t pa0 = Ps[r0 * QP_U + ks * 8 + lc];
                    uint32_t pa1 = Ps[(r0 + 8) * QP_U + ks * 8 + lc];
                    uint32_t pa2 = Ps[r0 * QP_U + ks * 8 + lc + 4];
                    uint32_t pa3 = Ps[(r0 + 8) * QP_U + ks * 8 + lc + 4];
                    #pragma unroll
                    for (int nfp = 0; nfp < 4; nfp++) {
                        int key = ks * 16 + (l & 15);
                        int col = nfp * 8 + ((l >> 4) << 2);
                        col ^= (key & 7) << 2;
                        uint32_t b0, b1, b2, b3;
                        ldsm4t(b0, b1, b2, b3, vsAddr + (key * VS_U + col) * 4);
                        mma_f16(o[2*nfp],   pa0, pa1, pa2, pa3, b0, b1);
                        mma_f16(o[2*nfp+1], pa0, pa1, pa2, pa3, b2, b3);
                    }
                }
            }
        }
    }

    float il0 = (l0 > 0.f) ? (1.f / l0) : 0.f;
    float il1 = (l1 > 0.f) ? (1.f / l1) : 0.f;
    int qr0 = q0 + w * 16 + lr;
    __half* d0 = g_attn + (size_t)(b * Ss + qr0) * Dd + h * HDd;
    __half* d1 = g_attn + (size_t)(b * Ss + qr0 + 8) * Dd + h * HDd;
    #pragma unroll
    for (int nf = 0; nf < 8; nf++) {
        int c = nf * 8 + 2 * lc;
        *(uint32_t*)(d0 + c) = pkh2(o[nf][0] * il0, o[nf][1] * il0);
        *(uint32_t*)(d1 + c) = pkh2(o[nf][2] * il1, o[nf][3] * il1);
    }
}

// ---------------- launch ------------------------------------------------------
extern "C" void kernel_launch(void* const* d_in, const int* in_sizes, int n_in,
                              void* d_out, int out_size)
{
    const float* hs   = (const float*)d_in[0];
    const int*   am   = (const int*)  d_in[1];
    const int*   pid  = (const int*)  d_in[2];
    const float* ln1  = (const float*)d_in[4];
    const float* wqkv = (const float*)d_in[5];
    const float* wout = (const float*)d_in[6];
    const float* ln2  = (const float*)d_in[7];
    float* out = (float*)d_out;

    __half *px, *pqkv, *pattn, *pwq, *pwo;
    cudaGetSymbolAddress((void**)&px,    g_x);
    cudaGetSymbolAddress((void**)&pqkv,  g_qkv);
    cudaGetSymbolAddress((void**)&pattn, g_attn);
    cudaGetSymbolAddress((void**)&pwq,   g_wqkvh);
    cudaGetSymbolAddress((void**)&pwo,   g_wouth);

    const int ATTN_SMEM = ATT_U32 * 4;               // 71424 B
    cudaFuncSetAttribute(attn_kernel,
                         cudaFuncAttributeMaxDynamicSharedMemorySize, ATTN_SMEM);
    const int GEMM_SMEM = NSTG * STAGE_U * 4;        // 55296 B
    cudaFuncSetAttribute(gemm_f16_kernel,
                         cudaFuncAttributeMaxDynamicSharedMemorySize, GEMM_SMEM);

    int n1 = Dd * QKVN / 4, n2 = Dd * Dd / 4;
    cvt2_kernel<<<(n1 + n2 + 255) / 256, 256>>>(wqkv, pwq, n1, wout, pwo, n2);
    invf_kernel<<<1, 32>>>();
    ln_kernel<<<Mrows, 256>>>(hs, ln1, px, 1);
    rope_table_kernel<<<(Bb * Ss * 32) / 256, 256>>>(pid);
    gemm_f16_kernel<<<dim3(QKVN / BN, Mrows / BM), 256, GEMM_SMEM>>>(
        px, pwq, pqkv, Mrows, QKVN, Dd, 0, nullptr);
    rope_apply_kernel<<<(Bb * Ss * 40 * 32) / 256, 256>>>();
    attn_kernel<<<dim3(Ss / 128, Hh, Bb), 256, ATTN_SMEM>>>(am);
    gemm_f16_kernel<<<dim3(Dd / BN, Mrows / BM), 256, GEMM_SMEM>>>(
        pattn, pwo, out, Mrows, Dd, Dd, 1, hs);
    ln_kernel<<<Mrows, 256>>>(out, ln2, out + OUTOFF, 0);
}

// round 7
// speedup vs baseline: 13.5047x; 1.0205x over previous
#include <cuda_runtime.h>
#include <cuda_fp16.h>
#include <math.h>
#include <stdint.h>

#define Bb    2
#define Ss    2048
#define Dd    2048
#define Hh    32
#define KVHh  8
#define HDd   64
#define QKVN  3072
#define Mrows (Bb*Ss)
#define OUTOFF ((size_t)Bb*Ss*Dd)
#define ATT_SCALE 0.125f

// ---------------- scratch ----------------------------------------------------
__device__ __half g_x[(size_t)Mrows*Dd];
__device__ __half g_qkv[(size_t)Mrows*QKVN];
__device__ __half g_q[(size_t)Bb*Hh*Ss*HDd];
__device__ __half g_k[(size_t)Bb*KVHh*Ss*HDd];
__device__ __half g_v[(size_t)Bb*KVHh*Ss*HDd];
__device__ __half g_attn[(size_t)Mrows*Dd];
__device__ __half g_wqkvh[(size_t)Dd*QKVN];
__device__ __half g_wouth[(size_t)Dd*Dd];
__device__ float g_cos[(size_t)Bb*Ss*32];
__device__ float g_sin[(size_t)Bb*Ss*32];
__device__ double g_invf[32];

__device__ __forceinline__ uint32_t pkh2(float x, float y) {
    __half2 h = __floats2half2_rn(x, y);
    return *(uint32_t*)&h;
}
__device__ __forceinline__ void mma_f16(float c[4], uint32_t a0, uint32_t a1,
                                        uint32_t a2, uint32_t a3,
                                        uint32_t b0, uint32_t b1)
{
    asm volatile(
        "mma.sync.aligned.m16n8k16.row.col.f32.f16.f16.f32 "
        "{%0,%1,%2,%3}, {%4,%5,%6,%7}, {%8,%9}, {%0,%1,%2,%3};"
        : "+f"(c[0]), "+f"(c[1]), "+f"(c[2]), "+f"(c[3])
        : "r"(a0), "r"(a1), "r"(a2), "r"(a3), "r"(b0), "r"(b1));
}
__device__ __forceinline__ void ldsm4t(uint32_t& r0, uint32_t& r1,
                                       uint32_t& r2, uint32_t& r3, uint32_t saddr)
{
    asm volatile(
        "ldmatrix.sync.aligned.m8n8.x4.trans.shared.b16 {%0,%1,%2,%3}, [%4];"
        : "=r"(r0), "=r"(r1), "=r"(r2), "=r"(r3) : "r"(saddr));
}
__device__ __forceinline__ void cpa16(uint32_t smem_addr, const void* gptr) {
    asm volatile("cp.async.cg.shared.global [%0], [%1], 16;"
                 :: "r"(smem_addr), "l"(gptr));
}
__device__ __forceinline__ void cpa4(uint32_t smem_addr, const void* gptr) {
    asm volatile("cp.async.ca.shared.global [%0], [%1], 4;"
                 :: "r"(smem_addr), "l"(gptr));
}
__device__ __forceinline__ void cpa_commit() {
    asm volatile("cp.async.commit_group;");
}
template<int N>
__device__ __forceinline__ void cpa_wait() {
    asm volatile("cp.async.wait_group %0;" :: "n"(N));
}

// ---------------- weight fp32 -> fp16 -----------------------------------------
__global__ void cvt2_kernel(const float* __restrict__ w1, __half* __restrict__ o1,
                            int n1, const float* __restrict__ w2,
                            __half* __restrict__ o2, int n2)
{
    int i = blockIdx.x * 256 + threadIdx.x;
    const float* src; __half* dst;
    if (i < n1) { src = w1 + (size_t)i * 4; dst = o1 + (size_t)i * 4; }
    else {
        i -= n1;
        if (i >= n2) return;
        src = w2 + (size_t)i * 4; dst = o2 + (size_t)i * 4;
    }
    float4 v = *(const float4*)src;
    uint32_t* d = (uint32_t*)dst;
    d[0] = pkh2(v.x, v.y);
    d[1] = pkh2(v.z, v.w);
}

// ---------------- LayerNorm ---------------------------------------------------
__global__ __launch_bounds__(256) void ln_kernel(
    const float* __restrict__ in, const float* __restrict__ sc,
    void* __restrict__ outp, int half_out)
{
    int row = blockIdx.x;
    const float* x = in + (size_t)row * Dd;
    float s = 0.f, s2 = 0.f;
    for (int i = threadIdx.x; i < Dd; i += 256) { float v = x[i]; s += v; s2 += v*v; }
    #pragma unroll
    for (int o = 16; o; o >>= 1) {
        s  += __shfl_xor_sync(0xffffffffu, s,  o);
        s2 += __shfl_xor_sync(0xffffffffu, s2, o);
    }
    __shared__ float ws[8], ws2[8];
    int w = threadIdx.x >> 5, l = threadIdx.x & 31;
    if (l == 0) { ws[w] = s; ws2[w] = s2; }
    __syncthreads();
    if (threadIdx.x < 32) {
        s  = (l < 8) ? ws[l]  : 0.f;
        s2 = (l < 8) ? ws2[l] : 0.f;
        #pragma unroll
        for (int o = 4; o; o >>= 1) {
            s  += __shfl_xor_sync(0xffffffffu, s,  o);
            s2 += __shfl_xor_sync(0xffffffffu, s2, o);
        }
        if (l == 0) { ws[0] = s; ws2[0] = s2; }
    }
    __syncthreads();
    float mean = ws[0] * (1.f / Dd);
    float var  = ws2[0] * (1.f / Dd) - mean * mean;
    float inv  = rsqrtf(var + 1e-6f);
    if (half_out) {
        __half* o_ = (__half*)outp + (size_t)row * Dd;
        for (int i = threadIdx.x * 2; i < Dd; i += 512) {
            float a = (x[i] - mean) * inv * sc[i];
            float b = (x[i+1] - mean) * inv * sc[i+1];
            *(uint32_t*)(o_ + i) = pkh2(a, b);
        }
    } else {
        float* o_ = (float*)outp + (size_t)row * Dd;
        for (int i = threadIdx.x; i < Dd; i += 256)
            o_[i] = (x[i] - mean) * inv * sc[i];
    }
}

// ---------------- FP16 GEMM 128x128x32, 3-stage cp.async ----------------------
#define BM 128
#define BN 128
#define BK 32
#define AS_U 20
#define AS_U32S (BM * AS_U)
#define BS_U32S (BK * 64)
#define STAGE_U (AS_U32S + BS_U32S)
#define NSTG 3

__global__ __launch_bounds__(256, 2) void gemm_f16_kernel(
    const __half* __restrict__ A, const __half* __restrict__ Bw,
    void* __restrict__ Cp, int M, int N, int K, int mode,
    const float* __restrict__ resid)
{
    extern __shared__ uint32_t smu[];
    int row0 = blockIdx.y * BM, col0 = blockIdx.x * BN;
    int t = threadIdx.x;
    int w = t >> 5, l = t & 31;
    int warpM = w >> 1, warpN = w & 1;
    int lr = l >> 2, lc = l & 3;

    const uint4* Au = (const uint4*)A;
    const uint4* Bu = (const uint4*)Bw;
    int K8 = K >> 3, N8 = N >> 3;

    uint32_t stAddr[NSTG];
    #pragma unroll
    for (int sidx = 0; sidx < NSTG; sidx++)
        stAddr[sidx] = (uint32_t)__cvta_generic_to_shared(smu + sidx * STAGE_U);

    int aRow[2], aC[2], bK[2], bDst[2];
    #pragma unroll
    for (int i = 0; i < 2; i++) {
        int idx = i * 256 + t;
        aRow[i] = idx >> 2;  aC[i] = idx & 3;
        int k = idx >> 4, c = idx & 15;
        bK[i] = k;
        bDst[i] = k * 64 + ((c * 4) ^ ((k & 7) << 2));
    }
    int bC0 = (col0 >> 3);

    float acc[2][8][4];
    #pragma unroll
    for (int mf = 0; mf < 2; mf++)
        #pragma unroll
        for (int nf = 0; nf < 8; nf++)
            #pragma unroll
            for (int r = 0; r < 4; r++) acc[mf][nf][r] = 0.f;

    int nk = K / BK;
    auto issue = [&](int kt, int stg) {
        if (kt < nk) {
            int k0 = kt * BK;
            uint32_t aBase = stAddr[stg];
            uint32_t bBase = stAddr[stg] + AS_U32S * 4;
            #pragma unroll
            for (int i = 0; i < 2; i++) {
                cpa16(aBase + (aRow[i] * AS_U + aC[i] * 4) * 4,
                      Au + (size_t)(row0 + aRow[i]) * K8 + (k0 >> 3) + aC[i]);
                int idx = i * 256 + t;
                cpa16(bBase + bDst[i] * 4,
                      Bu + (size_t)(k0 + bK[i]) * N8 + bC0 + (idx & 15));
            }
        }
        cpa_commit();
    };

    issue(0, 0);
    issue(1, 1);

    for (int kt = 0; kt < nk; kt++) {
        cpa_wait<1>();
        __syncthreads();            // single barrier per tile
        issue(kt + 2, (kt + 2) % NSTG);

        int cur = kt % NSTG;
        const uint32_t* as = smu + cur * STAGE_U;
        uint32_t bsAddr = stAddr[cur] + AS_U32S * 4;
        #pragma unroll
        for (int ks = 0; ks < 2; ks++) {
            uint32_t af[2][4];
            #pragma unroll
            for (int mf = 0; mf < 2; mf++) {
                int r = warpM * 32 + mf * 16 + lr;
                af[mf][0] = as[r * AS_U + ks * 8 + lc];
                af[mf][1] = as[(r + 8) * AS_U + ks * 8 + lc];
                af[mf][2] = as[r * AS_U + ks * 8 + lc + 4];
                af[mf][3] = as[(r + 8) * AS_U + ks * 8 + lc + 4];
            }
            #pragma unroll
            for (int nfp = 0; nfp < 4; nfp++) {
                int krow = ks * 16 + (l & 15);
                int col = warpN * 32 + nfp * 8 + ((l >> 4) << 2);
                col ^= (krow & 7) << 2;
                uint32_t b0, b1, b2, b3;
                ldsm4t(b0, b1, b2, b3, bsAddr + (krow * 64 + col) * 4);
                #pragma unroll
                for (int mf = 0; mf < 2; mf++) {
                    mma_f16(acc[mf][2*nfp],   af[mf][0], af[mf][1], af[mf][2], af[mf][3], b0, b1);
                    mma_f16(acc[mf][2*nfp+1], af[mf][0], af[mf][1], af[mf][2], af[mf][3], b2, b3);
                }
            }
        }
    }

    #pragma unroll
    for (int mf = 0; mf < 2; mf++) {
        #pragma unroll
        for (int half = 0; half < 2; half++) {
            int row = row0 + warpM * 32 + mf * 16 + lr + half * 8;
            #pragma unroll
            for (int nf = 0; nf < 8; nf++) {
                int col = col0 + warpN * 64 + nf * 8 + 2 * lc;
                float vx = acc[mf][nf][half * 2 + 0];
                float vy = acc[mf][nf][half * 2 + 1];
                size_t off = (size_t)row * N + col;
                if (mode == 0) {
                    vx = fminf(fmaxf(vx, -8.f), 8.f);
                    vy = fminf(fmaxf(vy, -8.f), 8.f);
                    *(uint32_t*)((__half*)Cp + off) = pkh2(vx, vy);
                } else {
                    float2 rv = *(const float2*)(resid + off);
                    float2 v; v.x = vx + rv.x; v.y = vy + rv.y;
                    *(float2*)((float*)Cp + off) = v;
                }
            }
        }
    }
}

// ---------------- RoPE --------------------------------------------------------
__global__ void invf_kernel()
{
    int i = threadIdx.x;
    if (i < 32)
        g_invf[i] = exp(-((double)(2 * i) / 64.0) * log(500000.0));
}

__global__ void rope_table_kernel(const int* __restrict__ pid)
{
    int idx = blockIdx.x * 256 + threadIdx.x;
    if (idx >= Bb * Ss * 32) return;
    int i = idx & 31;
    int s = (idx >> 5) & (Ss - 1);
    int b = idx >> 16;
    double pos = (double)pid[b * Ss + s];
    double ang = pos * g_invf[i];
    double k = rint(ang * 0.15915494309189535);
    float r = (float)(ang - k * 6.283185307179586);
    g_cos[idx] = cosf(r);
    g_sin[idx] = sinf(r);
}

__global__ void rope_apply_kernel()
{
    int idx = blockIdx.x * 256 + threadIdx.x;
    int i = idx & 31;
    int tmp = idx >> 5;
    int hh = tmp % 40;
    int bs = tmp / 40;
    int s = bs & (Ss - 1);
    int b = bs >> 11;
    int tidx = (b << 16) + (s << 5) + i;
    float c = g_cos[tidx], sn = g_sin[tidx];
    if (hh < 32) {
        const __half* src = g_qkv + (size_t)(b * Ss + s) * QKVN + hh * HDd;
        float x1 = __half2float(src[i]), x2 = __half2float(src[i + 32]);
        __half* dst = g_q + ((size_t)(b * Hh + hh) * Ss + s) * HDd;
        dst[i]      = __float2half_rn(x1 * c - x2 * sn);
        dst[i + 32] = __float2half_rn(x2 * c + x1 * sn);
    } else {
        int kvh = hh - 32;
        const __half* srcb = g_qkv + (size_t)(b * Ss + s) * QKVN + Dd;
        const __half* srck = srcb + kvh * HDd;
        float x1 = __half2float(srck[i]), x2 = __half2float(srck[i + 32]);
        size_t hoff = ((size_t)(b * KVHh + kvh) * Ss + s) * HDd;
        g_k[hoff + i]      = __float2half_rn(x1 * c - x2 * sn);
        g_k[hoff + i + 32] = __float2half_rn(x2 * c + x1 * sn);
        const __half* srcv = srcb + KVHh * HDd + kvh * HDd;
        g_v[hoff + i]      = srcv[i];
        g_v[hoff + i + 32] = srcv[i + 32];
    }
}

// ---------------- FP16 flash attention, 3-stage cp.async ----------------------
#define QP_U 36
#define KS_U 36
#define VS_U 32
#define NAS  3
#define SM_PS 0
#define SM_KS (128 * QP_U)
#define SM_VS (SM_KS + NAS * 64 * KS_U)
#define SM_MASK (SM_VS + NAS * 64 * VS_U)
#define ATT_U32 (SM_MASK + NAS * 64)
__global__ __launch_bounds__(256, 2) void attn_kernel(const int* __restrict__ amask)
{
    extern __shared__ uint32_t smu[];
    uint32_t* Ps = smu + SM_PS;
    int* maskS = (int*)(smu + SM_MASK);

    int qt = blockIdx.x, h = blockIdx.y, b = blockIdx.z;
    int kvh = h >> 2;
    int q0 = qt * 128;
    int t = threadIdx.x;
    int w = t >> 5, l = t & 31;
    int lr = l >> 2, lc = l & 3;

    const uint4* Qg = (const uint4*)(g_q + ((size_t)(b * Hh + h) * Ss + q0) * HDd);
    const uint4* Kg = (const uint4*)(g_k + (size_t)(b * KVHh + kvh) * Ss * HDd);
    const uint4* Vg = (const uint4*)(g_v + (size_t)(b * KVHh + kvh) * Ss * HDd);
    const int*   Mg = amask + b * Ss;

    uint32_t ksAddr0 = (uint32_t)__cvta_generic_to_shared(smu + SM_KS);
    uint32_t vsAddr0 = (uint32_t)__cvta_generic_to_shared(smu + SM_VS);
    uint32_t mkAddr0 = (uint32_t)__cvta_generic_to_shared(maskS);

    int nkt = 2 * qt + 2;
    auto issueKV = [&](int kt, int stg) {
        if (kt < nkt) {
            int k0 = kt * 64;
            uint32_t kBase = ksAddr0 + stg * 64 * KS_U * 4;
            uint32_t vBase = vsAddr0 + stg * 64 * VS_U * 4;
            #pragma unroll
            for (int i = 0; i < 2; i++) {
                int idx = i * 256 + t;
                int row = idx >> 3, c = idx & 7;
                cpa16(kBase + (row * KS_U + c * 4) * 4, Kg + (k0 + row) * 8 + c);
                cpa16(vBase + (row * VS_U + ((c * 4) ^ ((row & 7) << 2))) * 4,
                      Vg + (k0 + row) * 8 + c);
            }
            if (t < 64) cpa4(mkAddr0 + (stg * 64 + t) * 4, Mg + k0 + t);
        }
        cpa_commit();
    };

    issueKV(0, 0);
    issueKV(1, 1);

    // ---- stage Q + extract frags ----
    #pragma unroll
    for (int i = 0; i < 4; i++) {
        int idx = i * 256 + t;
        int row = idx >> 3, c = idx & 7;
        *(uint4*)&Ps[row * QP_U + c * 4] = Qg[row * 8 + c];
    }
    __syncthreads();
    uint32_t qa[4][4];
    {
        int r0 = w * 16 + lr;
        #pragma unroll
        for (int ks = 0; ks < 4; ks++) {
            qa[ks][0] = Ps[r0 * QP_U + ks * 8 + lc];
            qa[ks][1] = Ps[(r0 + 8) * QP_U + ks * 8 + lc];
            qa[ks][2] = Ps[r0 * QP_U + ks * 8 + lc + 4];
            qa[ks][3] = Ps[(r0 + 8) * QP_U + ks * 8 + lc + 4];
        }
    }

    float m0 = -1e30f, m1 = -1e30f, l0 = 0.f, l1 = 0.f;
    float o[8][4];
    #pragma unroll
    for (int nf = 0; nf < 8; nf++)
        #pragma unroll
        for (int r = 0; r < 4; r++) o[nf][r] = 0.f;

    for (int kt = 0; kt < nkt; kt++) {
        cpa_wait<1>();
        __syncthreads();
        issueKV(kt + 2, (kt + 2) % NAS);

        int cur = kt % NAS;
        int k0 = kt * 64;
        int qlow = q0 + w * 16;
        bool active = (k0 <= qlow + 15);
        if (active) {
            // ---- S = Q K^T ----
            float s[8][4];
            #pragma unroll
            for (int nf = 0; nf < 8; nf++)
                #pragma unroll
                for (int r = 0; r < 4; r++) s[nf][r] = 0.f;
            const uint32_t* kb = smu + SM_KS + cur * 64 * KS_U;
            #pragma unroll
            for (int ks = 0; ks < 4; ks++) {
                #pragma unroll
                for (int nf = 0; nf < 8; nf++) {
                    int n = nf * 8 + lr;
                    uint32_t b0 = kb[n * KS_U + ks * 8 + lc];
                    uint32_t b1 = kb[n * KS_U + ks * 8 + lc + 4];
                    mma_f16(s[nf], qa[ks][0], qa[ks][1], qa[ks][2], qa[ks][3], b0, b1);
                }
            }
            // ---- mask + scale ----
            int qr0 = qlow + lr, qr1 = qr0 + 8;
            bool fullvis = (k0 + 63 <= qlow);
            #pragma unroll
            for (int nf = 0; nf < 8; nf++) {
                int kg0 = k0 + nf * 8 + 2 * lc;
                int ms0 = maskS[(cur << 6) + nf * 8 + 2 * lc];
                int ms1 = maskS[(cur << 6) + nf * 8 + 2 * lc + 1];
                s[nf][0] = (ms0 && (fullvis || kg0     <= qr0)) ? s[nf][0] * ATT_SCALE : -1e30f;
                s[nf][1] = (ms1 && (fullvis || kg0 + 1 <= qr0)) ? s[nf][1] * ATT_SCALE : -1e30f;
                s[nf][2] = (ms0 && (fullvis || kg0     <= qr1)) ? s[nf][2] * ATT_SCALE : -1e30f;
                s[nf][3] = (ms1 && (fullvis || kg0 + 1 <= qr1)) ? s[nf][3] * ATT_SCALE : -1e30f;
            }
            // ---- online softmax ----
            float mt0 = -1e30f, mt1 = -1e30f;
            #pragma unroll
            for (int nf = 0; nf < 8; nf++) {
                mt0 = fmaxf(mt0, fmaxf(s[nf][0], s[nf][1]));
                mt1 = fmaxf(mt1, fmaxf(s[nf][2], s[nf][3]));
            }
            mt0 = fmaxf(mt0, __shfl_xor_sync(0xffffffffu, mt0, 1));
            mt0 = fmaxf(mt0, __shfl_xor_sync(0xffffffffu, mt0, 2));
            mt1 = fmaxf(mt1, __shfl_xor_sync(0xffffffffu, mt1, 1));
            mt1 = fmaxf(mt1, __shfl_xor_sync(0xffffffffu, mt1, 2));
            float mn0 = fmaxf(m0, mt0), mn1 = fmaxf(m1, mt1);
            float rs0 = 0.f, rs1 = 0.f;
            #pragma unroll
            for (int nf = 0; nf < 8; nf++) {
                s[nf][0] = expf(s[nf][0] - mn0);
                s[nf][1] = expf(s[nf][1] - mn0);
                s[nf][2] = expf(s[nf][2] - mn1);
                s[nf][3] = expf(s[nf][3] - mn1);
                rs0 += s[nf][0] + s[nf][1];
                rs1 += s[nf][2] + s[nf][3];
            }
            rs0 += __shfl_xor_sync(0xffffffffu, rs0, 1);
            rs0 += __shfl_xor_sync(0xffffffffu, rs0, 2);
            rs1 += __shfl_xor_sync(0xffffffffu, rs1, 1);
            rs1 += __shfl_xor_sync(0xffffffffu, rs1, 2);
            float a0 = expf(m0 - mn0), a1 = expf(m1 - mn1);
            l0 = l0 * a0 + rs0;  l1 = l1 * a1 + rs1;
            m0 = mn0;  m1 = mn1;
            #pragma unroll
            for (int nf = 0; nf < 8; nf++) {
                o[nf][0] *= a0; o[nf][1] *= a0;
                o[nf][2] *= a1; o[nf][3] *= a1;
            }
            // ---- O += P V : P packed directly from S C-frags (no smem!) ----
            {
                uint32_t vsAddr = vsAddr0 + cur * 64 * VS_U * 4;
                #pragma unroll
                for (int ks = 0; ks < 4; ks++) {
                    uint32_t pa0 = pkh2(s[2*ks][0],   s[2*ks][1]);
                    uint32_t pa1 = pkh2(s[2*ks][2],   s[2*ks][3]);
                    uint32_t pa2 = pkh2(s[2*ks+1][0], s[2*ks+1][1]);
                    uint32_t pa3 = pkh2(s[2*ks+1][2], s[2*ks+1][3]);
                    #pragma unroll
                    for (int nfp = 0; nfp < 4; nfp++) {
                        int key = ks * 16 + (l & 15);
                        int col = nfp * 8 + ((l >> 4) << 2);
                        col ^= (key & 7) << 2;
                        uint32_t b0, b1, b2, b3;
                        ldsm4t(b0, b1, b2, b3, vsAddr + (key * VS_U + col) * 4);
                        mma_f16(o[2*nfp],   pa0, pa1, pa2, pa3, b0, b1);
                        mma_f16(o[2*nfp+1], pa0, pa1, pa2, pa3, b2, b3);
                    }
                }
            }
        }
    }

    float il0 = (l0 > 0.f) ? (1.f / l0) : 0.f;
    float il1 = (l1 > 0.f) ? (1.f / l1) : 0.f;
    int qr0 = q0 + w * 16 + lr;
    __half* d0 = g_attn + (size_t)(b * Ss + qr0) * Dd + h * HDd;
    __half* d1 = g_attn + (size_t)(b * Ss + qr0 + 8) * Dd + h * HDd;
    #pragma unroll
    for (int nf = 0; nf < 8; nf++) {
        int c = nf * 8 + 2 * lc;
        *(uint32_t*)(d0 + c) = pkh2(o[nf][0] * il0, o[nf][1] * il0);
        *(uint32_t*)(d1 + c) = pkh2(o[nf][2] * il1, o[nf][3] * il1);
    }
}

// ---------------- launch ------------------------------------------------------
extern "C" void kernel_launch(void* const* d_in, const int* in_sizes, int n_in,
                              void* d_out, int out_size)
{
    const float* hs   = (const float*)d_in[0];
    const int*   am   = (const int*)  d_in[1];
    const int*   pid  = (const int*)  d_in[2];
    const float* ln1  = (const float*)d_in[4];
    const float* wqkv = (const float*)d_in[5];
    const float* wout = (const float*)d_in[6];
    const float* ln2  = (const float*)d_in[7];
    float* out = (float*)d_out;

    __half *px, *pqkv, *pattn, *pwq, *pwo;
    cudaGetSymbolAddress((void**)&px,    g_x);
    cudaGetSymbolAddress((void**)&pqkv,  g_qkv);
    cudaGetSymbolAddress((void**)&pattn, g_attn);
    cudaGetSymbolAddress((void**)&pwq,   g_wqkvh);
    cudaGetSymbolAddress((void**)&pwo,   g_wouth);

    const int ATTN_SMEM = ATT_U32 * 4;
    cudaFuncSetAttribute(attn_kernel,
                         cudaFuncAttributeMaxDynamicSharedMemorySize, ATTN_SMEM);
    const int GEMM_SMEM = NSTG * STAGE_U * 4;
    cudaFuncSetAttribute(gemm_f16_kernel,
                         cudaFuncAttributeMaxDynamicSharedMemorySize, GEMM_SMEM);

    int n1 = Dd * QKVN / 4, n2 = Dd * Dd / 4;
    cvt2_kernel<<<(n1 + n2 + 255) / 256, 256>>>(wqkv, pwq, n1, wout, pwo, n2);
    invf_kernel<<<1, 32>>>();
    ln_kernel<<<Mrows, 256>>>(hs, ln1, px, 1);
    rope_table_kernel<<<(Bb * Ss * 32) / 256, 256>>>(pid);
    gemm_f16_kernel<<<dim3(QKVN / BN, Mrows / BM), 256, GEMM_SMEM>>>(
        px, pwq, pqkv, Mrows, QKVN, Dd, 0, nullptr);
    rope_apply_kernel<<<(Bb * Ss * 40 * 32) / 256, 256>>>();
    attn_kernel<<<dim3(Ss / 128, Hh, Bb), 256, ATTN_SMEM>>>(am);
    gemm_f16_kernel<<<dim3(Dd / BN, Mrows / BM), 256, GEMM_SMEM>>>(
        pattn, pwo, out, Mrows, Dd, Dd, 1, hs);
    ln_kernel<<<Mrows, 256>>>(out, ln2, out + OUTOFF, 0);
}

// round 8
// speedup vs baseline: 14.2773x; 1.0572x over previous
#include <cuda_runtime.h>
#include <cuda_fp16.h>
#include <math.h>
#include <stdint.h>

#define Bb    2
#define Ss    2048
#define Dd    2048
#define Hh    32
#define KVHh  8
#define HDd   64
#define QKVN  3072
#define Mrows (Bb*Ss)
#define OUTOFF ((size_t)Bb*Ss*Dd)
#define ATT_SCALE 0.125f

// ---------------- scratch ----------------------------------------------------
__device__ __half g_x[(size_t)Mrows*Dd];
__device__ __half g_q[(size_t)Bb*Hh*Ss*HDd];
__device__ __half g_k[(size_t)Bb*KVHh*Ss*HDd];
__device__ __half g_v[(size_t)Bb*KVHh*Ss*HDd];
__device__ __half g_attn[(size_t)Mrows*Dd];
__device__ __half g_wqkvh[(size_t)Dd*QKVN];
__device__ __half g_wouth[(size_t)Dd*Dd];
__device__ float g_cos[(size_t)Bb*Ss*32];
__device__ float g_sin[(size_t)Bb*Ss*32];
__device__ double g_invf[32];

__device__ __forceinline__ uint32_t pkh2(float x, float y) {
    __half2 h = __floats2half2_rn(x, y);
    return *(uint32_t*)&h;
}
__device__ __forceinline__ void mma_f16(float c[4], uint32_t a0, uint32_t a1,
                                        uint32_t a2, uint32_t a3,
                                        uint32_t b0, uint32_t b1)
{
    asm volatile(
        "mma.sync.aligned.m16n8k16.row.col.f32.f16.f16.f32 "
        "{%0,%1,%2,%3}, {%4,%5,%6,%7}, {%8,%9}, {%0,%1,%2,%3};"
        : "+f"(c[0]), "+f"(c[1]), "+f"(c[2]), "+f"(c[3])
        : "r"(a0), "r"(a1), "r"(a2), "r"(a3), "r"(b0), "r"(b1));
}
__device__ __forceinline__ void ldsm4t(uint32_t& r0, uint32_t& r1,
                                       uint32_t& r2, uint32_t& r3, uint32_t saddr)
{
    asm volatile(
        "ldmatrix.sync.aligned.m8n8.x4.trans.shared.b16 {%0,%1,%2,%3}, [%4];"
        : "=r"(r0), "=r"(r1), "=r"(r2), "=r"(r3) : "r"(saddr));
}
__device__ __forceinline__ void cpa16(uint32_t smem_addr, const void* gptr) {
    asm volatile("cp.async.cg.shared.global [%0], [%1], 16;"
                 :: "r"(smem_addr), "l"(gptr));
}
__device__ __forceinline__ void cpa4(uint32_t smem_addr, const void* gptr) {
    asm volatile("cp.async.ca.shared.global [%0], [%1], 4;"
                 :: "r"(smem_addr), "l"(gptr));
}
__device__ __forceinline__ void cpa_commit() {
    asm volatile("cp.async.commit_group;");
}
template<int N>
__device__ __forceinline__ void cpa_wait() {
    asm volatile("cp.async.wait_group %0;" :: "n"(N));
}
__device__ __forceinline__ float clip8(float v) {
    return fminf(fmaxf(v, -8.f), 8.f);
}

// ---------------- weight fp32 -> fp16 -----------------------------------------
__global__ void cvt2_kernel(const float* __restrict__ w1, __half* __restrict__ o1,
                            int n1, const float* __restrict__ w2,
                            __half* __restrict__ o2, int n2)
{
    int i = blockIdx.x * 256 + threadIdx.x;
    const float* src; __half* dst;
    if (i < n1) { src = w1 + (size_t)i * 4; dst = o1 + (size_t)i * 4; }
    else {
        i -= n1;
        if (i >= n2) return;
        src = w2 + (size_t)i * 4; dst = o2 + (size_t)i * 4;
    }
    float4 v = *(const float4*)src;
    uint32_t* d = (uint32_t*)dst;
    d[0] = pkh2(v.x, v.y);
    d[1] = pkh2(v.z, v.w);
}

// ---------------- LayerNorm ---------------------------------------------------
__global__ __launch_bounds__(256) void ln_kernel(
    const float* __restrict__ in, const float* __restrict__ sc,
    void* __restrict__ outp, int half_out)
{
    int row = blockIdx.x;
    const float* x = in + (size_t)row * Dd;
    float s = 0.f, s2 = 0.f;
    for (int i = threadIdx.x; i < Dd; i += 256) { float v = x[i]; s += v; s2 += v*v; }
    #pragma unroll
    for (int o = 16; o; o >>= 1) {
        s  += __shfl_xor_sync(0xffffffffu, s,  o);
        s2 += __shfl_xor_sync(0xffffffffu, s2, o);
    }
    __shared__ float ws[8], ws2[8];
    int w = threadIdx.x >> 5, l = threadIdx.x & 31;
    if (l == 0) { ws[w] = s; ws2[w] = s2; }
    __syncthreads();
    if (threadIdx.x < 32) {
        s  = (l < 8) ? ws[l]  : 0.f;
        s2 = (l < 8) ? ws2[l] : 0.f;
        #pragma unroll
        for (int o = 4; o; o >>= 1) {
            s  += __shfl_xor_sync(0xffffffffu, s,  o);
            s2 += __shfl_xor_sync(0xffffffffu, s2, o);
        }
        if (l == 0) { ws[0] = s; ws2[0] = s2; }
    }
    __syncthreads();
    float mean = ws[0] * (1.f / Dd);
    float var  = ws2[0] * (1.f / Dd) - mean * mean;
    float inv  = rsqrtf(var + 1e-6f);
    if (half_out) {
        __half* o_ = (__half*)outp + (size_t)row * Dd;
        for (int i = threadIdx.x * 2; i < Dd; i += 512) {
            float a = (x[i] - mean) * inv * sc[i];
            float b = (x[i+1] - mean) * inv * sc[i+1];
            *(uint32_t*)(o_ + i) = pkh2(a, b);
        }
    } else {
        float* o_ = (float*)outp + (size_t)row * Dd;
        for (int i = threadIdx.x; i < Dd; i += 256)
            o_[i] = (x[i] - mean) * inv * sc[i];
    }
}

// ---------------- FP16 GEMM 128x128x32, 3-stage cp.async ----------------------
// mode 0: qkv GEMM -> clip -> fused RoPE -> scatter to g_q/g_k/g_v
// mode 1: out GEMM -> + resid -> float Cp
#define BM 128
#define BN 128
#define BK 32
#define AS_U 20
#define AS_U32S (BM * AS_U)
#define BS_U32S (BK * 64)
#define STAGE_U (AS_U32S + BS_U32S)
#define NSTG 3

__global__ __launch_bounds__(256, 2) void gemm_f16_kernel(
    const __half* __restrict__ A, const __half* __restrict__ Bw,
    void* __restrict__ Cp, int M, int N, int K, int mode,
    const float* __restrict__ resid)
{
    extern __shared__ uint32_t smu[];
    int row0 = blockIdx.y * BM, col0 = blockIdx.x * BN;
    int t = threadIdx.x;
    int w = t >> 5, l = t & 31;
    int warpM = w >> 1, warpN = w & 1;
    int lr = l >> 2, lc = l & 3;

    const uint4* Au = (const uint4*)A;
    const uint4* Bu = (const uint4*)Bw;
    int K8 = K >> 3, N8 = N >> 3;

    uint32_t stAddr[NSTG];
    #pragma unroll
    for (int sidx = 0; sidx < NSTG; sidx++)
        stAddr[sidx] = (uint32_t)__cvta_generic_to_shared(smu + sidx * STAGE_U);

    int aRow[2], aC[2], bK[2], bDst[2];
    #pragma unroll
    for (int i = 0; i < 2; i++) {
        int idx = i * 256 + t;
        aRow[i] = idx >> 2;  aC[i] = idx & 3;
        int k = idx >> 4, c = idx & 15;
        bK[i] = k;
        bDst[i] = k * 64 + ((c * 4) ^ ((k & 7) << 2));
    }
    int bC0 = (col0 >> 3);

    float acc[2][8][4];
    #pragma unroll
    for (int mf = 0; mf < 2; mf++)
        #pragma unroll
        for (int nf = 0; nf < 8; nf++)
            #pragma unroll
            for (int r = 0; r < 4; r++) acc[mf][nf][r] = 0.f;

    int nk = K / BK;
    auto issue = [&](int kt, int stg) {
        if (kt < nk) {
            int k0 = kt * BK;
            uint32_t aBase = stAddr[stg];
            uint32_t bBase = stAddr[stg] + AS_U32S * 4;
            #pragma unroll
            for (int i = 0; i < 2; i++) {
                cpa16(aBase + (aRow[i] * AS_U + aC[i] * 4) * 4,
                      Au + (size_t)(row0 + aRow[i]) * K8 + (k0 >> 3) + aC[i]);
                int idx = i * 256 + t;
                cpa16(bBase + bDst[i] * 4,
                      Bu + (size_t)(k0 + bK[i]) * N8 + bC0 + (idx & 15));
            }
        }
        cpa_commit();
    };

    issue(0, 0);
    issue(1, 1);

    for (int kt = 0; kt < nk; kt++) {
        cpa_wait<1>();
        __syncthreads();
        issue(kt + 2, (kt + 2) % NSTG);

        int cur = kt % NSTG;
        const uint32_t* as = smu + cur * STAGE_U;
        uint32_t bsAddr = stAddr[cur] + AS_U32S * 4;
        #pragma unroll
        for (int ks = 0; ks < 2; ks++) {
            uint32_t af[2][4];
            #pragma unroll
            for (int mf = 0; mf < 2; mf++) {
                int r = warpM * 32 + mf * 16 + lr;
                af[mf][0] = as[r * AS_U + ks * 8 + lc];
                af[mf][1] = as[(r + 8) * AS_U + ks * 8 + lc];
                af[mf][2] = as[r * AS_U + ks * 8 + lc + 4];
                af[mf][3] = as[(r + 8) * AS_U + ks * 8 + lc + 4];
            }
            #pragma unroll
            for (int nfp = 0; nfp < 4; nfp++) {
                int krow = ks * 16 + (l & 15);
                int col = warpN * 32 + nfp * 8 + ((l >> 4) << 2);
                col ^= (krow & 7) << 2;
                uint32_t b0, b1, b2, b3;
                ldsm4t(b0, b1, b2, b3, bsAddr + (krow * 64 + col) * 4);
                #pragma unroll
                for (int mf = 0; mf < 2; mf++) {
                    mma_f16(acc[mf][2*nfp],   af[mf][0], af[mf][1], af[mf][2], af[mf][3], b0, b1);
                    mma_f16(acc[mf][2*nfp+1], af[mf][0], af[mf][1], af[mf][2], af[mf][3], b2, b3);
                }
            }
        }
    }

    if (mode == 0) {
        // ---- fused clip + RoPE + head-major scatter ----
        int gcol = col0 + warpN * 64;             // head base column in qkv
        int isV = (gcol >= Dd + KVHh * HDd);
        int isK = (gcol >= Dd) && !isV;
        __half* headBase;                         // + (b*? + head)*Ss*HD later
        int headIdx;
        if (isV)      headIdx = (gcol - Dd - KVHh * HDd) >> 6;
        else if (isK) headIdx = (gcol - Dd) >> 6;
        else          headIdx = gcol >> 6;
        #pragma unroll
        for (int mf = 0; mf < 2; mf++) {
            #pragma unroll
            for (int half = 0; half < 2; half++) {
                int row = row0 + warpM * 32 + mf * 16 + lr + half * 8;
                int s_ = row & (Ss - 1), b_ = row >> 11;
                __half* dst;
                if (isV)
                    dst = g_v + ((size_t)(b_ * KVHh + headIdx) * Ss + s_) * HDd;
                else if (isK)
                    dst = g_k + ((size_t)(b_ * KVHh + headIdx) * Ss + s_) * HDd;
                else
                    dst = g_q + ((size_t)(b_ * Hh + headIdx) * Ss + s_) * HDd;
                const float* cosb = g_cos + ((size_t)b_ << 16) + (s_ << 5);
                const float* sinb = g_sin + ((size_t)b_ << 16) + (s_ << 5);
                #pragma unroll
                for (int nf = 0; nf < 4; nf++) {
                    int c0 = nf * 8 + 2 * lc;     // 0..30, pair (c0, c0+1)
                    float x1a = clip8(acc[mf][nf][half * 2 + 0]);
                    float x1b = clip8(acc[mf][nf][half * 2 + 1]);
                    float x2a = clip8(acc[mf][nf + 4][half * 2 + 0]);
                    float x2b = clip8(acc[mf][nf + 4][half * 2 + 1]);
                    if (isV) {
                        *(uint32_t*)(dst + c0)      = pkh2(x1a, x1b);
                        *(uint32_t*)(dst + c0 + 32) = pkh2(x2a, x2b);
                    } else {
                        float ca = cosb[c0], cb = cosb[c0 + 1];
                        float sa = sinb[c0], sb = sinb[c0 + 1];
                        *(uint32_t*)(dst + c0) =
                            pkh2(x1a * ca - x2a * sa, x1b * cb - x2b * sb);
                        *(uint32_t*)(dst + c0 + 32) =
                            pkh2(x2a * ca + x1a * sa, x2b * cb + x1b * sb);
                    }
                }
            }
        }
    } else {
        #pragma unroll
        for (int mf = 0; mf < 2; mf++) {
            #pragma unroll
            for (int half = 0; half < 2; half++) {
                int row = row0 + warpM * 32 + mf * 16 + lr + half * 8;
                #pragma unroll
                for (int nf = 0; nf < 8; nf++) {
                    int col = col0 + warpN * 64 + nf * 8 + 2 * lc;
                    size_t off = (size_t)row * N + col;
                    float2 rv = *(const float2*)(resid + off);
                    float2 v;
                    v.x = acc[mf][nf][half * 2 + 0] + rv.x;
                    v.y = acc[mf][nf][half * 2 + 1] + rv.y;
                    *(float2*)((float*)Cp + off) = v;
                }
            }
        }
    }
}

// ---------------- RoPE tables --------------------------------------------------
__global__ void invf_kernel()
{
    int i = threadIdx.x;
    if (i < 32)
        g_invf[i] = exp(-((double)(2 * i) / 64.0) * log(500000.0));
}

__global__ void rope_table_kernel(const int* __restrict__ pid)
{
    int idx = blockIdx.x * 256 + threadIdx.x;
    if (idx >= Bb * Ss * 32) return;
    int i = idx & 31;
    int s = (idx >> 5) & (Ss - 1);
    int b = idx >> 16;
    double pos = (double)pid[b * Ss + s];
    double ang = pos * g_invf[i];
    double k = rint(ang * 0.15915494309189535);
    float r = (float)(ang - k * 6.283185307179586);
    g_cos[idx] = cosf(r);
    g_sin[idx] = sinf(r);
}

// ---------------- FP16 flash attention, 3-stage cp.async ----------------------
#define QP_U 36
#define KS_U 36
#define VS_U 32
#define NAS  3
#define SM_PS 0
#define SM_KS (128 * QP_U)
#define SM_VS (SM_KS + NAS * 64 * KS_U)
#define SM_MASK (SM_VS + NAS * 64 * VS_U)
#define ATT_U32 (SM_MASK + NAS * 64)
__global__ __launch_bounds__(256, 2) void attn_kernel(const int* __restrict__ amask)
{
    extern __shared__ uint32_t smu[];
    uint32_t* Ps = smu + SM_PS;
    int* maskS = (int*)(smu + SM_MASK);

    // heaviest q-tiles first: reverse launch order
    int qt = (gridDim.x - 1) - blockIdx.x;
    int h = blockIdx.y, b = blockIdx.z;
    int kvh = h >> 2;
    int q0 = qt * 128;
    int t = threadIdx.x;
    int w = t >> 5, l = t & 31;
    int lr = l >> 2, lc = l & 3;

    const uint4* Qg = (const uint4*)(g_q + ((size_t)(b * Hh + h) * Ss + q0) * HDd);
    const uint4* Kg = (const uint4*)(g_k + (size_t)(b * KVHh + kvh) * Ss * HDd);
    const uint4* Vg = (const uint4*)(g_v + (size_t)(b * KVHh + kvh) * Ss * HDd);
    const int*   Mg = amask + b * Ss;

    uint32_t ksAddr0 = (uint32_t)__cvta_generic_to_shared(smu + SM_KS);
    uint32_t vsAddr0 = (uint32_t)__cvta_generic_to_shared(smu + SM_VS);
    uint32_t mkAddr0 = (uint32_t)__cvta_generic_to_shared(maskS);

    int nkt = 2 * qt + 2;
    auto issueKV = [&](int kt, int stg) {
        if (kt < nkt) {
            int k0 = kt * 64;
            uint32_t kBase = ksAddr0 + stg * 64 * KS_U * 4;
            uint32_t vBase = vsAddr0 + stg * 64 * VS_U * 4;
            #pragma unroll
            for (int i = 0; i < 2; i++) {
                int idx = i * 256 + t;
                int row = idx >> 3, c = idx & 7;
                cpa16(kBase + (row * KS_U + c * 4) * 4, Kg + (k0 + row) * 8 + c);
                cpa16(vBase + (row * VS_U + ((c * 4) ^ ((row & 7) << 2))) * 4,
                      Vg + (k0 + row) * 8 + c);
            }
            if (t < 64) cpa4(mkAddr0 + (stg * 64 + t) * 4, Mg + k0 + t);
        }
        cpa_commit();
    };

    issueKV(0, 0);
    issueKV(1, 1);

    // ---- stage Q + extract frags ----
    #pragma unroll
    for (int i = 0; i < 4; i++) {
        int idx = i * 256 + t;
        int row = idx >> 3, c = idx & 7;
        *(uint4*)&Ps[row * QP_U + c * 4] = Qg[row * 8 + c];
    }
    __syncthreads();
    uint32_t qa[4][4];
    {
        int r0 = w * 16 + lr;
        #pragma unroll
        for (int ks = 0; ks < 4; ks++) {
            qa[ks][0] = Ps[r0 * QP_U + ks * 8 + lc];
            qa[ks][1] = Ps[(r0 + 8) * QP_U + ks * 8 + lc];
            qa[ks][2] = Ps[r0 * QP_U + ks * 8 + lc + 4];
            qa[ks][3] = Ps[(r0 + 8) * QP_U + ks * 8 + lc + 4];
        }
    }

    float m0 = -1e30f, m1 = -1e30f, l0 = 0.f, l1 = 0.f;
    float o[8][4];
    #pragma unroll
    for (int nf = 0; nf < 8; nf++)
        #pragma unroll
        for (int r = 0; r < 4; r++) o[nf][r] = 0.f;

    for (int kt = 0; kt < nkt; kt++) {
        cpa_wait<1>();
        __syncthreads();
        issueKV(kt + 2, (kt + 2) % NAS);

        int cur = kt % NAS;
        int k0 = kt * 64;
        int qlow = q0 + w * 16;
        bool active = (k0 <= qlow + 15);
        if (active) {
            float s[8][4];
            #pragma unroll
            for (int nf = 0; nf < 8; nf++)
                #pragma unroll
                for (int r = 0; r < 4; r++) s[nf][r] = 0.f;
            const uint32_t* kb = smu + SM_KS + cur * 64 * KS_U;
            #pragma unroll
            for (int ks = 0; ks < 4; ks++) {
                #pragma unroll
                for (int nf = 0; nf < 8; nf++) {
                    int n = nf * 8 + lr;
                    uint32_t b0 = kb[n * KS_U + ks * 8 + lc];
                    uint32_t b1 = kb[n * KS_U + ks * 8 + lc + 4];
                    mma_f16(s[nf], qa[ks][0], qa[ks][1], qa[ks][2], qa[ks][3], b0, b1);
                }
            }
            int qr0 = qlow + lr, qr1 = qr0 + 8;
            bool fullvis = (k0 + 63 <= qlow);
            #pragma unroll
            for (int nf = 0; nf < 8; nf++) {
                int kg0 = k0 + nf * 8 + 2 * lc;
                int ms0 = maskS[(cur << 6) + nf * 8 + 2 * lc];
                int ms1 = maskS[(cur << 6) + nf * 8 + 2 * lc + 1];
                s[nf][0] = (ms0 && (fullvis || kg0     <= qr0)) ? s[nf][0] * ATT_SCALE : -1e30f;
                s[nf][1] = (ms1 && (fullvis || kg0 + 1 <= qr0)) ? s[nf][1] * ATT_SCALE : -1e30f;
                s[nf][2] = (ms0 && (fullvis || kg0     <= qr1)) ? s[nf][2] * ATT_SCALE : -1e30f;
                s[nf][3] = (ms1 && (fullvis || kg0 + 1 <= qr1)) ? s[nf][3] * ATT_SCALE : -1e30f;
            }
            float mt0 = -1e30f, mt1 = -1e30f;
            #pragma unroll
            for (int nf = 0; nf < 8; nf++) {
                mt0 = fmaxf(mt0, fmaxf(s[nf][0], s[nf][1]));
                mt1 = fmaxf(mt1, fmaxf(s[nf][2], s[nf][3]));
            }
            mt0 = fmaxf(mt0, __shfl_xor_sync(0xffffffffu, mt0, 1));
            mt0 = fmaxf(mt0, __shfl_xor_sync(0xffffffffu, mt0, 2));
            mt1 = fmaxf(mt1, __shfl_xor_sync(0xffffffffu, mt1, 1));
            mt1 = fmaxf(mt1, __shfl_xor_sync(0xffffffffu, mt1, 2));
            float mn0 = fmaxf(m0, mt0), mn1 = fmaxf(m1, mt1);
            float rs0 = 0.f, rs1 = 0.f;
            #pragma unroll
            for (int nf = 0; nf < 8; nf++) {
                s[nf][0] = __expf(s[nf][0] - mn0);
                s[nf][1] = __expf(s[nf][1] - mn0);
                s[nf][2] = __expf(s[nf][2] - mn1);
                s[nf][3] = __expf(s[nf][3] - mn1);
                rs0 += s[nf][0] + s[nf][1];
                rs1 += s[nf][2] + s[nf][3];
            }
            rs0 += __shfl_xor_sync(0xffffffffu, rs0, 1);
            rs0 += __shfl_xor_sync(0xffffffffu, rs0, 2);
            rs1 += __shfl_xor_sync(0xffffffffu, rs1, 1);
            rs1 += __shfl_xor_sync(0xffffffffu, rs1, 2);
            float a0 = __expf(m0 - mn0), a1 = __expf(m1 - mn1);
            l0 = l0 * a0 + rs0;  l1 = l1 * a1 + rs1;
            m0 = mn0;  m1 = mn1;
            #pragma unroll
            for (int nf = 0; nf < 8; nf++) {
                o[nf][0] *= a0; o[nf][1] *= a0;
                o[nf][2] *= a1; o[nf][3] *= a1;
            }
            // ---- O += P V : P packed directly from S C-frags ----
            {
                uint32_t vsAddr = vsAddr0 + cur * 64 * VS_U * 4;
                #pragma unroll
                for (int ks = 0; ks < 4; ks++) {
                    uint32_t pa0 = pkh2(s[2*ks][0],   s[2*ks][1]);
                    uint32_t pa1 = pkh2(s[2*ks][2],   s[2*ks][3]);
                    uint32_t pa2 = pkh2(s[2*ks+1][0], s[2*ks+1][1]);
                    uint32_t pa3 = pkh2(s[2*ks+1][2], s[2*ks+1][3]);
                    #pragma unroll
                    for (int nfp = 0; nfp < 4; nfp++) {
                        int key = ks * 16 + (l & 15);
                        int col = nfp * 8 + ((l >> 4) << 2);
                        col ^= (key & 7) << 2;
                        uint32_t b0, b1, b2, b3;
                        ldsm4t(b0, b1, b2, b3, vsAddr + (key * VS_U + col) * 4);
                        mma_f16(o[2*nfp],   pa0, pa1, pa2, pa3, b0, b1);
                        mma_f16(o[2*nfp+1], pa0, pa1, pa2, pa3, b2, b3);
                    }
                }
            }
        }
    }

    float il0 = (l0 > 0.f) ? (1.f / l0) : 0.f;
    float il1 = (l1 > 0.f) ? (1.f / l1) : 0.f;
    int qr0 = q0 + w * 16 + lr;
    __half* d0 = g_attn + (size_t)(b * Ss + qr0) * Dd + h * HDd;
    __half* d1 = g_attn + (size_t)(b * Ss + qr0 + 8) * Dd + h * HDd;
    #pragma unroll
    for (int nf = 0; nf < 8; nf++) {
        int c = nf * 8 + 2 * lc;
        *(uint32_t*)(d0 + c) = pkh2(o[nf][0] * il0, o[nf][1] * il0);
        *(uint32_t*)(d1 + c) = pkh2(o[nf][2] * il1, o[nf][3] * il1);
    }
}

// ---------------- launch ------------------------------------------------------
extern "C" void kernel_launch(void* const* d_in, const int* in_sizes, int n_in,
                              void* d_out, int out_size)
{
    const float* hs   = (const float*)d_in[0];
    const int*   am   = (const int*)  d_in[1];
    const int*   pid  = (const int*)  d_in[2];
    const float* ln1  = (const float*)d_in[4];
    const float* wqkv = (const float*)d_in[5];
    const float* wout = (const float*)d_in[6];
    const float* ln2  = (const float*)d_in[7];
    float* out = (float*)d_out;

    __half *px, *pattn, *pwq, *pwo;
    cudaGetSymbolAddress((void**)&px,    g_x);
    cudaGetSymbolAddress((void**)&pattn, g_attn);
    cudaGetSymbolAddress((void**)&pwq,   g_wqkvh);
    cudaGetSymbolAddress((void**)&pwo,   g_wouth);

    const int ATTN_SMEM = ATT_U32 * 4;
    cudaFuncSetAttribute(attn_kernel,
                         cudaFuncAttributeMaxDynamicSharedMemorySize, ATTN_SMEM);
    const int GEMM_SMEM = NSTG * STAGE_U * 4;
    cudaFuncSetAttribute(gemm_f16_kernel,
                         cudaFuncAttributeMaxDynamicSharedMemorySize, GEMM_SMEM);

    int n1 = Dd * QKVN / 4, n2 = Dd * Dd / 4;
    cvt2_kernel<<<(n1 + n2 + 255) / 256, 256>>>(wqkv, pwq, n1, wout, pwo, n2);
    invf_kernel<<<1, 32>>>();
    ln_kernel<<<Mrows, 256>>>(hs, ln1, px, 1);
    rope_table_kernel<<<(Bb * Ss * 32) / 256, 256>>>(pid);
    // qkv GEMM with fused clip+rope+scatter (writes g_q/g_k/g_v directly)
    gemm_f16_kernel<<<dim3(QKVN / BN, Mrows / BM), 256, GEMM_SMEM>>>(
        px, pwq, nullptr, Mrows, QKVN, Dd, 0, nullptr);
    attn_kernel<<<dim3(Ss / 128, Hh, Bb), 256, ATTN_SMEM>>>(am);
    gemm_f16_kernel<<<dim3(Dd / BN, Mrows / BM), 256, GEMM_SMEM>>>(
        pattn, pwo, out, Mrows, Dd, Dd, 1, hs);
    ln_kernel<<<Mrows, 256>>>(out, ln2, out + OUTOFF, 0);
}

// round 9
// speedup vs baseline: 14.9266x; 1.0455x over previous
#include <cuda_runtime.h>
#include <cuda_fp16.h>
#include <math.h>
#include <stdint.h>

#define Bb    2
#define Ss    2048
#define Dd    2048
#define Hh    32
#define KVHh  8
#define HDd   64
#define QKVN  3072
#define Mrows (Bb*Ss)
#define OUTOFF ((size_t)Bb*Ss*Dd)
#define ATT_SCALE 0.125f

// ---------------- scratch ----------------------------------------------------
__device__ __half g_x[(size_t)Mrows*Dd];
__device__ __half g_q[(size_t)Bb*Hh*Ss*HDd];
__device__ __half g_k[(size_t)Bb*KVHh*Ss*HDd];
__device__ __half g_v[(size_t)Bb*KVHh*Ss*HDd];
__device__ __half g_attn[(size_t)Mrows*Dd];
__device__ __half g_wqkvh[(size_t)Dd*QKVN];
__device__ __half g_wouth[(size_t)Dd*Dd];
__device__ float g_cos[(size_t)Bb*Ss*32];
__device__ float g_sin[(size_t)Bb*Ss*32];
__device__ double g_invf[32];

__device__ __forceinline__ uint32_t pkh2(float x, float y) {
    __half2 h = __floats2half2_rn(x, y);
    return *(uint32_t*)&h;
}
__device__ __forceinline__ void mma_f16(float c[4], uint32_t a0, uint32_t a1,
                                        uint32_t a2, uint32_t a3,
                                        uint32_t b0, uint32_t b1)
{
    asm volatile(
        "mma.sync.aligned.m16n8k16.row.col.f32.f16.f16.f32 "
        "{%0,%1,%2,%3}, {%4,%5,%6,%7}, {%8,%9}, {%0,%1,%2,%3};"
        : "+f"(c[0]), "+f"(c[1]), "+f"(c[2]), "+f"(c[3])
        : "r"(a0), "r"(a1), "r"(a2), "r"(a3), "r"(b0), "r"(b1));
}
__device__ __forceinline__ void ldsm4(uint32_t& r0, uint32_t& r1,
                                      uint32_t& r2, uint32_t& r3, uint32_t saddr)
{
    asm volatile(
        "ldmatrix.sync.aligned.m8n8.x4.shared.b16 {%0,%1,%2,%3}, [%4];"
        : "=r"(r0), "=r"(r1), "=r"(r2), "=r"(r3) : "r"(saddr));
}
__device__ __forceinline__ void ldsm4t(uint32_t& r0, uint32_t& r1,
                                       uint32_t& r2, uint32_t& r3, uint32_t saddr)
{
    asm volatile(
        "ldmatrix.sync.aligned.m8n8.x4.trans.shared.b16 {%0,%1,%2,%3}, [%4];"
        : "=r"(r0), "=r"(r1), "=r"(r2), "=r"(r3) : "r"(saddr));
}
__device__ __forceinline__ void cpa16(uint32_t smem_addr, const void* gptr) {
    asm volatile("cp.async.cg.shared.global [%0], [%1], 16;"
                 :: "r"(smem_addr), "l"(gptr));
}
__device__ __forceinline__ void cpa4(uint32_t smem_addr, const void* gptr) {
    asm volatile("cp.async.ca.shared.global [%0], [%1], 4;"
                 :: "r"(smem_addr), "l"(gptr));
}
__device__ __forceinline__ void cpa_commit() {
    asm volatile("cp.async.commit_group;");
}
template<int N>
__device__ __forceinline__ void cpa_wait() {
    asm volatile("cp.async.wait_group %0;" :: "n"(N));
}
__device__ __forceinline__ float clip8(float v) {
    return fminf(fmaxf(v, -8.f), 8.f);
}

// ---------------- weight fp32 -> fp16 -----------------------------------------
__global__ void cvt2_kernel(const float* __restrict__ w1, __half* __restrict__ o1,
                            int n1, const float* __restrict__ w2,
                            __half* __restrict__ o2, int n2)
{
    int i = blockIdx.x * 256 + threadIdx.x;
    const float* src; __half* dst;
    if (i < n1) { src = w1 + (size_t)i * 4; dst = o1 + (size_t)i * 4; }
    else {
        i -= n1;
        if (i >= n2) return;
        src = w2 + (size_t)i * 4; dst = o2 + (size_t)i * 4;
    }
    float4 v = *(const float4*)src;
    uint32_t* d = (uint32_t*)dst;
    d[0] = pkh2(v.x, v.y);
    d[1] = pkh2(v.z, v.w);
}

// ---------------- LayerNorm ---------------------------------------------------
__global__ __launch_bounds__(256) void ln_kernel(
    const float* __restrict__ in, const float* __restrict__ sc,
    void* __restrict__ outp, int half_out)
{
    int row = blockIdx.x;
    const float* x = in + (size_t)row * Dd;
    float s = 0.f, s2 = 0.f;
    for (int i = threadIdx.x; i < Dd; i += 256) { float v = x[i]; s += v; s2 += v*v; }
    #pragma unroll
    for (int o = 16; o; o >>= 1) {
        s  += __shfl_xor_sync(0xffffffffu, s,  o);
        s2 += __shfl_xor_sync(0xffffffffu, s2, o);
    }
    __shared__ float ws[8], ws2[8];
    int w = threadIdx.x >> 5, l = threadIdx.x & 31;
    if (l == 0) { ws[w] = s; ws2[w] = s2; }
    __syncthreads();
    if (threadIdx.x < 32) {
        s  = (l < 8) ? ws[l]  : 0.f;
        s2 = (l < 8) ? ws2[l] : 0.f;
        #pragma unroll
        for (int o = 4; o; o >>= 1) {
            s  += __shfl_xor_sync(0xffffffffu, s,  o);
            s2 += __shfl_xor_sync(0xffffffffu, s2, o);
        }
        if (l == 0) { ws[0] = s; ws2[0] = s2; }
    }
    __syncthreads();
    float mean = ws[0] * (1.f / Dd);
    float var  = ws2[0] * (1.f / Dd) - mean * mean;
    float inv  = rsqrtf(var + 1e-6f);
    if (half_out) {
        __half* o_ = (__half*)outp + (size_t)row * Dd;
        for (int i = threadIdx.x * 2; i < Dd; i += 512) {
            float a = (x[i] - mean) * inv * sc[i];
            float b = (x[i+1] - mean) * inv * sc[i+1];
            *(uint32_t*)(o_ + i) = pkh2(a, b);
        }
    } else {
        float* o_ = (float*)outp + (size_t)row * Dd;
        for (int i = threadIdx.x; i < Dd; i += 256)
            o_[i] = (x[i] - mean) * inv * sc[i];
    }
}

// ---------------- FP16 GEMM 128x128x32, 3-stage cp.async ----------------------
#define BM 128
#define BN 128
#define BK 32
#define AS_U 20
#define AS_U32S (BM * AS_U)
#define BS_U32S (BK * 64)
#define STAGE_U (AS_U32S + BS_U32S)
#define NSTG 3

__global__ __launch_bounds__(256, 2) void gemm_f16_kernel(
    const __half* __restrict__ A, const __half* __restrict__ Bw,
    void* __restrict__ Cp, int M, int N, int K, int mode,
    const float* __restrict__ resid)
{
    extern __shared__ uint32_t smu[];
    int row0 = blockIdx.y * BM, col0 = blockIdx.x * BN;
    int t = threadIdx.x;
    int w = t >> 5, l = t & 31;
    int warpM = w >> 1, warpN = w & 1;
    int lr = l >> 2, lc = l & 3;

    const uint4* Au = (const uint4*)A;
    const uint4* Bu = (const uint4*)Bw;
    int K8 = K >> 3, N8 = N >> 3;

    uint32_t stAddr[NSTG];
    #pragma unroll
    for (int sidx = 0; sidx < NSTG; sidx++)
        stAddr[sidx] = (uint32_t)__cvta_generic_to_shared(smu + sidx * STAGE_U);

    int aRow[2], aC[2], bK[2], bDst[2];
    #pragma unroll
    for (int i = 0; i < 2; i++) {
        int idx = i * 256 + t;
        aRow[i] = idx >> 2;  aC[i] = idx & 3;
        int k = idx >> 4, c = idx & 15;
        bK[i] = k;
        bDst[i] = k * 64 + ((c * 4) ^ ((k & 7) << 2));
    }
    int bC0 = (col0 >> 3);

    float acc[2][8][4];
    #pragma unroll
    for (int mf = 0; mf < 2; mf++)
        #pragma unroll
        for (int nf = 0; nf < 8; nf++)
            #pragma unroll
            for (int r = 0; r < 4; r++) acc[mf][nf][r] = 0.f;

    int nk = K / BK;
    auto issue = [&](int kt, int stg) {
        if (kt < nk) {
            int k0 = kt * BK;
            uint32_t aBase = stAddr[stg];
            uint32_t bBase = stAddr[stg] + AS_U32S * 4;
            #pragma unroll
            for (int i = 0; i < 2; i++) {
                cpa16(aBase + (aRow[i] * AS_U + aC[i] * 4) * 4,
                      Au + (size_t)(row0 + aRow[i]) * K8 + (k0 >> 3) + aC[i]);
                int idx = i * 256 + t;
                cpa16(bBase + bDst[i] * 4,
                      Bu + (size_t)(k0 + bK[i]) * N8 + bC0 + (idx & 15));
            }
        }
        cpa_commit();
    };

    issue(0, 0);
    issue(1, 1);

    // ldmatrix lane offsets (A non-trans): row = l&15, k-half = (l>>4)*4 u32
    int aLdsmRow = l & 15;
    int aLdsmCol = (l >> 4) << 2;

    for (int kt = 0; kt < nk; kt++) {
        cpa_wait<1>();
        __syncthreads();
        issue(kt + 2, (kt + 2) % NSTG);

        int cur = kt % NSTG;
        uint32_t asAddr = stAddr[cur];
        uint32_t bsAddr = stAddr[cur] + AS_U32S * 4;
        #pragma unroll
        for (int ks = 0; ks < 2; ks++) {
            uint32_t af[2][4];
            #pragma unroll
            for (int mf = 0; mf < 2; mf++) {
                int r = warpM * 32 + mf * 16;
                ldsm4(af[mf][0], af[mf][1], af[mf][2], af[mf][3],
                      asAddr + ((r + aLdsmRow) * AS_U + ks * 8 + aLdsmCol) * 4);
            }
            #pragma unroll
            for (int nfp = 0; nfp < 4; nfp++) {
                int krow = ks * 16 + (l & 15);
                int col = warpN * 32 + nfp * 8 + ((l >> 4) << 2);
                col ^= (krow & 7) << 2;
                uint32_t b0, b1, b2, b3;
                ldsm4t(b0, b1, b2, b3, bsAddr + (krow * 64 + col) * 4);
                #pragma unroll
                for (int mf = 0; mf < 2; mf++) {
                    mma_f16(acc[mf][2*nfp],   af[mf][0], af[mf][1], af[mf][2], af[mf][3], b0, b1);
                    mma_f16(acc[mf][2*nfp+1], af[mf][0], af[mf][1], af[mf][2], af[mf][3], b2, b3);
                }
            }
        }
    }

    if (mode == 0) {
        // ---- fused clip + RoPE + head-major scatter ----
        int gcol = col0 + warpN * 64;
        int isV = (gcol >= Dd + KVHh * HDd);
        int isK = (gcol >= Dd) && !isV;
        int headIdx;
        if (isV)      headIdx = (gcol - Dd - KVHh * HDd) >> 6;
        else if (isK) headIdx = (gcol - Dd) >> 6;
        else          headIdx = gcol >> 6;
        #pragma unroll
        for (int mf = 0; mf < 2; mf++) {
            #pragma unroll
            for (int half = 0; half < 2; half++) {
                int row = row0 + warpM * 32 + mf * 16 + lr + half * 8;
                int s_ = row & (Ss - 1), b_ = row >> 11;
                __half* dst;
                if (isV)
                    dst = g_v + ((size_t)(b_ * KVHh + headIdx) * Ss + s_) * HDd;
                else if (isK)
                    dst = g_k + ((size_t)(b_ * KVHh + headIdx) * Ss + s_) * HDd;
                else
                    dst = g_q + ((size_t)(b_ * Hh + headIdx) * Ss + s_) * HDd;
                const float* cosb = g_cos + ((size_t)b_ << 16) + (s_ << 5);
                const float* sinb = g_sin + ((size_t)b_ << 16) + (s_ << 5);
                #pragma unroll
                for (int nf = 0; nf < 4; nf++) {
                    int c0 = nf * 8 + 2 * lc;
                    float x1a = clip8(acc[mf][nf][half * 2 + 0]);
                    float x1b = clip8(acc[mf][nf][half * 2 + 1]);
                    float x2a = clip8(acc[mf][nf + 4][half * 2 + 0]);
                    float x2b = clip8(acc[mf][nf + 4][half * 2 + 1]);
                    if (isV) {
                        *(uint32_t*)(dst + c0)      = pkh2(x1a, x1b);
                        *(uint32_t*)(dst + c0 + 32) = pkh2(x2a, x2b);
                    } else {
                        float ca = cosb[c0], cb = cosb[c0 + 1];
                        float sa = sinb[c0], sb = sinb[c0 + 1];
                        *(uint32_t*)(dst + c0) =
                            pkh2(x1a * ca - x2a * sa, x1b * cb - x2b * sb);
                        *(uint32_t*)(dst + c0 + 32) =
                            pkh2(x2a * ca + x1a * sa, x2b * cb + x1b * sb);
                    }
                }
            }
        }
    } else {
        #pragma unroll
        for (int mf = 0; mf < 2; mf++) {
            #pragma unroll
            for (int half = 0; half < 2; half++) {
                int row = row0 + warpM * 32 + mf * 16 + lr + half * 8;
                #pragma unroll
                for (int nf = 0; nf < 8; nf++) {
                    int col = col0 + warpN * 64 + nf * 8 + 2 * lc;
                    size_t off = (size_t)row * N + col;
                    float2 rv = *(const float2*)(resid + off);
                    float2 v;
                    v.x = acc[mf][nf][half * 2 + 0] + rv.x;
                    v.y = acc[mf][nf][half * 2 + 1] + rv.y;
                    *(float2*)((float*)Cp + off) = v;
                }
            }
        }
    }
}

// ---------------- RoPE tables --------------------------------------------------
__global__ void invf_kernel()
{
    int i = threadIdx.x;
    if (i < 32)
        g_invf[i] = exp(-((double)(2 * i) / 64.0) * log(500000.0));
}

__global__ void rope_table_kernel(const int* __restrict__ pid)
{
    int idx = blockIdx.x * 256 + threadIdx.x;
    if (idx >= Bb * Ss * 32) return;
    int i = idx & 31;
    int s = (idx >> 5) & (Ss - 1);
    int b = idx >> 16;
    double pos = (double)pid[b * Ss + s];
    double ang = pos * g_invf[i];
    double k = rint(ang * 0.15915494309189535);
    float r = (float)(ang - k * 6.283185307179586);
    g_cos[idx] = cosf(r);
    g_sin[idx] = sinf(r);
}

// ---------------- FP16 flash attention, 3-stage cp.async ----------------------
#define QP_U 36
#define KS_U 36
#define VS_U 32
#define NAS  3
#define SM_PS 0
#define SM_KS (128 * QP_U)
#define SM_VS (SM_KS + NAS * 64 * KS_U)
#define SM_MASK (SM_VS + NAS * 64 * VS_U)
#define ATT_U32 (SM_MASK + NAS * 64)
__global__ __launch_bounds__(256, 2) void attn_kernel(const int* __restrict__ amask)
{
    extern __shared__ uint32_t smu[];
    uint32_t* Ps = smu + SM_PS;
    int* maskS = (int*)(smu + SM_MASK);

    int qt = (gridDim.x - 1) - blockIdx.x;
    int h = blockIdx.y, b = blockIdx.z;
    int kvh = h >> 2;
    int q0 = qt * 128;
    int t = threadIdx.x;
    int w = t >> 5, l = t & 31;
    int lr = l >> 2, lc = l & 3;

    const uint4* Qg = (const uint4*)(g_q + ((size_t)(b * Hh + h) * Ss + q0) * HDd);
    const uint4* Kg = (const uint4*)(g_k + (size_t)(b * KVHh + kvh) * Ss * HDd);
    const uint4* Vg = (const uint4*)(g_v + (size_t)(b * KVHh + kvh) * Ss * HDd);
    const int*   Mg = amask + b * Ss;

    uint32_t ksAddr0 = (uint32_t)__cvta_generic_to_shared(smu + SM_KS);
    uint32_t vsAddr0 = (uint32_t)__cvta_generic_to_shared(smu + SM_VS);
    uint32_t mkAddr0 = (uint32_t)__cvta_generic_to_shared(maskS);

    int nkt = 2 * qt + 2;
    auto issueKV = [&](int kt, int stg) {
        if (kt < nkt) {
            int k0 = kt * 64;
            uint32_t kBase = ksAddr0 + stg * 64 * KS_U * 4;
            uint32_t vBase = vsAddr0 + stg * 64 * VS_U * 4;
            #pragma unroll
            for (int i = 0; i < 2; i++) {
                int idx = i * 256 + t;
                int row = idx >> 3, c = idx & 7;
                cpa16(kBase + (row * KS_U + c * 4) * 4, Kg + (k0 + row) * 8 + c);
                cpa16(vBase + (row * VS_U + ((c * 4) ^ ((row & 7) << 2))) * 4,
                      Vg + (k0 + row) * 8 + c);
            }
            if (t < 64) cpa4(mkAddr0 + (stg * 64 + t) * 4, Mg + k0 + t);
        }
        cpa_commit();
    };

    issueKV(0, 0);
    issueKV(1, 1);

    // ---- stage Q + extract frags ----
    #pragma unroll
    for (int i = 0; i < 4; i++) {
        int idx = i * 256 + t;
        int row = idx >> 3, c = idx & 7;
        *(uint4*)&Ps[row * QP_U + c * 4] = Qg[row * 8 + c];
    }
    __syncthreads();
    uint32_t qa[4][4];
    {
        int r0 = w * 16 + lr;
        #pragma unroll
        for (int ks = 0; ks < 4; ks++) {
            qa[ks][0] = Ps[r0 * QP_U + ks * 8 + lc];
            qa[ks][1] = Ps[(r0 + 8) * QP_U + ks * 8 + lc];
            qa[ks][2] = Ps[r0 * QP_U + ks * 8 + lc + 4];
            qa[ks][3] = Ps[(r0 + 8) * QP_U + ks * 8 + lc + 4];
        }
    }

    float m0 = -1e30f, m1 = -1e30f, l0 = 0.f, l1 = 0.f;
    float o[8][4];
    #pragma unroll
    for (int nf = 0; nf < 8; nf++)
        #pragma unroll
        for (int r = 0; r < 4; r++) o[nf][r] = 0.f;

    // ldmatrix lane offsets for K (non-trans)
    int kLdsmRow = l & 15;
    int kLdsmCol = (l >> 4) << 2;

    for (int kt = 0; kt < nkt; kt++) {
        cpa_wait<1>();
        __syncthreads();
        issueKV(kt + 2, (kt + 2) % NAS);

        int cur = kt % NAS;
        int k0 = kt * 64;
        int qlow = q0 + w * 16;
        bool active = (k0 <= qlow + 15);
        if (active) {
            // ---- S = Q K^T (K B-frags via ldmatrix.x4) ----
            float s[8][4];
            #pragma unroll
            for (int nf = 0; nf < 8; nf++)
                #pragma unroll
                for (int r = 0; r < 4; r++) s[nf][r] = 0.f;
            uint32_t kbAddr = ksAddr0 + cur * 64 * KS_U * 4;
            #pragma unroll
            for (int ks = 0; ks < 4; ks++) {
                #pragma unroll
                for (int p = 0; p < 4; p++) {
                    uint32_t b0, b1, b2, b3;
                    ldsm4(b0, b1, b2, b3,
                          kbAddr + ((p * 16 + kLdsmRow) * KS_U + ks * 8 + kLdsmCol) * 4);
                    mma_f16(s[2*p],   qa[ks][0], qa[ks][1], qa[ks][2], qa[ks][3], b0, b2);
                    mma_f16(s[2*p+1], qa[ks][0], qa[ks][1], qa[ks][2], qa[ks][3], b1, b3);
                }
            }
            // ---- mask + scale ----
            int qr0 = qlow + lr, qr1 = qr0 + 8;
            bool fullvis = (k0 + 63 <= qlow);
            #pragma unroll
            for (int nf = 0; nf < 8; nf++) {
                int kg0 = k0 + nf * 8 + 2 * lc;
                int ms0 = maskS[(cur << 6) + nf * 8 + 2 * lc];
                int ms1 = maskS[(cur << 6) + nf * 8 + 2 * lc + 1];
                s[nf][0] = (ms0 && (fullvis || kg0     <= qr0)) ? s[nf][0] * ATT_SCALE : -1e30f;
                s[nf][1] = (ms1 && (fullvis || kg0 + 1 <= qr0)) ? s[nf][1] * ATT_SCALE : -1e30f;
                s[nf][2] = (ms0 && (fullvis || kg0     <= qr1)) ? s[nf][2] * ATT_SCALE : -1e30f;
                s[nf][3] = (ms1 && (fullvis || kg0 + 1 <= qr1)) ? s[nf][3] * ATT_SCALE : -1e30f;
            }
            // ---- online softmax ----
            float mt0 = -1e30f, mt1 = -1e30f;
            #pragma unroll
            for (int nf = 0; nf < 8; nf++) {
                mt0 = fmaxf(mt0, fmaxf(s[nf][0], s[nf][1]));
                mt1 = fmaxf(mt1, fmaxf(s[nf][2], s[nf][3]));
            }
            mt0 = fmaxf(mt0, __shfl_xor_sync(0xffffffffu, mt0, 1));
            mt0 = fmaxf(mt0, __shfl_xor_sync(0xffffffffu, mt0, 2));
            mt1 = fmaxf(mt1, __shfl_xor_sync(0xffffffffu, mt1, 1));
            mt1 = fmaxf(mt1, __shfl_xor_sync(0xffffffffu, mt1, 2));
            float mn0 = fmaxf(m0, mt0), mn1 = fmaxf(m1, mt1);
            float rs0 = 0.f, rs1 = 0.f;
            #pragma unroll
            for (int nf = 0; nf < 8; nf++) {
                s[nf][0] = __expf(s[nf][0] - mn0);
                s[nf][1] = __expf(s[nf][1] - mn0);
                s[nf][2] = __expf(s[nf][2] - mn1);
                s[nf][3] = __expf(s[nf][3] - mn1);
                rs0 += s[nf][0] + s[nf][1];
                rs1 += s[nf][2] + s[nf][3];
            }
            rs0 += __shfl_xor_sync(0xffffffffu, rs0, 1);
            rs0 += __shfl_xor_sync(0xffffffffu, rs0, 2);
            rs1 += __shfl_xor_sync(0xffffffffu, rs1, 1);
            rs1 += __shfl_xor_sync(0xffffffffu, rs1, 2);
            float a0 = __expf(m0 - mn0), a1 = __expf(m1 - mn1);
            l0 = l0 * a0 + rs0;  l1 = l1 * a1 + rs1;
            m0 = mn0;  m1 = mn1;
            #pragma unroll
            for (int nf = 0; nf < 8; nf++) {
                o[nf][0] *= a0; o[nf][1] *= a0;
                o[nf][2] *= a1; o[nf][3] *= a1;
            }
            // ---- O += P V : P packed directly from S C-frags ----
            {
                uint32_t vsAddr = vsAddr0 + cur * 64 * VS_U * 4;
                #pragma unroll
                for (int ks = 0; ks < 4; ks++) {
                    uint32_t pa0 = pkh2(s[2*ks][0],   s[2*ks][1]);
                    uint32_t pa1 = pkh2(s[2*ks][2],   s[2*ks][3]);
                    uint32_t pa2 = pkh2(s[2*ks+1][0], s[2*ks+1][1]);
                    uint32_t pa3 = pkh2(s[2*ks+1][2], s[2*ks+1][3]);
                    #pragma unroll
                    for (int nfp = 0; nfp < 4; nfp++) {
                        int key = ks * 16 + (l & 15);
                        int col = nfp * 8 + ((l >> 4) << 2);
                        col ^= (key & 7) << 2;
                        uint32_t b0, b1, b2, b3;
                        ldsm4t(b0, b1, b2, b3, vsAddr + (key * VS_U + col) * 4);
                        mma_f16(o[2*nfp],   pa0, pa1, pa2, pa3, b0, b1);
                        mma_f16(o[2*nfp+1], pa0, pa1, pa2, pa3, b2, b3);
                    }
                }
            }
        }
    }

    float il0 = (l0 > 0.f) ? (1.f / l0) : 0.f;
    float il1 = (l1 > 0.f) ? (1.f / l1) : 0.f;
    int qr0 = q0 + w * 16 + lr;
    __half* d0 = g_attn + (size_t)(b * Ss + qr0) * Dd + h * HDd;
    __half* d1 = g_attn + (size_t)(b * Ss + qr0 + 8) * Dd + h * HDd;
    #pragma unroll
    for (int nf = 0; nf < 8; nf++) {
        int c = nf * 8 + 2 * lc;
        *(uint32_t*)(d0 + c) = pkh2(o[nf][0] * il0, o[nf][1] * il0);
        *(uint32_t*)(d1 + c) = pkh2(o[nf][2] * il1, o[nf][3] * il1);
    }
}

// ---------------- launch ------------------------------------------------------
extern "C" void kernel_launch(void* const* d_in, const int* in_sizes, int n_in,
                              void* d_out, int out_size)
{
    const float* hs   = (const float*)d_in[0];
    const int*   am   = (const int*)  d_in[1];
    const int*   pid  = (const int*)  d_in[2];
    const float* ln1  = (const float*)d_in[4];
    const float* wqkv = (const float*)d_in[5];
    const float* wout = (const float*)d_in[6];
    const float* ln2  = (const float*)d_in[7];
    float* out = (float*)d_out;

    __half *px, *pattn, *pwq, *pwo;
    cudaGetSymbolAddress((void**)&px,    g_x);
    cudaGetSymbolAddress((void**)&pattn, g_attn);
    cudaGetSymbolAddress((void**)&pwq,   g_wqkvh);
    cudaGetSymbolAddress((void**)&pwo,   g_wouth);

    const int ATTN_SMEM = ATT_U32 * 4;
    cudaFuncSetAttribute(attn_kernel,
                         cudaFuncAttributeMaxDynamicSharedMemorySize, ATTN_SMEM);
    const int GEMM_SMEM = NSTG * STAGE_U * 4;
    cudaFuncSetAttribute(gemm_f16_kernel,
                         cudaFuncAttributeMaxDynamicSharedMemorySize, GEMM_SMEM);

    int n1 = Dd * QKVN / 4, n2 = Dd * Dd / 4;
    cvt2_kernel<<<(n1 + n2 + 255) / 256, 256>>>(wqkv, pwq, n1, wout, pwo, n2);
    invf_kernel<<<1, 32>>>();
    ln_kernel<<<Mrows, 256>>>(hs, ln1, px, 1);
    rope_table_kernel<<<(Bb * Ss * 32) / 256, 256>>>(pid);
    gemm_f16_kernel<<<dim3(QKVN / BN, Mrows / BM), 256, GEMM_SMEM>>>(
        px, pwq, nullptr, Mrows, QKVN, Dd, 0, nullptr);
    attn_kernel<<<dim3(Ss / 128, Hh, Bb), 256, ATTN_SMEM>>>(am);
    gemm_f16_kernel<<<dim3(Dd / BN, Mrows / BM), 256, GEMM_SMEM>>>(
        pattn, pwo, out, Mrows, Dd, Dd, 1, hs);
    ln_kernel<<<Mrows, 256>>>(out, ln2, out + OUTOFF, 0);
}

// round 10
// speedup vs baseline: 15.2158x; 1.0194x over previous
#include <cuda_runtime.h>
#include <cuda_fp16.h>
#include <math.h>
#include <stdint.h>

#define Bb    2
#define Ss    2048
#define Dd    2048
#define Hh    32
#define KVHh  8
#define HDd   64
#define QKVN  3072
#define Mrows (Bb*Ss)
#define OUTOFF ((size_t)Bb*Ss*Dd)
#define ATT_SCALE 0.125f

// ---------------- scratch ----------------------------------------------------
__device__ __half g_x[(size_t)Mrows*Dd];
__device__ __half g_q[(size_t)Bb*Hh*Ss*HDd];
__device__ __half g_k[(size_t)Bb*KVHh*Ss*HDd];
__device__ __half g_v[(size_t)Bb*KVHh*Ss*HDd];
__device__ __half g_attn[(size_t)Mrows*Dd];
__device__ __half g_wqkvh[(size_t)Dd*QKVN];
__device__ __half g_wouth[(size_t)Dd*Dd];
__device__ float g_cos[(size_t)Bb*Ss*32];
__device__ float g_sin[(size_t)Bb*Ss*32];
__device__ double g_invf[32];

__device__ __forceinline__ uint32_t pkh2(float x, float y) {
    __half2 h = __floats2half2_rn(x, y);
    return *(uint32_t*)&h;
}
__device__ __forceinline__ void mma_f16(float c[4], uint32_t a0, uint32_t a1,
                                        uint32_t a2, uint32_t a3,
                                        uint32_t b0, uint32_t b1)
{
    asm volatile(
        "mma.sync.aligned.m16n8k16.row.col.f32.f16.f16.f32 "
        "{%0,%1,%2,%3}, {%4,%5,%6,%7}, {%8,%9}, {%0,%1,%2,%3};"
        : "+f"(c[0]), "+f"(c[1]), "+f"(c[2]), "+f"(c[3])
        : "r"(a0), "r"(a1), "r"(a2), "r"(a3), "r"(b0), "r"(b1));
}
__device__ __forceinline__ void ldsm4(uint32_t& r0, uint32_t& r1,
                                      uint32_t& r2, uint32_t& r3, uint32_t saddr)
{
    asm volatile(
        "ldmatrix.sync.aligned.m8n8.x4.shared.b16 {%0,%1,%2,%3}, [%4];"
        : "=r"(r0), "=r"(r1), "=r"(r2), "=r"(r3) : "r"(saddr));
}
__device__ __forceinline__ void ldsm4t(uint32_t& r0, uint32_t& r1,
                                       uint32_t& r2, uint32_t& r3, uint32_t saddr)
{
    asm volatile(
        "ldmatrix.sync.aligned.m8n8.x4.trans.shared.b16 {%0,%1,%2,%3}, [%4];"
        : "=r"(r0), "=r"(r1), "=r"(r2), "=r"(r3) : "r"(saddr));
}
__device__ __forceinline__ void cpa16(uint32_t smem_addr, const void* gptr) {
    asm volatile("cp.async.cg.shared.global [%0], [%1], 16;"
                 :: "r"(smem_addr), "l"(gptr));
}
__device__ __forceinline__ void cpa4(uint32_t smem_addr, const void* gptr) {
    asm volatile("cp.async.ca.shared.global [%0], [%1], 4;"
                 :: "r"(smem_addr), "l"(gptr));
}
__device__ __forceinline__ void cpa_commit() {
    asm volatile("cp.async.commit_group;");
}
template<int N>
__device__ __forceinline__ void cpa_wait() {
    asm volatile("cp.async.wait_group %0;" :: "n"(N));
}
__device__ __forceinline__ float clip8(float v) {
    return fminf(fmaxf(v, -8.f), 8.f);
}

// ---------------- weight fp32 -> fp16 -----------------------------------------
__global__ void cvt2_kernel(const float* __restrict__ w1, __half* __restrict__ o1,
                            int n1, const float* __restrict__ w2,
                            __half* __restrict__ o2, int n2)
{
    int i = blockIdx.x * 256 + threadIdx.x;
    const float* src; __half* dst;
    if (i < n1) { src = w1 + (size_t)i * 4; dst = o1 + (size_t)i * 4; }
    else {
        i -= n1;
        if (i >= n2) return;
        src = w2 + (size_t)i * 4; dst = o2 + (size_t)i * 4;
    }
    float4 v = *(const float4*)src;
    uint32_t* d = (uint32_t*)dst;
    d[0] = pkh2(v.x, v.y);
    d[1] = pkh2(v.z, v.w);
}

// ---------------- LayerNorm ---------------------------------------------------
__global__ __launch_bounds__(256) void ln_kernel(
    const float* __restrict__ in, const float* __restrict__ sc,
    void* __restrict__ outp, int half_out)
{
    int row = blockIdx.x;
    const float* x = in + (size_t)row * Dd;
    float s = 0.f, s2 = 0.f;
    for (int i = threadIdx.x; i < Dd; i += 256) { float v = x[i]; s += v; s2 += v*v; }
    #pragma unroll
    for (int o = 16; o; o >>= 1) {
        s  += __shfl_xor_sync(0xffffffffu, s,  o);
        s2 += __shfl_xor_sync(0xffffffffu, s2, o);
    }
    __shared__ float ws[8], ws2[8];
    int w = threadIdx.x >> 5, l = threadIdx.x & 31;
    if (l == 0) { ws[w] = s; ws2[w] = s2; }
    __syncthreads();
    if (threadIdx.x < 32) {
        s  = (l < 8) ? ws[l]  : 0.f;
        s2 = (l < 8) ? ws2[l] : 0.f;
        #pragma unroll
        for (int o = 4; o; o >>= 1) {
            s  += __shfl_xor_sync(0xffffffffu, s,  o);
            s2 += __shfl_xor_sync(0xffffffffu, s2, o);
        }
        if (l == 0) { ws[0] = s; ws2[0] = s2; }
    }
    __syncthreads();
    float mean = ws[0] * (1.f / Dd);
    float var  = ws2[0] * (1.f / Dd) - mean * mean;
    float inv  = rsqrtf(var + 1e-6f);
    if (half_out) {
        __half* o_ = (__half*)outp + (size_t)row * Dd;
        for (int i = threadIdx.x * 2; i < Dd; i += 512) {
            float a = (x[i] - mean) * inv * sc[i];
            float b = (x[i+1] - mean) * inv * sc[i+1];
            *(uint32_t*)(o_ + i) = pkh2(a, b);
        }
    } else {
        float* o_ = (float*)outp + (size_t)row * Dd;
        for (int i = threadIdx.x; i < Dd; i += 256)
            o_[i] = (x[i] - mean) * inv * sc[i];
    }
}

// ---------------- FP16 GEMM 128x128x64, 3-stage cp.async ----------------------
#define BM 128
#define BN 128
#define BK 64
#define AS_U 36                    // 32 data u32 + 4 pad; row banks 4r%32 ok
#define AS_U32S (BM * AS_U)        // 4608
#define BS_U32S (BK * 64)          // 4096
#define STAGE_U (AS_U32S + BS_U32S)  // 8704 u32 = 34816 B
#define NSTG 3

__global__ __launch_bounds__(256, 2) void gemm_f16_kernel(
    const __half* __restrict__ A, const __half* __restrict__ Bw,
    void* __restrict__ Cp, int M, int N, int K, int mode,
    const float* __restrict__ resid)
{
    extern __shared__ uint32_t smu[];
    int row0 = blockIdx.y * BM, col0 = blockIdx.x * BN;
    int t = threadIdx.x;
    int w = t >> 5, l = t & 31;
    int warpM = w >> 1, warpN = w & 1;
    int lr = l >> 2, lc = l & 3;

    const uint4* Au = (const uint4*)A;
    const uint4* Bu = (const uint4*)Bw;
    int K8 = K >> 3, N8 = N >> 3;

    uint32_t stAddr[NSTG];
    #pragma unroll
    for (int sidx = 0; sidx < NSTG; sidx++)
        stAddr[sidx] = (uint32_t)__cvta_generic_to_shared(smu + sidx * STAGE_U);

    // A: 4 chunks/thread (1024 chunks of 8 halves); B: 4 chunks/thread
    int aRow[4], aC[4], bRow[4], bDst[4], bC[4];
    #pragma unroll
    for (int i = 0; i < 4; i++) {
        int idx = i * 256 + t;
        aRow[i] = idx >> 3;  aC[i] = idx & 7;
        int k = idx >> 4, c = idx & 15;
        bRow[i] = k;  bC[i] = c;
        bDst[i] = k * 64 + ((c * 4) ^ ((k & 7) << 2));
    }
    int bC0 = (col0 >> 3);

    float acc[2][8][4];
    #pragma unroll
    for (int mf = 0; mf < 2; mf++)
        #pragma unroll
        for (int nf = 0; nf < 8; nf++)
            #pragma unroll
            for (int r = 0; r < 4; r++) acc[mf][nf][r] = 0.f;

    int nk = K / BK;
    auto issue = [&](int kt, int stg) {
        if (kt < nk) {
            int k0 = kt * BK;
            uint32_t aBase = stAddr[stg];
            uint32_t bBase = stAddr[stg] + AS_U32S * 4;
            #pragma unroll
            for (int i = 0; i < 4; i++) {
                cpa16(aBase + (aRow[i] * AS_U + aC[i] * 4) * 4,
                      Au + (size_t)(row0 + aRow[i]) * K8 + (k0 >> 3) + aC[i]);
                cpa16(bBase + bDst[i] * 4,
                      Bu + (size_t)(k0 + bRow[i]) * N8 + bC0 + bC[i]);
            }
        }
        cpa_commit();
    };

    issue(0, 0);
    issue(1, 1);

    int aLdsmRow = l & 15;
    int aLdsmCol = (l >> 4) << 2;

    for (int kt = 0; kt < nk; kt++) {
        cpa_wait<1>();
        __syncthreads();
        issue(kt + 2, (kt + 2) % NSTG);

        int cur = kt % NSTG;
        uint32_t asAddr = stAddr[cur];
        uint32_t bsAddr = stAddr[cur] + AS_U32S * 4;
        #pragma unroll
        for (int ks = 0; ks < 4; ks++) {
            uint32_t af[2][4];
            #pragma unroll
            for (int mf = 0; mf < 2; mf++) {
                int r = warpM * 32 + mf * 16;
                ldsm4(af[mf][0], af[mf][1], af[mf][2], af[mf][3],
                      asAddr + ((r + aLdsmRow) * AS_U + ks * 8 + aLdsmCol) * 4);
            }
            #pragma unroll
            for (int nfp = 0; nfp < 4; nfp++) {
                int krow = ks * 16 + (l & 15);
                int col = warpN * 32 + nfp * 8 + ((l >> 4) << 2);
                col ^= (krow & 7) << 2;
                uint32_t b0, b1, b2, b3;
                ldsm4t(b0, b1, b2, b3, bsAddr + (krow * 64 + col) * 4);
                #pragma unroll
                for (int mf = 0; mf < 2; mf++) {
                    mma_f16(acc[mf][2*nfp],   af[mf][0], af[mf][1], af[mf][2], af[mf][3], b0, b1);
                    mma_f16(acc[mf][2*nfp+1], af[mf][0], af[mf][1], af[mf][2], af[mf][3], b2, b3);
                }
            }
        }
    }

    if (mode == 0) {
        // ---- fused clip + RoPE + head-major scatter ----
        int gcol = col0 + warpN * 64;
        int isV = (gcol >= Dd + KVHh * HDd);
        int isK = (gcol >= Dd) && !isV;
        int headIdx;
        if (isV)      headIdx = (gcol - Dd - KVHh * HDd) >> 6;
        else if (isK) headIdx = (gcol - Dd) >> 6;
        else          headIdx = gcol >> 6;
        #pragma unroll
        for (int mf = 0; mf < 2; mf++) {
            #pragma unroll
            for (int half = 0; half < 2; half++) {
                int row = row0 + warpM * 32 + mf * 16 + lr + half * 8;
                int s_ = row & (Ss - 1), b_ = row >> 11;
                __half* dst;
                if (isV)
                    dst = g_v + ((size_t)(b_ * KVHh + headIdx) * Ss + s_) * HDd;
                else if (isK)
                    dst = g_k + ((size_t)(b_ * KVHh + headIdx) * Ss + s_) * HDd;
                else
                    dst = g_q + ((size_t)(b_ * Hh + headIdx) * Ss + s_) * HDd;
                const float* cosb = g_cos + ((size_t)b_ << 16) + (s_ << 5);
                const float* sinb = g_sin + ((size_t)b_ << 16) + (s_ << 5);
                #pragma unroll
                for (int nf = 0; nf < 4; nf++) {
                    int c0 = nf * 8 + 2 * lc;
                    float x1a = clip8(acc[mf][nf][half * 2 + 0]);
                    float x1b = clip8(acc[mf][nf][half * 2 + 1]);
                    float x2a = clip8(acc[mf][nf + 4][half * 2 + 0]);
                    float x2b = clip8(acc[mf][nf + 4][half * 2 + 1]);
                    if (isV) {
                        *(uint32_t*)(dst + c0)      = pkh2(x1a, x1b);
                        *(uint32_t*)(dst + c0 + 32) = pkh2(x2a, x2b);
                    } else {
                        float ca = cosb[c0], cb = cosb[c0 + 1];
                        float sa = sinb[c0], sb = sinb[c0 + 1];
                        *(uint32_t*)(dst + c0) =
                            pkh2(x1a * ca - x2a * sa, x1b * cb - x2b * sb);
                        *(uint32_t*)(dst + c0 + 32) =
                            pkh2(x2a * ca + x1a * sa, x2b * cb + x1b * sb);
                    }
                }
            }
        }
    } else {
        #pragma unroll
        for (int mf = 0; mf < 2; mf++) {
            #pragma unroll
            for (int half = 0; half < 2; half++) {
                int row = row0 + warpM * 32 + mf * 16 + lr + half * 8;
                #pragma unroll
                for (int nf = 0; nf < 8; nf++) {
                    int col = col0 + warpN * 64 + nf * 8 + 2 * lc;
                    size_t off = (size_t)row * N + col;
                    float2 rv = *(const float2*)(resid + off);
                    float2 v;
                    v.x = acc[mf][nf][half * 2 + 0] + rv.x;
                    v.y = acc[mf][nf][half * 2 + 1] + rv.y;
                    *(float2*)((float*)Cp + off) = v;
                }
            }
        }
    }
}

// ---------------- RoPE tables --------------------------------------------------
__global__ void invf_kernel()
{
    int i = threadIdx.x;
    if (i < 32)
        g_invf[i] = exp(-((double)(2 * i) / 64.0) * log(500000.0));
}

__global__ void rope_table_kernel(const int* __restrict__ pid)
{
    int idx = blockIdx.x * 256 + threadIdx.x;
    if (idx >= Bb * Ss * 32) return;
    int i = idx & 31;
    int s = (idx >> 5) & (Ss - 1);
    int b = idx >> 16;
    double pos = (double)pid[b * Ss + s];
    double ang = pos * g_invf[i];
    double k = rint(ang * 0.15915494309189535);
    float r = (float)(ang - k * 6.283185307179586);
    g_cos[idx] = cosf(r);
    g_sin[idx] = sinf(r);
}

// ---------------- FP16 flash attention, 3-stage cp.async ----------------------
#define QP_U 36
#define KS_U 36
#define VS_U 32
#define NAS  3
#define SM_PS 0
#define SM_KS (128 * QP_U)
#define SM_VS (SM_KS + NAS * 64 * KS_U)
#define SM_MASK (SM_VS + NAS * 64 * VS_U)
#define ATT_U32 (SM_MASK + NAS * 64)
__global__ __launch_bounds__(256, 2) void attn_kernel(const int* __restrict__ amask)
{
    extern __shared__ uint32_t smu[];
    uint32_t* Ps = smu + SM_PS;
    int* maskS = (int*)(smu + SM_MASK);

    int qt = (gridDim.x - 1) - blockIdx.x;
    int h = blockIdx.y, b = blockIdx.z;
    int kvh = h >> 2;
    int q0 = qt * 128;
    int t = threadIdx.x;
    int w = t >> 5, l = t & 31;
    int lr = l >> 2, lc = l & 3;

    const uint4* Qg = (const uint4*)(g_q + ((size_t)(b * Hh + h) * Ss + q0) * HDd);
    const uint4* Kg = (const uint4*)(g_k + (size_t)(b * KVHh + kvh) * Ss * HDd);
    const uint4* Vg = (const uint4*)(g_v + (size_t)(b * KVHh + kvh) * Ss * HDd);
    const int*   Mg = amask + b * Ss;

    uint32_t ksAddr0 = (uint32_t)__cvta_generic_to_shared(smu + SM_KS);
    uint32_t vsAddr0 = (uint32_t)__cvta_generic_to_shared(smu + SM_VS);
    uint32_t mkAddr0 = (uint32_t)__cvta_generic_to_shared(maskS);

    int nkt = 2 * qt + 2;
    auto issueKV = [&](int kt, int stg) {
        if (kt < nkt) {
            int k0 = kt * 64;
            uint32_t kBase = ksAddr0 + stg * 64 * KS_U * 4;
            uint32_t vBase = vsAddr0 + stg * 64 * VS_U * 4;
            #pragma unroll
            for (int i = 0; i < 2; i++) {
                int idx = i * 256 + t;
                int row = idx >> 3, c = idx & 7;
                cpa16(kBase + (row * KS_U + c * 4) * 4, Kg + (k0 + row) * 8 + c);
                cpa16(vBase + (row * VS_U + ((c * 4) ^ ((row & 7) << 2))) * 4,
                      Vg + (k0 + row) * 8 + c);
            }
            if (t < 64) cpa4(mkAddr0 + (stg * 64 + t) * 4, Mg + k0 + t);
        }
        cpa_commit();
    };

    issueKV(0, 0);
    issueKV(1, 1);

    #pragma unroll
    for (int i = 0; i < 4; i++) {
        int idx = i * 256 + t;
        int row = idx >> 3, c = idx & 7;
        *(uint4*)&Ps[row * QP_U + c * 4] = Qg[row * 8 + c];
    }
    __syncthreads();
    uint32_t qa[4][4];
    {
        int r0 = w * 16 + lr;
        #pragma unroll
        for (int ks = 0; ks < 4; ks++) {
            qa[ks][0] = Ps[r0 * QP_U + ks * 8 + lc];
            qa[ks][1] = Ps[(r0 + 8) * QP_U + ks * 8 + lc];
            qa[ks][2] = Ps[r0 * QP_U + ks * 8 + lc + 4];
            qa[ks][3] = Ps[(r0 + 8) * QP_U + ks * 8 + lc + 4];
        }
    }

    float m0 = -1e30f, m1 = -1e30f, l0 = 0.f, l1 = 0.f;
    float o[8][4];
    #pragma unroll
    for (int nf = 0; nf < 8; nf++)
        #pragma unroll
        for (int r = 0; r < 4; r++) o[nf][r] = 0.f;

    int kLdsmRow = l & 15;
    int kLdsmCol = (l >> 4) << 2;

    for (int kt = 0; kt < nkt; kt++) {
        cpa_wait<1>();
        __syncthreads();
        issueKV(kt + 2, (kt + 2) % NAS);

        int cur = kt % NAS;
        int k0 = kt * 64;
        int qlow = q0 + w * 16;
        bool active = (k0 <= qlow + 15);
        if (active) {
            float s[8][4];
            #pragma unroll
            for (int nf = 0; nf < 8; nf++)
                #pragma unroll
                for (int r = 0; r < 4; r++) s[nf][r] = 0.f;
            uint32_t kbAddr = ksAddr0 + cur * 64 * KS_U * 4;
            #pragma unroll
            for (int ks = 0; ks < 4; ks++) {
                #pragma unroll
                for (int p = 0; p < 4; p++) {
                    uint32_t b0, b1, b2, b3;
                    ldsm4(b0, b1, b2, b3,
                          kbAddr + ((p * 16 + kLdsmRow) * KS_U + ks * 8 + kLdsmCol) * 4);
                    mma_f16(s[2*p],   qa[ks][0], qa[ks][1], qa[ks][2], qa[ks][3], b0, b2);
                    mma_f16(s[2*p+1], qa[ks][0], qa[ks][1], qa[ks][2], qa[ks][3], b1, b3);
                }
            }
            int qr0 = qlow + lr, qr1 = qr0 + 8;
            bool fullvis = (k0 + 63 <= qlow);
            #pragma unroll
            for (int nf = 0; nf < 8; nf++) {
                int kg0 = k0 + nf * 8 + 2 * lc;
                int ms0 = maskS[(cur << 6) + nf * 8 + 2 * lc];
                int ms1 = maskS[(cur << 6) + nf * 8 + 2 * lc + 1];
                s[nf][0] = (ms0 && (fullvis || kg0     <= qr0)) ? s[nf][0] * ATT_SCALE : -1e30f;
                s[nf][1] = (ms1 && (fullvis || kg0 + 1 <= qr0)) ? s[nf][1] * ATT_SCALE : -1e30f;
                s[nf][2] = (ms0 && (fullvis || kg0     <= qr1)) ? s[nf][2] * ATT_SCALE : -1e30f;
                s[nf][3] = (ms1 && (fullvis || kg0 + 1 <= qr1)) ? s[nf][3] * ATT_SCALE : -1e30f;
            }
            float mt0 = -1e30f, mt1 = -1e30f;
            #pragma unroll
            for (int nf = 0; nf < 8; nf++) {
                mt0 = fmaxf(mt0, fmaxf(s[nf][0], s[nf][1]));
                mt1 = fmaxf(mt1, fmaxf(s[nf][2], s[nf][3]));
            }
            mt0 = fmaxf(mt0, __shfl_xor_sync(0xffffffffu, mt0, 1));
            mt0 = fmaxf(mt0, __shfl_xor_sync(0xffffffffu, mt0, 2));
            mt1 = fmaxf(mt1, __shfl_xor_sync(0xffffffffu, mt1, 1));
            mt1 = fmaxf(mt1, __shfl_xor_sync(0xffffffffu, mt1, 2));
            float mn0 = fmaxf(m0, mt0), mn1 = fmaxf(m1, mt1);
            float rs0 = 0.f, rs1 = 0.f;
            #pragma unroll
            for (int nf = 0; nf < 8; nf++) {
                s[nf][0] = __expf(s[nf][0] - mn0);
                s[nf][1] = __expf(s[nf][1] - mn0);
                s[nf][2] = __expf(s[nf][2] - mn1);
                s[nf][3] = __expf(s[nf][3] - mn1);
                rs0 += s[nf][0] + s[nf][1];
                rs1 += s[nf][2] + s[nf][3];
            }
            rs0 += __shfl_xor_sync(0xffffffffu, rs0, 1);
            rs0 += __shfl_xor_sync(0xffffffffu, rs0, 2);
            rs1 += __shfl_xor_sync(0xffffffffu, rs1, 1);
            rs1 += __shfl_xor_sync(0xffffffffu, rs1, 2);
            float a0 = __expf(m0 - mn0), a1 = __expf(m1 - mn1);
            l0 = l0 * a0 + rs0;  l1 = l1 * a1 + rs1;
            m0 = mn0;  m1 = mn1;
            #pragma unroll
            for (int nf = 0; nf < 8; nf++) {
                o[nf][0] *= a0; o[nf][1] *= a0;
                o[nf][2] *= a1; o[nf][3] *= a1;
            }
            {
                uint32_t vsAddr = vsAddr0 + cur * 64 * VS_U * 4;
                #pragma unroll
                for (int ks = 0; ks < 4; ks++) {
                    uint32_t pa0 = pkh2(s[2*ks][0],   s[2*ks][1]);
                    uint32_t pa1 = pkh2(s[2*ks][2],   s[2*ks][3]);
                    uint32_t pa2 = pkh2(s[2*ks+1][0], s[2*ks+1][1]);
                    uint32_t pa3 = pkh2(s[2*ks+1][2], s[2*ks+1][3]);
                    #pragma unroll
                    for (int nfp = 0; nfp < 4; nfp++) {
                        int key = ks * 16 + (l & 15);
                        int col = nfp * 8 + ((l >> 4) << 2);
                        col ^= (key & 7) << 2;
                        uint32_t b0, b1, b2, b3;
                        ldsm4t(b0, b1, b2, b3, vsAddr + (key * VS_U + col) * 4);
                        mma_f16(o[2*nfp],   pa0, pa1, pa2, pa3, b0, b1);
                        mma_f16(o[2*nfp+1], pa0, pa1, pa2, pa3, b2, b3);
                    }
                }
            }
        }
    }

    float il0 = (l0 > 0.f) ? (1.f / l0) : 0.f;
    float il1 = (l1 > 0.f) ? (1.f / l1) : 0.f;
    int qr0 = q0 + w * 16 + lr;
    __half* d0 = g_attn + (size_t)(b * Ss + qr0) * Dd + h * HDd;
    __half* d1 = g_attn + (size_t)(b * Ss + qr0 + 8) * Dd + h * HDd;
    #pragma unroll
    for (int nf = 0; nf < 8; nf++) {
        int c = nf * 8 + 2 * lc;
        *(uint32_t*)(d0 + c) = pkh2(o[nf][0] * il0, o[nf][1] * il0);
        *(uint32_t*)(d1 + c) = pkh2(o[nf][2] * il1, o[nf][3] * il1);
    }
}

// ---------------- launch ------------------------------------------------------
extern "C" void kernel_launch(void* const* d_in, const int* in_sizes, int n_in,
                              void* d_out, int out_size)
{
    const float* hs   = (const float*)d_in[0];
    const int*   am   = (const int*)  d_in[1];
    const int*   pid  = (const int*)  d_in[2];
    const float* ln1  = (const float*)d_in[4];
    const float* wqkv = (const float*)d_in[5];
    const float* wout = (const float*)d_in[6];
    const float* ln2  = (const float*)d_in[7];
    float* out = (float*)d_out;

    __half *px, *pattn, *pwq, *pwo;
    cudaGetSymbolAddress((void**)&px,    g_x);
    cudaGetSymbolAddress((void**)&pattn, g_attn);
    cudaGetSymbolAddress((void**)&pwq,   g_wqkvh);
    cudaGetSymbolAddress((void**)&pwo,   g_wouth);

    const int ATTN_SMEM = ATT_U32 * 4;
    cudaFuncSetAttribute(attn_kernel,
                         cudaFuncAttributeMaxDynamicSharedMemorySize, ATTN_SMEM);
    const int GEMM_SMEM = NSTG * STAGE_U * 4;   // 104448 B
    cudaFuncSetAttribute(gemm_f16_kernel,
                         cudaFuncAttributeMaxDynamicSharedMemorySize, GEMM_SMEM);

    int n1 = Dd * QKVN / 4, n2 = Dd * Dd / 4;
    cvt2_kernel<<<(n1 + n2 + 255) / 256, 256>>>(wqkv, pwq, n1, wout, pwo, n2);
    invf_kernel<<<1, 32>>>();
    ln_kernel<<<Mrows, 256>>>(hs, ln1, px, 1);
    rope_table_kernel<<<(Bb * Ss * 32) / 256, 256>>>(pid);
    gemm_f16_kernel<<<dim3(QKVN / BN, Mrows / BM), 256, GEMM_SMEM>>>(
        px, pwq, nullptr, Mrows, QKVN, Dd, 0, nullptr);
    attn_kernel<<<dim3(Ss / 128, Hh, Bb), 256, ATTN_SMEM>>>(am);
    gemm_f16_kernel<<<dim3(Dd / BN, Mrows / BM), 256, GEMM_SMEM>>>(
        pattn, pwo, out, Mrows, Dd, Dd, 1, hs);
    ln_kernel<<<Mrows, 256>>>(out, ln2, out + OUTOFF, 0);
}

// round 11
// speedup vs baseline: 15.2811x; 1.0043x over previous
#include <cuda_runtime.h>
#include <cuda_fp16.h>
#include <math.h>
#include <stdint.h>

#define Bb    2
#define Ss    2048
#define Dd    2048
#define Hh    32
#define KVHh  8
#define HDd   64
#define QKVN  3072
#define Mrows (Bb*Ss)
#define OUTOFF ((size_t)Bb*Ss*Dd)
#define ATT_SCALE 0.125f

// ---------------- scratch ----------------------------------------------------
__device__ __half g_x[(size_t)Mrows*Dd];
__device__ __half g_q[(size_t)Bb*Hh*Ss*HDd];
__device__ __half g_k[(size_t)Bb*KVHh*Ss*HDd];
__device__ __half g_v[(size_t)Bb*KVHh*Ss*HDd];
__device__ __half g_attn[(size_t)Mrows*Dd];
__device__ __half g_wqkvh[(size_t)Dd*QKVN];
__device__ __half g_wouth[(size_t)Dd*Dd];
__device__ float g_cos[(size_t)Bb*Ss*32];
__device__ float g_sin[(size_t)Bb*Ss*32];
__device__ double g_invf[32];

__device__ __forceinline__ uint32_t pkh2(float x, float y) {
    __half2 h = __floats2half2_rn(x, y);
    return *(uint32_t*)&h;
}
__device__ __forceinline__ void mma_f16(float c[4], uint32_t a0, uint32_t a1,
                                        uint32_t a2, uint32_t a3,
                                        uint32_t b0, uint32_t b1)
{
    asm volatile(
        "mma.sync.aligned.m16n8k16.row.col.f32.f16.f16.f32 "
        "{%0,%1,%2,%3}, {%4,%5,%6,%7}, {%8,%9}, {%0,%1,%2,%3};"
        : "+f"(c[0]), "+f"(c[1]), "+f"(c[2]), "+f"(c[3])
        : "r"(a0), "r"(a1), "r"(a2), "r"(a3), "r"(b0), "r"(b1));
}
__device__ __forceinline__ void ldsm4(uint32_t& r0, uint32_t& r1,
                                      uint32_t& r2, uint32_t& r3, uint32_t saddr)
{
    asm volatile(
        "ldmatrix.sync.aligned.m8n8.x4.shared.b16 {%0,%1,%2,%3}, [%4];"
        : "=r"(r0), "=r"(r1), "=r"(r2), "=r"(r3) : "r"(saddr));
}
__device__ __forceinline__ void ldsm4t(uint32_t& r0, uint32_t& r1,
                                       uint32_t& r2, uint32_t& r3, uint32_t saddr)
{
    asm volatile(
        "ldmatrix.sync.aligned.m8n8.x4.trans.shared.b16 {%0,%1,%2,%3}, [%4];"
        : "=r"(r0), "=r"(r1), "=r"(r2), "=r"(r3) : "r"(saddr));
}
__device__ __forceinline__ void cpa16(uint32_t smem_addr, const void* gptr) {
    asm volatile("cp.async.cg.shared.global [%0], [%1], 16;"
                 :: "r"(smem_addr), "l"(gptr));
}
__device__ __forceinline__ void cpa4(uint32_t smem_addr, const void* gptr) {
    asm volatile("cp.async.ca.shared.global [%0], [%1], 4;"
                 :: "r"(smem_addr), "l"(gptr));
}
__device__ __forceinline__ void cpa_commit() {
    asm volatile("cp.async.commit_group;");
}
template<int N>
__device__ __forceinline__ void cpa_wait() {
    asm volatile("cp.async.wait_group %0;" :: "n"(N));
}
__device__ __forceinline__ float clip8(float v) {
    return fminf(fmaxf(v, -8.f), 8.f);
}

// ---------------- weight fp32 -> fp16 -----------------------------------------
__global__ void cvt2_kernel(const float* __restrict__ w1, __half* __restrict__ o1,
                            int n1, const float* __restrict__ w2,
                            __half* __restrict__ o2, int n2)
{
    int i = blockIdx.x * 256 + threadIdx.x;
    const float* src; __half* dst;
    if (i < n1) { src = w1 + (size_t)i * 4; dst = o1 + (size_t)i * 4; }
    else {
        i -= n1;
        if (i >= n2) return;
        src = w2 + (size_t)i * 4; dst = o2 + (size_t)i * 4;
    }
    float4 v = *(const float4*)src;
    uint32_t* d = (uint32_t*)dst;
    d[0] = pkh2(v.x, v.y);
    d[1] = pkh2(v.z, v.w);
}

// ---------------- LayerNorm ---------------------------------------------------
__global__ __launch_bounds__(256) void ln_kernel(
    const float* __restrict__ in, const float* __restrict__ sc,
    void* __restrict__ outp, int half_out)
{
    int row = blockIdx.x;
    const float* x = in + (size_t)row * Dd;
    float s = 0.f, s2 = 0.f;
    for (int i = threadIdx.x; i < Dd; i += 256) { float v = x[i]; s += v; s2 += v*v; }
    #pragma unroll
    for (int o = 16; o; o >>= 1) {
        s  += __shfl_xor_sync(0xffffffffu, s,  o);
        s2 += __shfl_xor_sync(0xffffffffu, s2, o);
    }
    __shared__ float ws[8], ws2[8];
    int w = threadIdx.x >> 5, l = threadIdx.x & 31;
    if (l == 0) { ws[w] = s; ws2[w] = s2; }
    __syncthreads();
    if (threadIdx.x < 32) {
        s  = (l < 8) ? ws[l]  : 0.f;
        s2 = (l < 8) ? ws2[l] : 0.f;
        #pragma unroll
        for (int o = 4; o; o >>= 1) {
            s  += __shfl_xor_sync(0xffffffffu, s,  o);
            s2 += __shfl_xor_sync(0xffffffffu, s2, o);
        }
        if (l == 0) { ws[0] = s; ws2[0] = s2; }
    }
    __syncthreads();
    float mean = ws[0] * (1.f / Dd);
    float var  = ws2[0] * (1.f / Dd) - mean * mean;
    float inv  = rsqrtf(var + 1e-6f);
    if (half_out) {
        __half* o_ = (__half*)outp + (size_t)row * Dd;
        for (int i = threadIdx.x * 2; i < Dd; i += 512) {
            float a = (x[i] - mean) * inv * sc[i];
            float b = (x[i+1] - mean) * inv * sc[i+1];
            *(uint32_t*)(o_ + i) = pkh2(a, b);
        }
    } else {
        float* o_ = (float*)outp + (size_t)row * Dd;
        for (int i = threadIdx.x; i < Dd; i += 256)
            o_[i] = (x[i] - mean) * inv * sc[i];
    }
}

// ---------------- FP16 GEMM 128x128x64, 3-stage cp.async ----------------------
#define BM 128
#define BN 128
#define BK 64
#define AS_U 36
#define AS_U32S (BM * AS_U)
#define BS_U32S (BK * 64)
#define STAGE_U (AS_U32S + BS_U32S)
#define NSTG 3

__global__ __launch_bounds__(256, 2) void gemm_f16_kernel(
    const __half* __restrict__ A, const __half* __restrict__ Bw,
    void* __restrict__ Cp, int M, int N, int K, int mode,
    const float* __restrict__ resid)
{
    extern __shared__ uint32_t smu[];
    int row0 = blockIdx.y * BM, col0 = blockIdx.x * BN;
    int t = threadIdx.x;
    int w = t >> 5, l = t & 31;
    int warpM = w >> 1, warpN = w & 1;
    int lr = l >> 2, lc = l & 3;

    const uint4* Au = (const uint4*)A;
    const uint4* Bu = (const uint4*)Bw;
    int K8 = K >> 3, N8 = N >> 3;

    uint32_t stAddr[NSTG];
    #pragma unroll
    for (int sidx = 0; sidx < NSTG; sidx++)
        stAddr[sidx] = (uint32_t)__cvta_generic_to_shared(smu + sidx * STAGE_U);

    int aRow[4], aC[4], bRow[4], bDst[4], bC[4];
    #pragma unroll
    for (int i = 0; i < 4; i++) {
        int idx = i * 256 + t;
        aRow[i] = idx >> 3;  aC[i] = idx & 7;
        int k = idx >> 4, c = idx & 15;
        bRow[i] = k;  bC[i] = c;
        bDst[i] = k * 64 + ((c * 4) ^ ((k & 7) << 2));
    }
    int bC0 = (col0 >> 3);

    float acc[2][8][4];
    #pragma unroll
    for (int mf = 0; mf < 2; mf++)
        #pragma unroll
        for (int nf = 0; nf < 8; nf++)
            #pragma unroll
            for (int r = 0; r < 4; r++) acc[mf][nf][r] = 0.f;

    int nk = K / BK;
    auto issue = [&](int kt, int stg) {
        if (kt < nk) {
            int k0 = kt * BK;
            uint32_t aBase = stAddr[stg];
            uint32_t bBase = stAddr[stg] + AS_U32S * 4;
            #pragma unroll
            for (int i = 0; i < 4; i++) {
                cpa16(aBase + (aRow[i] * AS_U + aC[i] * 4) * 4,
                      Au + (size_t)(row0 + aRow[i]) * K8 + (k0 >> 3) + aC[i]);
                cpa16(bBase + bDst[i] * 4,
                      Bu + (size_t)(k0 + bRow[i]) * N8 + bC0 + bC[i]);
            }
        }
        cpa_commit();
    };

    issue(0, 0);
    issue(1, 1);

    int aLdsmRow = l & 15;
    int aLdsmCol = (l >> 4) << 2;

    for (int kt = 0; kt < nk; kt++) {
        cpa_wait<1>();
        __syncthreads();
        issue(kt + 2, (kt + 2) % NSTG);

        int cur = kt % NSTG;
        uint32_t asAddr = stAddr[cur];
        uint32_t bsAddr = stAddr[cur] + AS_U32S * 4;
        #pragma unroll
        for (int ks = 0; ks < 4; ks++) {
            uint32_t af[2][4];
            #pragma unroll
            for (int mf = 0; mf < 2; mf++) {
                int r = warpM * 32 + mf * 16;
                ldsm4(af[mf][0], af[mf][1], af[mf][2], af[mf][3],
                      asAddr + ((r + aLdsmRow) * AS_U + ks * 8 + aLdsmCol) * 4);
            }
            #pragma unroll
            for (int nfp = 0; nfp < 4; nfp++) {
                int krow = ks * 16 + (l & 15);
                int col = warpN * 32 + nfp * 8 + ((l >> 4) << 2);
                col ^= (krow & 7) << 2;
                uint32_t b0, b1, b2, b3;
                ldsm4t(b0, b1, b2, b3, bsAddr + (krow * 64 + col) * 4);
                #pragma unroll
                for (int mf = 0; mf < 2; mf++) {
                    mma_f16(acc[mf][2*nfp],   af[mf][0], af[mf][1], af[mf][2], af[mf][3], b0, b1);
                    mma_f16(acc[mf][2*nfp+1], af[mf][0], af[mf][1], af[mf][2], af[mf][3], b2, b3);
                }
            }
        }
    }

    if (mode == 0) {
        int gcol = col0 + warpN * 64;
        int isV = (gcol >= Dd + KVHh * HDd);
        int isK = (gcol >= Dd) && !isV;
        int headIdx;
        if (isV)      headIdx = (gcol - Dd - KVHh * HDd) >> 6;
        else if (isK) headIdx = (gcol - Dd) >> 6;
        else          headIdx = gcol >> 6;
        #pragma unroll
        for (int mf = 0; mf < 2; mf++) {
            #pragma unroll
            for (int half = 0; half < 2; half++) {
                int row = row0 + warpM * 32 + mf * 16 + lr + half * 8;
                int s_ = row & (Ss - 1), b_ = row >> 11;
                __half* dst;
                if (isV)
                    dst = g_v + ((size_t)(b_ * KVHh + headIdx) * Ss + s_) * HDd;
                else if (isK)
                    dst = g_k + ((size_t)(b_ * KVHh + headIdx) * Ss + s_) * HDd;
                else
                    dst = g_q + ((size_t)(b_ * Hh + headIdx) * Ss + s_) * HDd;
                const float* cosb = g_cos + ((size_t)b_ << 16) + (s_ << 5);
                const float* sinb = g_sin + ((size_t)b_ << 16) + (s_ << 5);
                #pragma unroll
                for (int nf = 0; nf < 4; nf++) {
                    int c0 = nf * 8 + 2 * lc;
                    float x1a = clip8(acc[mf][nf][half * 2 + 0]);
                    float x1b = clip8(acc[mf][nf][half * 2 + 1]);
                    float x2a = clip8(acc[mf][nf + 4][half * 2 + 0]);
                    float x2b = clip8(acc[mf][nf + 4][half * 2 + 1]);
                    if (isV) {
                        *(uint32_t*)(dst + c0)      = pkh2(x1a, x1b);
                        *(uint32_t*)(dst + c0 + 32) = pkh2(x2a, x2b);
                    } else {
                        float ca = cosb[c0], cb = cosb[c0 + 1];
                        float sa = sinb[c0], sb = sinb[c0 + 1];
                        *(uint32_t*)(dst + c0) =
                            pkh2(x1a * ca - x2a * sa, x1b * cb - x2b * sb);
                        *(uint32_t*)(dst + c0 + 32) =
                            pkh2(x2a * ca + x1a * sa, x2b * cb + x1b * sb);
                    }
                }
            }
        }
    } else {
        #pragma unroll
        for (int mf = 0; mf < 2; mf++) {
            #pragma unroll
            for (int half = 0; half < 2; half++) {
                int row = row0 + warpM * 32 + mf * 16 + lr + half * 8;
                #pragma unroll
                for (int nf = 0; nf < 8; nf++) {
                    int col = col0 + warpN * 64 + nf * 8 + 2 * lc;
                    size_t off = (size_t)row * N + col;
                    float2 rv = *(const float2*)(resid + off);
                    float2 v;
                    v.x = acc[mf][nf][half * 2 + 0] + rv.x;
                    v.y = acc[mf][nf][half * 2 + 1] + rv.y;
                    *(float2*)((float*)Cp + off) = v;
                }
            }
        }
    }
}

// ---------------- RoPE tables --------------------------------------------------
__global__ void invf_kernel()
{
    int i = threadIdx.x;
    if (i < 32)
        g_invf[i] = exp(-((double)(2 * i) / 64.0) * log(500000.0));
}

__global__ void rope_table_kernel(const int* __restrict__ pid)
{
    int idx = blockIdx.x * 256 + threadIdx.x;
    if (idx >= Bb * Ss * 32) return;
    int i = idx & 31;
    int s = (idx >> 5) & (Ss - 1);
    int b = idx >> 16;
    double pos = (double)pid[b * Ss + s];
    double ang = pos * g_invf[i];
    double k = rint(ang * 0.15915494309189535);
    float r = (float)(ang - k * 6.283185307179586);
    g_cos[idx] = cosf(r);
    g_sin[idx] = sinf(r);
}

// ---------------- FP16 flash attention, 128-key macro-tiles, 3 stages ----------
#define KS_U 36
#define VS_U 32
#define NAS  3
#define KT_ROWS 128
#define SM_KS 0
#define SM_VS (NAS * KT_ROWS * KS_U)                 // 13824
#define SM_MASK (SM_VS + NAS * KT_ROWS * VS_U)       // + 12288
#define ATT_U32 (SM_MASK + NAS * KT_ROWS)            // + 384 -> 26496 u32
#define QP_U 36   // Q staging stride; aliases K stage 0 (4608 <= 4608)
__global__ __launch_bounds__(256, 2) void attn_kernel(const int* __restrict__ amask)
{
    extern __shared__ uint32_t smu[];
    uint32_t* Ps = smu;                       // aliases K stage 0 (pre-pipeline)
    int* maskS = (int*)(smu + SM_MASK);

    int qt = (gridDim.x - 1) - blockIdx.x;
    int h = blockIdx.y, b = blockIdx.z;
    int kvh = h >> 2;
    int q0 = qt * 128;
    int t = threadIdx.x;
    int w = t >> 5, l = t & 31;
    int lr = l >> 2, lc = l & 3;

    const uint4* Qg = (const uint4*)(g_q + ((size_t)(b * Hh + h) * Ss + q0) * HDd);
    const uint4* Kg = (const uint4*)(g_k + (size_t)(b * KVHh + kvh) * Ss * HDd);
    const uint4* Vg = (const uint4*)(g_v + (size_t)(b * KVHh + kvh) * Ss * HDd);
    const int*   Mg = amask + b * Ss;

    uint32_t ksAddr0 = (uint32_t)__cvta_generic_to_shared(smu + SM_KS);
    uint32_t vsAddr0 = (uint32_t)__cvta_generic_to_shared(smu + SM_VS);
    uint32_t mkAddr0 = (uint32_t)__cvta_generic_to_shared(maskS);

    // ---- stage Q (into K-stage-0 alias) + extract frags BEFORE pipeline ----
    #pragma unroll
    for (int i = 0; i < 4; i++) {
        int idx = i * 256 + t;
        int row = idx >> 3, c = idx & 7;
        *(uint4*)&Ps[row * QP_U + c * 4] = Qg[row * 8 + c];
    }
    __syncthreads();
    uint32_t qa[4][4];
    {
        int r0 = w * 16 + lr;
        #pragma unroll
        for (int ks = 0; ks < 4; ks++) {
            qa[ks][0] = Ps[r0 * QP_U + ks * 8 + lc];
            qa[ks][1] = Ps[(r0 + 8) * QP_U + ks * 8 + lc];
            qa[ks][2] = Ps[r0 * QP_U + ks * 8 + lc + 4];
            qa[ks][3] = Ps[(r0 + 8) * QP_U + ks * 8 + lc + 4];
        }
    }
    __syncthreads();   // Q reads done; K stage 0 region free for cp.async

    int nkt = qt + 1;  // 128-key macro tiles
    auto issueKV = [&](int kt, int stg) {
        if (kt < nkt) {
            int k0 = kt * KT_ROWS;
            uint32_t kBase = ksAddr0 + stg * KT_ROWS * KS_U * 4;
            uint32_t vBase = vsAddr0 + stg * KT_ROWS * VS_U * 4;
            #pragma unroll
            for (int i = 0; i < 4; i++) {
                int idx = i * 256 + t;            // 1024 chunks of 8 halves
                int row = idx >> 3, c = idx & 7;
                cpa16(kBase + (row * KS_U + c * 4) * 4, Kg + (k0 + row) * 8 + c);
                cpa16(vBase + (row * VS_U + ((c * 4) ^ ((row & 7) << 2))) * 4,
                      Vg + (k0 + row) * 8 + c);
            }
            if (t < KT_ROWS) cpa4(mkAddr0 + (stg * KT_ROWS + t) * 4, Mg + k0 + t);
        }
        cpa_commit();
    };

    issueKV(0, 0);
    issueKV(1, 1);

    float m0 = -1e30f, m1 = -1e30f, l0 = 0.f, l1 = 0.f;
    float o[8][4];
    #pragma unroll
    for (int nf = 0; nf < 8; nf++)
        #pragma unroll
        for (int r = 0; r < 4; r++) o[nf][r] = 0.f;

    int kLdsmRow = l & 15;
    int kLdsmCol = (l >> 4) << 2;
    int qlow = q0 + w * 16;

    for (int kt = 0; kt < nkt; kt++) {
        cpa_wait<1>();
        __syncthreads();
        issueKV(kt + 2, (kt + 2) % NAS);

        int cur = kt % NAS;
        uint32_t kbAddr = ksAddr0 + cur * KT_ROWS * KS_U * 4;
        uint32_t vsAddr = vsAddr0 + cur * KT_ROWS * VS_U * 4;

        #pragma unroll
        for (int half = 0; half < 2; half++) {
            int k0 = kt * KT_ROWS + half * 64;
            if (k0 > qlow + 15) break;
            int rbase = half * 64;
            // ---- S = Q K^T ----
            float s[8][4];
            #pragma unroll
            for (int nf = 0; nf < 8; nf++)
                #pragma unroll
                for (int r = 0; r < 4; r++) s[nf][r] = 0.f;
            #pragma unroll
            for (int ks = 0; ks < 4; ks++) {
                #pragma unroll
                for (int p = 0; p < 4; p++) {
                    uint32_t b0, b1, b2, b3;
                    ldsm4(b0, b1, b2, b3,
                          kbAddr + ((rbase + p * 16 + kLdsmRow) * KS_U
                                    + ks * 8 + kLdsmCol) * 4);
                    mma_f16(s[2*p],   qa[ks][0], qa[ks][1], qa[ks][2], qa[ks][3], b0, b2);
                    mma_f16(s[2*p+1], qa[ks][0], qa[ks][1], qa[ks][2], qa[ks][3], b1, b3);
                }
            }
            // ---- mask + scale ----
            int qr0 = qlow + lr, qr1 = qr0 + 8;
            bool fullvis = (k0 + 63 <= qlow);
            int mbase = cur * KT_ROWS + rbase;
            #pragma unroll
            for (int nf = 0; nf < 8; nf++) {
                int kg0 = k0 + nf * 8 + 2 * lc;
                int ms0 = maskS[mbase + nf * 8 + 2 * lc];
                int ms1 = maskS[mbase + nf * 8 + 2 * lc + 1];
                s[nf][0] = (ms0 && (fullvis || kg0     <= qr0)) ? s[nf][0] * ATT_SCALE : -1e30f;
                s[nf][1] = (ms1 && (fullvis || kg0 + 1 <= qr0)) ? s[nf][1] * ATT_SCALE : -1e30f;
                s[nf][2] = (ms0 && (fullvis || kg0     <= qr1)) ? s[nf][2] * ATT_SCALE : -1e30f;
                s[nf][3] = (ms1 && (fullvis || kg0 + 1 <= qr1)) ? s[nf][3] * ATT_SCALE : -1e30f;
            }
            // ---- online softmax ----
            float mt0 = -1e30f, mt1 = -1e30f;
            #pragma unroll
            for (int nf = 0; nf < 8; nf++) {
                mt0 = fmaxf(mt0, fmaxf(s[nf][0], s[nf][1]));
                mt1 = fmaxf(mt1, fmaxf(s[nf][2], s[nf][3]));
            }
            mt0 = fmaxf(mt0, __shfl_xor_sync(0xffffffffu, mt0, 1));
            mt0 = fmaxf(mt0, __shfl_xor_sync(0xffffffffu, mt0, 2));
            mt1 = fmaxf(mt1, __shfl_xor_sync(0xffffffffu, mt1, 1));
            mt1 = fmaxf(mt1, __shfl_xor_sync(0xffffffffu, mt1, 2));
            float mn0 = fmaxf(m0, mt0), mn1 = fmaxf(m1, mt1);
            float rs0 = 0.f, rs1 = 0.f;
            #pragma unroll
            for (int nf = 0; nf < 8; nf++) {
                s[nf][0] = __expf(s[nf][0] - mn0);
                s[nf][1] = __expf(s[nf][1] - mn0);
                s[nf][2] = __expf(s[nf][2] - mn1);
                s[nf][3] = __expf(s[nf][3] - mn1);
                rs0 += s[nf][0] + s[nf][1];
                rs1 += s[nf][2] + s[nf][3];
            }
            rs0 += __shfl_xor_sync(0xffffffffu, rs0, 1);
            rs0 += __shfl_xor_sync(0xffffffffu, rs0, 2);
            rs1 += __shfl_xor_sync(0xffffffffu, rs1, 1);
            rs1 += __shfl_xor_sync(0xffffffffu, rs1, 2);
            float a0 = __expf(m0 - mn0), a1 = __expf(m1 - mn1);
            l0 = l0 * a0 + rs0;  l1 = l1 * a1 + rs1;
            m0 = mn0;  m1 = mn1;
            #pragma unroll
            for (int nf = 0; nf < 8; nf++) {
                o[nf][0] *= a0; o[nf][1] *= a0;
                o[nf][2] *= a1; o[nf][3] *= a1;
            }
            // ---- O += P V (P packed from S C-frags; V via ldmatrix.trans) ----
            #pragma unroll
            for (int ks = 0; ks < 4; ks++) {
                uint32_t pa0 = pkh2(s[2*ks][0],   s[2*ks][1]);
                uint32_t pa1 = pkh2(s[2*ks][2],   s[2*ks][3]);
                uint32_t pa2 = pkh2(s[2*ks+1][0], s[2*ks+1][1]);
                uint32_t pa3 = pkh2(s[2*ks+1][2], s[2*ks+1][3]);
                #pragma unroll
                for (int nfp = 0; nfp < 4; nfp++) {
                    int key = rbase + ks * 16 + (l & 15);
                    int col = nfp * 8 + ((l >> 4) << 2);
                    col ^= (key & 7) << 2;
                    uint32_t b0, b1, b2, b3;
                    ldsm4t(b0, b1, b2, b3, vsAddr + (key * VS_U + col) * 4);
                    mma_f16(o[2*nfp],   pa0, pa1, pa2, pa3, b0, b1);
                    mma_f16(o[2*nfp+1], pa0, pa1, pa2, pa3, b2, b3);
                }
            }
        }
    }

    float il0 = (l0 > 0.f) ? (1.f / l0) : 0.f;
    float il1 = (l1 > 0.f) ? (1.f / l1) : 0.f;
    int qr0 = q0 + w * 16 + lr;
    __half* d0 = g_attn + (size_t)(b * Ss + qr0) * Dd + h * HDd;
    __half* d1 = g_attn + (size_t)(b * Ss + qr0 + 8) * Dd + h * HDd;
    #pragma unroll
    for (int nf = 0; nf < 8; nf++) {
        int c = nf * 8 + 2 * lc;
        *(uint32_t*)(d0 + c) = pkh2(o[nf][0] * il0, o[nf][1] * il0);
        *(uint32_t*)(d1 + c) = pkh2(o[nf][2] * il1, o[nf][3] * il1);
    }
}

// ---------------- launch ------------------------------------------------------
extern "C" void kernel_launch(void* const* d_in, const int* in_sizes, int n_in,
                              void* d_out, int out_size)
{
    const float* hs   = (const float*)d_in[0];
    const int*   am   = (const int*)  d_in[1];
    const int*   pid  = (const int*)  d_in[2];
    const float* ln1  = (const float*)d_in[4];
    const float* wqkv = (const float*)d_in[5];
    const float* wout = (const float*)d_in[6];
    const float* ln2  = (const float*)d_in[7];
    float* out = (float*)d_out;

    __half *px, *pattn, *pwq, *pwo;
    cudaGetSymbolAddress((void**)&px,    g_x);
    cudaGetSymbolAddress((void**)&pattn, g_attn);
    cudaGetSymbolAddress((void**)&pwq,   g_wqkvh);
    cudaGetSymbolAddress((void**)&pwo,   g_wouth);

    const int ATTN_SMEM = ATT_U32 * 4;          // 105984 B
    cudaFuncSetAttribute(attn_kernel,
                         cudaFuncAttributeMaxDynamicSharedMemorySize, ATTN_SMEM);
    const int GEMM_SMEM = NSTG * STAGE_U * 4;   // 104448 B
    cudaFuncSetAttribute(gemm_f16_kernel,
                         cudaFuncAttributeMaxDynamicSharedMemorySize, GEMM_SMEM);

    int n1 = Dd * QKVN / 4, n2 = Dd * Dd / 4;
    cvt2_kernel<<<(n1 + n2 + 255) / 256, 256>>>(wqkv, pwq, n1, wout, pwo, n2);
    invf_kernel<<<1, 32>>>();
    ln_kernel<<<Mrows, 256>>>(hs, ln1, px, 1);
    rope_table_kernel<<<(Bb * Ss * 32) / 256, 256>>>(pid);
    gemm_f16_kernel<<<dim3(QKVN / BN, Mrows / BM), 256, GEMM_SMEM>>>(
        px, pwq, nullptr, Mrows, QKVN, Dd, 0, nullptr);
    attn_kernel<<<dim3(Ss / 128, Hh, Bb), 256, ATTN_SMEM>>>(am);
    gemm_f16_kernel<<<dim3(Dd / BN, Mrows / BM), 256, GEMM_SMEM>>>(
        pattn, pwo, out, Mrows, Dd, Dd, 1, hs);
    ln_kernel<<<Mrows, 256>>>(out, ln2, out + OUTOFF, 0);
}

// round 13
// speedup vs baseline: 15.8701x; 1.0385x over previous
#include <cuda_runtime.h>
#include <cuda_fp16.h>
#include <math.h>
#include <stdint.h>

#define Bb    2
#define Ss    2048
#define Dd    2048
#define Hh    32
#define KVHh  8
#define HDd   64
#define QKVN  3072
#define Mrows (Bb*Ss)
#define OUTOFF ((size_t)Bb*Ss*Dd)
#define ATT_SCALE 0.125f

// ---------------- scratch ----------------------------------------------------
__device__ __half g_x[(size_t)Mrows*Dd];
__device__ __half g_q[(size_t)Bb*Hh*Ss*HDd];
__device__ __half g_k[(size_t)Bb*KVHh*Ss*HDd];
__device__ __half g_v[(size_t)Bb*KVHh*Ss*HDd];
__device__ __half g_attn[(size_t)Mrows*Dd];
__device__ __half g_wqkvh[(size_t)Dd*QKVN];
__device__ __half g_wouth[(size_t)Dd*Dd];
__device__ float g_cos[(size_t)Bb*Ss*32];
__device__ float g_sin[(size_t)Bb*Ss*32];

__device__ __forceinline__ uint32_t pkh2(float x, float y) {
    __half2 h = __floats2half2_rn(x, y);
    return *(uint32_t*)&h;
}
__device__ __forceinline__ void mma_f16(float c[4], uint32_t a0, uint32_t a1,
                                        uint32_t a2, uint32_t a3,
                                        uint32_t b0, uint32_t b1)
{
    asm volatile(
        "mma.sync.aligned.m16n8k16.row.col.f32.f16.f16.f32 "
        "{%0,%1,%2,%3}, {%4,%5,%6,%7}, {%8,%9}, {%0,%1,%2,%3};"
        : "+f"(c[0]), "+f"(c[1]), "+f"(c[2]), "+f"(c[3])
        : "r"(a0), "r"(a1), "r"(a2), "r"(a3), "r"(b0), "r"(b1));
}
__device__ __forceinline__ void ldsm4(uint32_t& r0, uint32_t& r1,
                                      uint32_t& r2, uint32_t& r3, uint32_t saddr)
{
    asm volatile(
        "ldmatrix.sync.aligned.m8n8.x4.shared.b16 {%0,%1,%2,%3}, [%4];"
        : "=r"(r0), "=r"(r1), "=r"(r2), "=r"(r3) : "r"(saddr));
}
__device__ __forceinline__ void ldsm4t(uint32_t& r0, uint32_t& r1,
                                       uint32_t& r2, uint32_t& r3, uint32_t saddr)
{
    asm volatile(
        "ldmatrix.sync.aligned.m8n8.x4.trans.shared.b16 {%0,%1,%2,%3}, [%4];"
        : "=r"(r0), "=r"(r1), "=r"(r2), "=r"(r3) : "r"(saddr));
}
__device__ __forceinline__ void cpa16(uint32_t smem_addr, const void* gptr) {
    asm volatile("cp.async.cg.shared.global [%0], [%1], 16;"
                 :: "r"(smem_addr), "l"(gptr));
}
__device__ __forceinline__ void cpa4(uint32_t smem_addr, const void* gptr) {
    asm volatile("cp.async.ca.shared.global [%0], [%1], 4;"
                 :: "r"(smem_addr), "l"(gptr));
}
__device__ __forceinline__ void cpa_commit() {
    asm volatile("cp.async.commit_group;");
}
template<int N>
__device__ __forceinline__ void cpa_wait() {
    asm volatile("cp.async.wait_group %0;" :: "n"(N));
}
__device__ __forceinline__ float clip8(float v) {
    return fminf(fmaxf(v, -8.f), 8.f);
}

// ---------------- weight fp32 -> fp16 -----------------------------------------
__global__ void cvt2_kernel(const float* __restrict__ w1, __half* __restrict__ o1,
                            int n1, const float* __restrict__ w2,
                            __half* __restrict__ o2, int n2)
{
    int i = blockIdx.x * 256 + threadIdx.x;
    const float* src; __half* dst;
    if (i < n1) { src = w1 + (size_t)i * 4; dst = o1 + (size_t)i * 4; }
    else {
        i -= n1;
        if (i >= n2) return;
        src = w2 + (size_t)i * 4; dst = o2 + (size_t)i * 4;
    }
    float4 v = *(const float4*)src;
    uint32_t* d = (uint32_t*)dst;
    d[0] = pkh2(v.x, v.y);
    d[1] = pkh2(v.z, v.w);
}

// ---------------- LayerNorm (vectorized float4) --------------------------------
__global__ __launch_bounds__(256) void ln_kernel(
    const float* __restrict__ in, const float* __restrict__ sc,
    void* __restrict__ outp, int half_out)
{
    int row = blockIdx.x;
    const float4* x4 = (const float4*)(in + (size_t)row * Dd);
    float s = 0.f, s2 = 0.f;
    float4 v[2];
    #pragma unroll
    for (int i = 0; i < 2; i++) {
        v[i] = x4[threadIdx.x + i * 256];
        s  += v[i].x + v[i].y + v[i].z + v[i].w;
        s2 += v[i].x*v[i].x + v[i].y*v[i].y + v[i].z*v[i].z + v[i].w*v[i].w;
    }
    #pragma unroll
    for (int o = 16; o; o >>= 1) {
        s  += __shfl_xor_sync(0xffffffffu, s,  o);
        s2 += __shfl_xor_sync(0xffffffffu, s2, o);
    }
    __shared__ float ws[8], ws2[8];
    int w = threadIdx.x >> 5, l = threadIdx.x & 31;
    if (l == 0) { ws[w] = s; ws2[w] = s2; }
    __syncthreads();
    if (threadIdx.x < 32) {
        s  = (l < 8) ? ws[l]  : 0.f;
        s2 = (l < 8) ? ws2[l] : 0.f;
        #pragma unroll
        for (int o = 4; o; o >>= 1) {
            s  += __shfl_xor_sync(0xffffffffu, s,  o);
            s2 += __shfl_xor_sync(0xffffffffu, s2, o);
        }
        if (l == 0) { ws[0] = s; ws2[0] = s2; }
    }
    __syncthreads();
    float mean = ws[0] * (1.f / Dd);
    float var  = ws2[0] * (1.f / Dd) - mean * mean;
    float inv  = rsqrtf(var + 1e-6f);
    if (half_out) {
        __half* o_ = (__half*)outp + (size_t)row * Dd;
        #pragma unroll
        for (int i = 0; i < 2; i++) {
            int c = (threadIdx.x + i * 256) * 4;
            const float4 sv = *(const float4*)(sc + c);
            uint32_t p0 = pkh2((v[i].x - mean) * inv * sv.x,
                               (v[i].y - mean) * inv * sv.y);
            uint32_t p1 = pkh2((v[i].z - mean) * inv * sv.z,
                               (v[i].w - mean) * inv * sv.w);
            uint2 pk; pk.x = p0; pk.y = p1;
            *(uint2*)(o_ + c) = pk;
        }
    } else {
        float* o_ = (float*)outp + (size_t)row * Dd;
        #pragma unroll
        for (int i = 0; i < 2; i++) {
            int c = (threadIdx.x + i * 256) * 4;
            const float4 sv = *(const float4*)(sc + c);
            float4 ov;
            ov.x = (v[i].x - mean) * inv * sv.x;
            ov.y = (v[i].y - mean) * inv * sv.y;
            ov.z = (v[i].z - mean) * inv * sv.z;
            ov.w = (v[i].w - mean) * inv * sv.w;
            *(float4*)(o_ + c) = ov;
        }
    }
}

// ---------------- FP16 GEMM 128x128x64, 3-stage cp.async ----------------------
#define BM 128
#define BN 128
#define BK 64
#define AS_U 36
#define AS_U32S (BM * AS_U)
#define BS_U32S (BK * 64)
#define STAGE_U (AS_U32S + BS_U32S)
#define NSTG 3

__global__ __launch_bounds__(256, 2) void gemm_f16_kernel(
    const __half* __restrict__ A, const __half* __restrict__ Bw,
    void* __restrict__ Cp, int M, int N, int K, int mode,
    const float* __restrict__ resid)
{
    extern __shared__ uint32_t smu[];
    int row0 = blockIdx.y * BM, col0 = blockIdx.x * BN;
    int t = threadIdx.x;
    int w = t >> 5, l = t & 31;
    int warpM = w >> 1, warpN = w & 1;
    int lr = l >> 2, lc = l & 3;

    const uint4* Au = (const uint4*)A;
    const uint4* Bu = (const uint4*)Bw;
    int K8 = K >> 3, N8 = N >> 3;

    uint32_t stAddr[NSTG];
    #pragma unroll
    for (int sidx = 0; sidx < NSTG; sidx++)
        stAddr[sidx] = (uint32_t)__cvta_generic_to_shared(smu + sidx * STAGE_U);

    int aRow[4], aC[4], bRow[4], bDst[4], bC[4];
    #pragma unroll
    for (int i = 0; i < 4; i++) {
        int idx = i * 256 + t;
        aRow[i] = idx >> 3;  aC[i] = idx & 7;
        int k = idx >> 4, c = idx & 15;
        bRow[i] = k;  bC[i] = c;
        bDst[i] = k * 64 + ((c * 4) ^ ((k & 7) << 2));
    }
    int bC0 = (col0 >> 3);

    float acc[2][8][4];
    #pragma unroll
    for (int mf = 0; mf < 2; mf++)
        #pragma unroll
        for (int nf = 0; nf < 8; nf++)
            #pragma unroll
            for (int r = 0; r < 4; r++) acc[mf][nf][r] = 0.f;

    int nk = K / BK;
    auto issue = [&](int kt, int stg) {
        if (kt < nk) {
            int k0 = kt * BK;
            uint32_t aBase = stAddr[stg];
            uint32_t bBase = stAddr[stg] + AS_U32S * 4;
            #pragma unroll
            for (int i = 0; i < 4; i++) {
                cpa16(aBase + (aRow[i] * AS_U + aC[i] * 4) * 4,
                      Au + (size_t)(row0 + aRow[i]) * K8 + (k0 >> 3) + aC[i]);
                cpa16(bBase + bDst[i] * 4,
                      Bu + (size_t)(k0 + bRow[i]) * N8 + bC0 + bC[i]);
            }
        }
        cpa_commit();
    };

    issue(0, 0);
    issue(1, 1);

    int aLdsmRow = l & 15;
    int aLdsmCol = (l >> 4) << 2;

    for (int kt = 0; kt < nk; kt++) {
        cpa_wait<1>();
        __syncthreads();
        issue(kt + 2, (kt + 2) % NSTG);

        int cur = kt % NSTG;
        uint32_t asAddr = stAddr[cur];
        uint32_t bsAddr = stAddr[cur] + AS_U32S * 4;
        #pragma unroll
        for (int ks = 0; ks < 4; ks++) {
            uint32_t af[2][4];
            #pragma unroll
            for (int mf = 0; mf < 2; mf++) {
                int r = warpM * 32 + mf * 16;
                ldsm4(af[mf][0], af[mf][1], af[mf][2], af[mf][3],
                      asAddr + ((r + aLdsmRow) * AS_U + ks * 8 + aLdsmCol) * 4);
            }
            #pragma unroll
            for (int nfp = 0; nfp < 4; nfp++) {
                int krow = ks * 16 + (l & 15);
                int col = warpN * 32 + nfp * 8 + ((l >> 4) << 2);
                col ^= (krow & 7) << 2;
                uint32_t b0, b1, b2, b3;
                ldsm4t(b0, b1, b2, b3, bsAddr + (krow * 64 + col) * 4);
                #pragma unroll
                for (int mf = 0; mf < 2; mf++) {
                    mma_f16(acc[mf][2*nfp],   af[mf][0], af[mf][1], af[mf][2], af[mf][3], b0, b1);
                    mma_f16(acc[mf][2*nfp+1], af[mf][0], af[mf][1], af[mf][2], af[mf][3], b2, b3);
                }
            }
        }
    }

    if (mode == 0) {
        int gcol = col0 + warpN * 64;
        int isV = (gcol >= Dd + KVHh * HDd);
        int isK = (gcol >= Dd) && !isV;
        int headIdx;
        if (isV)      headIdx = (gcol - Dd - KVHh * HDd) >> 6;
        else if (isK) headIdx = (gcol - Dd) >> 6;
        else          headIdx = gcol >> 6;
        #pragma unroll
        for (int mf = 0; mf < 2; mf++) {
            #pragma unroll
            for (int half = 0; half < 2; half++) {
                int row = row0 + warpM * 32 + mf * 16 + lr + half * 8;
                int s_ = row & (Ss - 1), b_ = row >> 11;
                __half* dst;
                if (isV)
                    dst = g_v + ((size_t)(b_ * KVHh + headIdx) * Ss + s_) * HDd;
                else if (isK)
                    dst = g_k + ((size_t)(b_ * KVHh + headIdx) * Ss + s_) * HDd;
                else
                    dst = g_q + ((size_t)(b_ * Hh + headIdx) * Ss + s_) * HDd;
                const float* cosb = g_cos + ((size_t)b_ << 16) + (s_ << 5);
                const float* sinb = g_sin + ((size_t)b_ << 16) + (s_ << 5);
                #pragma unroll
                for (int nf = 0; nf < 4; nf++) {
                    int c0 = nf * 8 + 2 * lc;
                    float x1a = clip8(acc[mf][nf][half * 2 + 0]);
                    float x1b = clip8(acc[mf][nf][half * 2 + 1]);
                    float x2a = clip8(acc[mf][nf + 4][half * 2 + 0]);
                    float x2b = clip8(acc[mf][nf + 4][half * 2 + 1]);
                    if (isV) {
                        *(uint32_t*)(dst + c0)      = pkh2(x1a, x1b);
                        *(uint32_t*)(dst + c0 + 32) = pkh2(x2a, x2b);
                    } else {
                        float ca = cosb[c0], cb = cosb[c0 + 1];
                        float sa = sinb[c0], sb = sinb[c0 + 1];
                        *(uint32_t*)(dst + c0) =
                            pkh2(x1a * ca - x2a * sa, x1b * cb - x2b * sb);
                        *(uint32_t*)(dst + c0 + 32) =
                            pkh2(x2a * ca + x1a * sa, x2b * cb + x1b * sb);
                    }
                }
            }
        }
    } else {
        #pragma unroll
        for (int mf = 0; mf < 2; mf++) {
            #pragma unroll
            for (int half = 0; half < 2; half++) {
                int row = row0 + warpM * 32 + mf * 16 + lr + half * 8;
                #pragma unroll
                for (int nf = 0; nf < 8; nf++) {
                    int col = col0 + warpN * 64 + nf * 8 + 2 * lc;
                    size_t off = (size_t)row * N + col;
                    float2 rv = *(const float2*)(resid + off);
                    float2 v;
                    v.x = acc[mf][nf][half * 2 + 0] + rv.x;
                    v.y = acc[mf][nf][half * 2 + 1] + rv.y;
                    *(float2*)((float*)Cp + off) = v;
                }
            }
        }
    }
}

// ---------------- RoPE table (inv_freq computed in-block) ----------------------
__global__ void rope_table_kernel(const int* __restrict__ pid)
{
    __shared__ double sInv[32];
    if (threadIdx.x < 32) {
        int i = threadIdx.x;
        sInv[i] = exp(-((double)(2 * i) / 64.0) * log(500000.0));
    }
    __syncthreads();
    int idx = blockIdx.x * 256 + threadIdx.x;
    if (idx >= Bb * Ss * 32) return;
    int i = idx & 31;
    int s = (idx >> 5) & (Ss - 1);
    int b = idx >> 16;
    double pos = (double)pid[b * Ss + s];
    double ang = pos * sInv[i];
    double k = rint(ang * 0.15915494309189535);
    float r = (float)(ang - k * 6.283185307179586);
    g_cos[idx] = cosf(r);
    g_sin[idx] = sinf(r);
}

// ---------------- FP16 flash attention, 128-key macro-tiles, 3 stages ----------
#define KS_U 36
#define VS_U 32
#define NAS  3
#define KT_ROWS 128
#define SM_KS 0
#define SM_VS (NAS * KT_ROWS * KS_U)
#define SM_MASK (SM_VS + NAS * KT_ROWS * VS_U)
#define ATT_U32 (SM_MASK + NAS * KT_ROWS)
#define QP_U 36
__global__ __launch_bounds__(256, 2) void attn_kernel(const int* __restrict__ amask)
{
    extern __shared__ uint32_t smu[];
    uint32_t* Ps = smu;
    int* maskS = (int*)(smu + SM_MASK);

    int qt = (gridDim.x - 1) - blockIdx.x;
    int h = blockIdx.y, b = blockIdx.z;
    int kvh = h >> 2;
    int q0 = qt * 128;
    int t = threadIdx.x;
    int w = t >> 5, l = t & 31;
    int lr = l >> 2, lc = l & 3;

    const uint4* Qg = (const uint4*)(g_q + ((size_t)(b * Hh + h) * Ss + q0) * HDd);
    const uint4* Kg = (const uint4*)(g_k + (size_t)(b * KVHh + kvh) * Ss * HDd);
    const uint4* Vg = (const uint4*)(g_v + (size_t)(b * KVHh + kvh) * Ss * HDd);
    const int*   Mg = amask + b * Ss;

    uint32_t ksAddr0 = (uint32_t)__cvta_generic_to_shared(smu + SM_KS);
    uint32_t vsAddr0 = (uint32_t)__cvta_generic_to_shared(smu + SM_VS);
    uint32_t mkAddr0 = (uint32_t)__cvta_generic_to_shared(maskS);

    #pragma unroll
    for (int i = 0; i < 4; i++) {
        int idx = i * 256 + t;
        int row = idx >> 3, c = idx & 7;
        *(uint4*)&Ps[row * QP_U + c * 4] = Qg[row * 8 + c];
    }
    __syncthreads();
    uint32_t qa[4][4];
    {
        int r0 = w * 16 + lr;
        #pragma unroll
        for (int ks = 0; ks < 4; ks++) {
            qa[ks][0] = Ps[r0 * QP_U + ks * 8 + lc];
            qa[ks][1] = Ps[(r0 + 8) * QP_U + ks * 8 + lc];
            qa[ks][2] = Ps[r0 * QP_U + ks * 8 + lc + 4];
            qa[ks][3] = Ps[(r0 + 8) * QP_U + ks * 8 + lc + 4];
        }
    }
    __syncthreads();

    int nkt = qt + 1;
    auto issueKV = [&](int kt, int stg) {
        if (kt < nkt) {
            int k0 = kt * KT_ROWS;
            uint32_t kBase = ksAddr0 + stg * KT_ROWS * KS_U * 4;
            uint32_t vBase = vsAddr0 + stg * KT_ROWS * VS_U * 4;
            #pragma unroll
            for (int i = 0; i < 4; i++) {
                int idx = i * 256 + t;
                int row = idx >> 3, c = idx & 7;
                cpa16(kBase + (row * KS_U + c * 4) * 4, Kg + (k0 + row) * 8 + c);
                cpa16(vBase + (row * VS_U + ((c * 4) ^ ((row & 7) << 2))) * 4,
                      Vg + (k0 + row) * 8 + c);
            }
            if (t < KT_ROWS) cpa4(mkAddr0 + (stg * KT_ROWS + t) * 4, Mg + k0 + t);
        }
        cpa_commit();
    };

    issueKV(0, 0);
    issueKV(1, 1);

    float m0 = -1e30f, m1 = -1e30f, l0 = 0.f, l1 = 0.f;
    float o[8][4];
    #pragma unroll
    for (int nf = 0; nf < 8; nf++)
        #pragma unroll
        for (int r = 0; r < 4; r++) o[nf][r] = 0.f;

    int kLdsmRow = l & 15;
    int kLdsmCol = (l >> 4) << 2;
    int qlow = q0 + w * 16;

    for (int kt = 0; kt < nkt; kt++) {
        cpa_wait<1>();
        __syncthreads();
        issueKV(kt + 2, (kt + 2) % NAS);

        int cur = kt % NAS;
        uint32_t kbAddr = ksAddr0 + cur * KT_ROWS * KS_U * 4;
        uint32_t vsAddr = vsAddr0 + cur * KT_ROWS * VS_U * 4;

        #pragma unroll
        for (int half = 0; half < 2; half++) {
            int k0 = kt * KT_ROWS + half * 64;
            if (k0 > qlow + 15) break;
            int rbase = half * 64;
            float s[8][4];
            #pragma unroll
            for (int nf = 0; nf < 8; nf++)
                #pragma unroll
                for (int r = 0; r < 4; r++) s[nf][r] = 0.f;
            #pragma unroll
            for (int ks = 0; ks < 4; ks++) {
                #pragma unroll
                for (int p = 0; p < 4; p++) {
                    uint32_t b0, b1, b2, b3;
                    ldsm4(b0, b1, b2, b3,
                          kbAddr + ((rbase + p * 16 + kLdsmRow) * KS_U
                                    + ks * 8 + kLdsmCol) * 4);
                    mma_f16(s[2*p],   qa[ks][0], qa[ks][1], qa[ks][2], qa[ks][3], b0, b2);
                    mma_f16(s[2*p+1], qa[ks][0], qa[ks][1], qa[ks][2], qa[ks][3], b1, b3);
                }
            }
            int qr0 = qlow + lr, qr1 = qr0 + 8;
            bool fullvis = (k0 + 63 <= qlow);
            int mbase = cur * KT_ROWS + rbase;
            #pragma unroll
            for (int nf = 0; nf < 8; nf++) {
                int kg0 = k0 + nf * 8 + 2 * lc;
                int ms0 = maskS[mbase + nf * 8 + 2 * lc];
                int ms1 = maskS[mbase + nf * 8 + 2 * lc + 1];
                s[nf][0] = (ms0 && (fullvis || kg0     <= qr0)) ? s[nf][0] * ATT_SCALE : -1e30f;
                s[nf][1] = (ms1 && (fullvis || kg0 + 1 <= qr0)) ? s[nf][1] * ATT_SCALE : -1e30f;
                s[nf][2] = (ms0 && (fullvis || kg0     <= qr1)) ? s[nf][2] * ATT_SCALE : -1e30f;
                s[nf][3] = (ms1 && (fullvis || kg0 + 1 <= qr1)) ? s[nf][3] * ATT_SCALE : -1e30f;
            }
            float mt0 = -1e30f, mt1 = -1e30f;
            #pragma unroll
            for (int nf = 0; nf < 8; nf++) {
                mt0 = fmaxf(mt0, fmaxf(s[nf][0], s[nf][1]));
                mt1 = fmaxf(mt1, fmaxf(s[nf][2], s[nf][3]));
            }
            mt0 = fmaxf(mt0, __shfl_xor_sync(0xffffffffu, mt0, 1));
            mt0 = fmaxf(mt0, __shfl_xor_sync(0xffffffffu, mt0, 2));
            mt1 = fmaxf(mt1, __shfl_xor_sync(0xffffffffu, mt1, 1));
            mt1 = fmaxf(mt1, __shfl_xor_sync(0xffffffffu, mt1, 2));
            float mn0 = fmaxf(m0, mt0), mn1 = fmaxf(m1, mt1);
            float rs0 = 0.f, rs1 = 0.f;
            #pragma unroll
            for (int nf = 0; nf < 8; nf++) {
                s[nf][0] = __expf(s[nf][0] - mn0);
                s[nf][1] = __expf(s[nf][1] - mn0);
                s[nf][2] = __expf(s[nf][2] - mn1);
                s[nf][3] = __expf(s[nf][3] - mn1);
                rs0 += s[nf][0] + s[nf][1];
                rs1 += s[nf][2] + s[nf][3];
            }
            rs0 += __shfl_xor_sync(0xffffffffu, rs0, 1);
            rs0 += __shfl_xor_sync(0xffffffffu, rs0, 2);
            rs1 += __shfl_xor_sync(0xffffffffu, rs1, 1);
            rs1 += __shfl_xor_sync(0xffffffffu, rs1, 2);
            float a0 = __expf(m0 - mn0), a1 = __expf(m1 - mn1);
            l0 = l0 * a0 + rs0;  l1 = l1 * a1 + rs1;
            m0 = mn0;  m1 = mn1;
            #pragma unroll
            for (int nf = 0; nf < 8; nf++) {
                o[nf][0] *= a0; o[nf][1] *= a0;
                o[nf][2] *= a1; o[nf][3] *= a1;
            }
            #pragma unroll
            for (int ks = 0; ks < 4; ks++) {
                uint32_t pa0 = pkh2(s[2*ks][0],   s[2*ks][1]);
                uint32_t pa1 = pkh2(s[2*ks][2],   s[2*ks][3]);
                uint32_t pa2 = pkh2(s[2*ks+1][0], s[2*ks+1][1]);
                uint32_t pa3 = pkh2(s[2*ks+1][2], s[2*ks+1][3]);
                #pragma unroll
                for (int nfp = 0; nfp < 4; nfp++) {
                    int key = rbase + ks * 16 + (l & 15);
                    int col = nfp * 8 + ((l >> 4) << 2);
                    col ^= (key & 7) << 2;
                    uint32_t b0, b1, b2, b3;
                    ldsm4t(b0, b1, b2, b3, vsAddr + (key * VS_U + col) * 4);
                    mma_f16(o[2*nfp],   pa0, pa1, pa2, pa3, b0, b1);
                    mma_f16(o[2*nfp+1], pa0, pa1, pa2, pa3, b2, b3);
                }
            }
        }
    }

    float il0 = (l0 > 0.f) ? (1.f / l0) : 0.f;
    float il1 = (l1 > 0.f) ? (1.f / l1) : 0.f;
    int qr0 = q0 + w * 16 + lr;
    __half* d0 = g_attn + (size_t)(b * Ss + qr0) * Dd + h * HDd;
    __half* d1 = g_attn + (size_t)(b * Ss + qr0 + 8) * Dd + h * HDd;
    #pragma unroll
    for (int nf = 0; nf < 8; nf++) {
        int c = nf * 8 + 2 * lc;
        *(uint32_t*)(d0 + c) = pkh2(o[nf][0] * il0, o[nf][1] * il0);
        *(uint32_t*)(d1 + c) = pkh2(o[nf][2] * il1, o[nf][3] * il1);
    }
}

// ---------------- launch ------------------------------------------------------
extern "C" void kernel_launch(void* const* d_in, const int* in_sizes, int n_in,
                              void* d_out, int out_size)
{
    const float* hs   = (const float*)d_in[0];
    const int*   am   = (const int*)  d_in[1];
    const int*   pid  = (const int*)  d_in[2];
    const float* ln1  = (const float*)d_in[4];
    const float* wqkv = (const float*)d_in[5];
    const float* wout = (const float*)d_in[6];
    const float* ln2  = (const float*)d_in[7];
    float* out = (float*)d_out;

    __half *px, *pattn, *pwq, *pwo;
    cudaGetSymbolAddress((void**)&px,    g_x);
    cudaGetSymbolAddress((void**)&pattn, g_attn);
    cudaGetSymbolAddress((void**)&pwq,   g_wqkvh);
    cudaGetSymbolAddress((void**)&pwo,   g_wouth);

    const int ATTN_SMEM = ATT_U32 * 4;
    cudaFuncSetAttribute(attn_kernel,
                         cudaFuncAttributeMaxDynamicSharedMemorySize, ATTN_SMEM);
    const int GEMM_SMEM = NSTG * STAGE_U * 4;
    cudaFuncSetAttribute(gemm_f16_kernel,
                         cudaFuncAttributeMaxDynamicSharedMemorySize, GEMM_SMEM);

    int n1 = Dd * QKVN / 4, n2 = Dd * Dd / 4;
    cvt2_kernel<<<(n1 + n2 + 255) / 256, 256>>>(wqkv, pwq, n1, wout, pwo, n2);
    ln_kernel<<<Mrows, 256>>>(hs, ln1, px, 1);
    rope_table_kernel<<<(Bb * Ss * 32) / 256, 256>>>(pid);
    gemm_f16_kernel<<<dim3(QKVN / BN, Mrows / BM), 256, GEMM_SMEM>>>(
        px, pwq, nullptr, Mrows, QKVN, Dd, 0, nullptr);
    attn_kernel<<<dim3(Ss / 128, Hh, Bb), 256, ATTN_SMEM>>>(am);
    gemm_f16_kernel<<<dim3(Dd / BN, Mrows / BM), 256, GEMM_SMEM>>>(
        pattn, pwo, out, Mrows, Dd, Dd, 1, hs);
    ln_kernel<<<Mrows, 256>>>(out, ln2, out + OUTOFF, 0);
}

// round 14
// speedup vs baseline: 17.6741x; 1.1137x over previous
#include <cuda_runtime.h>
#include <cuda_fp16.h>
#include <math.h>
#include <stdint.h>

#define Bb    2
#define Ss    2048
#define Dd    2048
#define Hh    32
#define KVHh  8
#define HDd   64
#define QKVN  3072
#define Mrows (Bb*Ss)
#define OUTOFF ((size_t)Bb*Ss*Dd)
#define ATT_SCALE 0.125f

// ---------------- scratch ----------------------------------------------------
__device__ __half g_x[(size_t)Mrows*Dd];
__device__ __half g_q[(size_t)Bb*Hh*Ss*HDd];
__device__ __half g_k[(size_t)Bb*KVHh*Ss*HDd];
__device__ __half g_v[(size_t)Bb*KVHh*Ss*HDd];
__device__ __half g_attn[(size_t)Mrows*Dd];
__device__ __half g_wqkvh[(size_t)Dd*QKVN];
__device__ __half g_wouth[(size_t)Dd*Dd];
__device__ float g_cos[(size_t)Bb*Ss*32];
__device__ float g_sin[(size_t)Bb*Ss*32];

__device__ __forceinline__ uint32_t pkh2(float x, float y) {
    __half2 h = __floats2half2_rn(x, y);
    return *(uint32_t*)&h;
}
__device__ __forceinline__ void mma_f16(float c[4], uint32_t a0, uint32_t a1,
                                        uint32_t a2, uint32_t a3,
                                        uint32_t b0, uint32_t b1)
{
    asm volatile(
        "mma.sync.aligned.m16n8k16.row.col.f32.f16.f16.f32 "
        "{%0,%1,%2,%3}, {%4,%5,%6,%7}, {%8,%9}, {%0,%1,%2,%3};"
        : "+f"(c[0]), "+f"(c[1]), "+f"(c[2]), "+f"(c[3])
        : "r"(a0), "r"(a1), "r"(a2), "r"(a3), "r"(b0), "r"(b1));
}
__device__ __forceinline__ void ldsm4(uint32_t& r0, uint32_t& r1,
                                      uint32_t& r2, uint32_t& r3, uint32_t saddr)
{
    asm volatile(
        "ldmatrix.sync.aligned.m8n8.x4.shared.b16 {%0,%1,%2,%3}, [%4];"
        : "=r"(r0), "=r"(r1), "=r"(r2), "=r"(r3) : "r"(saddr));
}
__device__ __forceinline__ void ldsm4t(uint32_t& r0, uint32_t& r1,
                                       uint32_t& r2, uint32_t& r3, uint32_t saddr)
{
    asm volatile(
        "ldmatrix.sync.aligned.m8n8.x4.trans.shared.b16 {%0,%1,%2,%3}, [%4];"
        : "=r"(r0), "=r"(r1), "=r"(r2), "=r"(r3) : "r"(saddr));
}
__device__ __forceinline__ void cpa16(uint32_t smem_addr, const void* gptr) {
    asm volatile("cp.async.cg.shared.global [%0], [%1], 16;"
                 :: "r"(smem_addr), "l"(gptr));
}
__device__ __forceinline__ void cpa4(uint32_t smem_addr, const void* gptr) {
    asm volatile("cp.async.ca.shared.global [%0], [%1], 4;"
                 :: "r"(smem_addr), "l"(gptr));
}
__device__ __forceinline__ void cpa_commit() {
    asm volatile("cp.async.commit_group;");
}
template<int N>
__device__ __forceinline__ void cpa_wait() {
    asm volatile("cp.async.wait_group %0;" :: "n"(N));
}
__device__ __forceinline__ float clip8(float v) {
    return fminf(fmaxf(v, -8.f), 8.f);
}

// ---------------- weight fp32 -> fp16 -----------------------------------------
__global__ void cvt2_kernel(const float* __restrict__ w1, __half* __restrict__ o1,
                            int n1, const float* __restrict__ w2,
                            __half* __restrict__ o2, int n2)
{
    int i = blockIdx.x * 256 + threadIdx.x;
    const float* src; __half* dst;
    if (i < n1) { src = w1 + (size_t)i * 4; dst = o1 + (size_t)i * 4; }
    else {
        i -= n1;
        if (i >= n2) return;
        src = w2 + (size_t)i * 4; dst = o2 + (size_t)i * 4;
    }
    float4 v = *(const float4*)src;
    uint32_t* d = (uint32_t*)dst;
    d[0] = pkh2(v.x, v.y);
    d[1] = pkh2(v.z, v.w);
}

// ---------------- LayerNorm (vectorized float4) --------------------------------
__global__ __launch_bounds__(256) void ln_kernel(
    const float* __restrict__ in, const float* __restrict__ sc,
    void* __restrict__ outp, int half_out)
{
    int row = blockIdx.x;
    const float4* x4 = (const float4*)(in + (size_t)row * Dd);
    float s = 0.f, s2 = 0.f;
    float4 v[2];
    #pragma unroll
    for (int i = 0; i < 2; i++) {
        v[i] = x4[threadIdx.x + i * 256];
        s  += v[i].x + v[i].y + v[i].z + v[i].w;
        s2 += v[i].x*v[i].x + v[i].y*v[i].y + v[i].z*v[i].z + v[i].w*v[i].w;
    }
    #pragma unroll
    for (int o = 16; o; o >>= 1) {
        s  += __shfl_xor_sync(0xffffffffu, s,  o);
        s2 += __shfl_xor_sync(0xffffffffu, s2, o);
    }
    __shared__ float ws[8], ws2[8];
    int w = threadIdx.x >> 5, l = threadIdx.x & 31;
    if (l == 0) { ws[w] = s; ws2[w] = s2; }
    __syncthreads();
    if (threadIdx.x < 32) {
        s  = (l < 8) ? ws[l]  : 0.f;
        s2 = (l < 8) ? ws2[l] : 0.f;
        #pragma unroll
        for (int o = 4; o; o >>= 1) {
            s  += __shfl_xor_sync(0xffffffffu, s,  o);
            s2 += __shfl_xor_sync(0xffffffffu, s2, o);
        }
        if (l == 0) { ws[0] = s; ws2[0] = s2; }
    }
    __syncthreads();
    float mean = ws[0] * (1.f / Dd);
    float var  = ws2[0] * (1.f / Dd) - mean * mean;
    float inv  = rsqrtf(var + 1e-6f);
    if (half_out) {
        __half* o_ = (__half*)outp + (size_t)row * Dd;
        #pragma unroll
        for (int i = 0; i < 2; i++) {
            int c = (threadIdx.x + i * 256) * 4;
            const float4 sv = *(const float4*)(sc + c);
            uint32_t p0 = pkh2((v[i].x - mean) * inv * sv.x,
                               (v[i].y - mean) * inv * sv.y);
            uint32_t p1 = pkh2((v[i].z - mean) * inv * sv.z,
                               (v[i].w - mean) * inv * sv.w);
            uint2 pk; pk.x = p0; pk.y = p1;
            *(uint2*)(o_ + c) = pk;
        }
    } else {
        float* o_ = (float*)outp + (size_t)row * Dd;
        #pragma unroll
        for (int i = 0; i < 2; i++) {
            int c = (threadIdx.x + i * 256) * 4;
            const float4 sv = *(const float4*)(sc + c);
            float4 ov;
            ov.x = (v[i].x - mean) * inv * sv.x;
            ov.y = (v[i].y - mean) * inv * sv.y;
            ov.z = (v[i].z - mean) * inv * sv.z;
            ov.w = (v[i].w - mean) * inv * sv.w;
            *(float4*)(o_ + c) = ov;
        }
    }
}

// ---------------- FP16 GEMM 128x128x64, 3-stage cp.async ----------------------
#define BM 128
#define BN 128
#define BK 64
#define AS_U 36
#define AS_U32S (BM * AS_U)
#define BS_U32S (BK * 64)
#define STAGE_U (AS_U32S + BS_U32S)
#define NSTG 3

__global__ __launch_bounds__(256, 2) void gemm_f16_kernel(
    const __half* __restrict__ A, const __half* __restrict__ Bw,
    void* __restrict__ Cp, int M, int N, int K, int mode,
    const float* __restrict__ resid)
{
    extern __shared__ uint32_t smu[];
    int row0 = blockIdx.y * BM, col0 = blockIdx.x * BN;
    int t = threadIdx.x;
    int w = t >> 5, l = t & 31;
    int warpM = w >> 1, warpN = w & 1;
    int lr = l >> 2, lc = l & 3;

    const uint4* Au = (const uint4*)A;
    const uint4* Bu = (const uint4*)Bw;
    int K8 = K >> 3, N8 = N >> 3;

    uint32_t smuBase = (uint32_t)__cvta_generic_to_shared(smu);
    int bC0 = (col0 >> 3);

    float acc[2][8][4];
    #pragma unroll
    for (int mf = 0; mf < 2; mf++)
        #pragma unroll
        for (int nf = 0; nf < 8; nf++)
            #pragma unroll
            for (int r = 0; r < 4; r++) acc[mf][nf][r] = 0.f;

    int nk = K / BK;
    // recompute all indices per call: keeps zero long-lived registers
    auto issue = [&](int kt, int stg) {
        if (kt < nk) {
            int k0 = kt * BK;
            uint32_t aBase = smuBase + stg * STAGE_U * 4;
            uint32_t bBase = aBase + AS_U32S * 4;
            #pragma unroll
            for (int i = 0; i < 4; i++) {
                int idx = i * 256 + t;
                int ar = idx >> 3, ac = idx & 7;
                cpa16(aBase + (ar * AS_U + ac * 4) * 4,
                      Au + (size_t)(row0 + ar) * K8 + (k0 >> 3) + ac);
                int bk = idx >> 4, bc = idx & 15;
                cpa16(bBase + (bk * 64 + ((bc * 4) ^ ((bk & 7) << 2))) * 4,
                      Bu + (size_t)(k0 + bk) * N8 + bC0 + bc);
            }
        }
        cpa_commit();
    };

    issue(0, 0);
    issue(1, 1);

    int aLdsmRow = l & 15;
    int aLdsmCol = (l >> 4) << 2;

    for (int kt = 0; kt < nk; kt++) {
        cpa_wait<1>();
        __syncthreads();
        issue(kt + 2, (kt + 2) % NSTG);

        uint32_t asAddr = smuBase + (kt % NSTG) * STAGE_U * 4;
        uint32_t bsAddr = asAddr + AS_U32S * 4;
        #pragma unroll
        for (int ks = 0; ks < 4; ks++) {
            uint32_t af[2][4];
            #pragma unroll
            for (int mf = 0; mf < 2; mf++) {
                int r = warpM * 32 + mf * 16;
                ldsm4(af[mf][0], af[mf][1], af[mf][2], af[mf][3],
                      asAddr + ((r + aLdsmRow) * AS_U + ks * 8 + aLdsmCol) * 4);
            }
            #pragma unroll
            for (int nfp = 0; nfp < 4; nfp++) {
                int krow = ks * 16 + (l & 15);
                int col = warpN * 32 + nfp * 8 + ((l >> 4) << 2);
                col ^= (krow & 7) << 2;
                uint32_t b0, b1, b2, b3;
                ldsm4t(b0, b1, b2, b3, bsAddr + (krow * 64 + col) * 4);
                #pragma unroll
                for (int mf = 0; mf < 2; mf++) {
                    mma_f16(acc[mf][2*nfp],   af[mf][0], af[mf][1], af[mf][2], af[mf][3], b0, b1);
                    mma_f16(acc[mf][2*nfp+1], af[mf][0], af[mf][1], af[mf][2], af[mf][3], b2, b3);
                }
            }
        }
    }

    if (mode == 0) {
        int gcol = col0 + warpN * 64;
        int isV = (gcol >= Dd + KVHh * HDd);
        int isK = (gcol >= Dd) && !isV;
        int headIdx;
        if (isV)      headIdx = (gcol - Dd - KVHh * HDd) >> 6;
        else if (isK) headIdx = (gcol - Dd) >> 6;
        else          headIdx = gcol >> 6;
        #pragma unroll
        for (int mf = 0; mf < 2; mf++) {
            #pragma unroll
            for (int half = 0; half < 2; half++) {
                int row = row0 + warpM * 32 + mf * 16 + lr + half * 8;
                int s_ = row & (Ss - 1), b_ = row >> 11;
                __half* dst;
                if (isV)
                    dst = g_v + ((size_t)(b_ * KVHh + headIdx) * Ss + s_) * HDd;
                else if (isK)
                    dst = g_k + ((size_t)(b_ * KVHh + headIdx) * Ss + s_) * HDd;
                else
                    dst = g_q + ((size_t)(b_ * Hh + headIdx) * Ss + s_) * HDd;
                const float* cosb = g_cos + ((size_t)b_ << 16) + (s_ << 5);
                const float* sinb = g_sin + ((size_t)b_ << 16) + (s_ << 5);
                #pragma unroll
                for (int nf = 0; nf < 4; nf++) {
                    int c0 = nf * 8 + 2 * lc;
                    float x1a = clip8(acc[mf][nf][half * 2 + 0]);
                    float x1b = clip8(acc[mf][nf][half * 2 + 1]);
                    float x2a = clip8(acc[mf][nf + 4][half * 2 + 0]);
                    float x2b = clip8(acc[mf][nf + 4][half * 2 + 1]);
                    if (isV) {
                        *(uint32_t*)(dst + c0)      = pkh2(x1a, x1b);
                        *(uint32_t*)(dst + c0 + 32) = pkh2(x2a, x2b);
                    } else {
                        float ca = cosb[c0], cb = cosb[c0 + 1];
                        float sa = sinb[c0], sb = sinb[c0 + 1];
                        *(uint32_t*)(dst + c0) =
                            pkh2(x1a * ca - x2a * sa, x1b * cb - x2b * sb);
                        *(uint32_t*)(dst + c0 + 32) =
                            pkh2(x2a * ca + x1a * sa, x2b * cb + x1b * sb);
                    }
                }
            }
        }
    } else {
        #pragma unroll
        for (int mf = 0; mf < 2; mf++) {
            #pragma unroll
            for (int half = 0; half < 2; half++) {
                int row = row0 + warpM * 32 + mf * 16 + lr + half * 8;
                #pragma unroll
                for (int nf = 0; nf < 8; nf++) {
                    int col = col0 + warpN * 64 + nf * 8 + 2 * lc;
                    size_t off = (size_t)row * N + col;
                    float2 rv = *(const float2*)(resid + off);
                    float2 v;
                    v.x = acc[mf][nf][half * 2 + 0] + rv.x;
                    v.y = acc[mf][nf][half * 2 + 1] + rv.y;
                    *(float2*)((float*)Cp + off) = v;
                }
            }
        }
    }
}

// ---------------- RoPE table (inv_freq computed in-block) ----------------------
__global__ void rope_table_kernel(const int* __restrict__ pid)
{
    __shared__ double sInv[32];
    if (threadIdx.x < 32) {
        int i = threadIdx.x;
        sInv[i] = exp(-((double)(2 * i) / 64.0) * log(500000.0));
    }
    __syncthreads();
    int idx = blockIdx.x * 256 + threadIdx.x;
    if (idx >= Bb * Ss * 32) return;
    int i = idx & 31;
    int s = (idx >> 5) & (Ss - 1);
    int b = idx >> 16;
    double pos = (double)pid[b * Ss + s];
    double ang = pos * sInv[i];
    double k = rint(ang * 0.15915494309189535);
    float r = (float)(ang - k * 6.283185307179586);
    g_cos[idx] = cosf(r);
    g_sin[idx] = sinf(r);
}

// ---------------- FP16 flash attention, 128-key macro-tiles, 3 stages ----------
// 1D grid, LPT order: all heaviest q-tiles launch first.
#define KS_U 36
#define VS_U 32
#define NAS  3
#define KT_ROWS 128
#define SM_KS 0
#define SM_VS (NAS * KT_ROWS * KS_U)
#define SM_MASK (SM_VS + NAS * KT_ROWS * VS_U)
#define ATT_U32 (SM_MASK + NAS * KT_ROWS)
#define QP_U 36
#define NQT (Ss / 128)
__global__ __launch_bounds__(256, 2) void attn_kernel(const int* __restrict__ amask)
{
    extern __shared__ uint32_t smu[];
    uint32_t* Ps = smu;
    int* maskS = (int*)(smu + SM_MASK);

    // LPT: bid 0..63 -> qt=15, 64..127 -> qt=14, ...
    int bid = blockIdx.x;
    int qt = (NQT - 1) - (bid >> 6);
    int rem = bid & 63;
    int h = rem >> 1;
    int b = rem & 1;
    int kvh = h >> 2;
    int q0 = qt * 128;
    int t = threadIdx.x;
    int w = t >> 5, l = t & 31;
    int lr = l >> 2, lc = l & 3;

    const uint4* Qg = (const uint4*)(g_q + ((size_t)(b * Hh + h) * Ss + q0) * HDd);
    const uint4* Kg = (const uint4*)(g_k + (size_t)(b * KVHh + kvh) * Ss * HDd);
    const uint4* Vg = (const uint4*)(g_v + (size_t)(b * KVHh + kvh) * Ss * HDd);
    const int*   Mg = amask + b * Ss;

    uint32_t smuBase = (uint32_t)__cvta_generic_to_shared(smu);

    #pragma unroll
    for (int i = 0; i < 4; i++) {
        int idx = i * 256 + t;
        int row = idx >> 3, c = idx & 7;
        *(uint4*)&Ps[row * QP_U + c * 4] = Qg[row * 8 + c];
    }
    __syncthreads();
    uint32_t qa[4][4];
    {
        int r0 = w * 16 + lr;
        #pragma unroll
        for (int ks = 0; ks < 4; ks++) {
            qa[ks][0] = Ps[r0 * QP_U + ks * 8 + lc];
            qa[ks][1] = Ps[(r0 + 8) * QP_U + ks * 8 + lc];
            qa[ks][2] = Ps[r0 * QP_U + ks * 8 + lc + 4];
            qa[ks][3] = Ps[(r0 + 8) * QP_U + ks * 8 + lc + 4];
        }
    }
    __syncthreads();

    int nkt = qt + 1;
    auto issueKV = [&](int kt, int stg) {
        if (kt < nkt) {
            int k0 = kt * KT_ROWS;
            uint32_t kBase = smuBase + (SM_KS + stg * KT_ROWS * KS_U) * 4;
            uint32_t vBase = smuBase + (SM_VS + stg * KT_ROWS * VS_U) * 4;
            #pragma unroll
            for (int i = 0; i < 4; i++) {
                int idx = i * 256 + t;
                int row = idx >> 3, c = idx & 7;
                cpa16(kBase + (row * KS_U + c * 4) * 4, Kg + (k0 + row) * 8 + c);
                cpa16(vBase + (row * VS_U + ((c * 4) ^ ((row & 7) << 2))) * 4,
                      Vg + (k0 + row) * 8 + c);
            }
            if (t < KT_ROWS)
                cpa4(smuBase + (SM_MASK + stg * KT_ROWS + t) * 4, Mg + k0 + t);
        }
        cpa_commit();
    };

    issueKV(0, 0);
    issueKV(1, 1);

    float m0 = -1e30f, m1 = -1e30f, l0 = 0.f, l1 = 0.f;
    float o[8][4];
    #pragma unroll
    for (int nf = 0; nf < 8; nf++)
        #pragma unroll
        for (int r = 0; r < 4; r++) o[nf][r] = 0.f;

    int kLdsmRow = l & 15;
    int kLdsmCol = (l >> 4) << 2;
    int qlow = q0 + w * 16;

    for (int kt = 0; kt < nkt; kt++) {
        cpa_wait<1>();
        __syncthreads();
        issueKV(kt + 2, (kt + 2) % NAS);

        int cur = kt % NAS;
        uint32_t kbAddr = smuBase + (SM_KS + cur * KT_ROWS * KS_U) * 4;
        uint32_t vsAddr = smuBase + (SM_VS + cur * KT_ROWS * VS_U) * 4;

        #pragma unroll
        for (int half = 0; half < 2; half++) {
            int k0 = kt * KT_ROWS + half * 64;
            if (k0 > qlow + 15) break;
            int rbase = half * 64;
            float s[8][4];
            #pragma unroll
            for (int nf = 0; nf < 8; nf++)
                #pragma unroll
                for (int r = 0; r < 4; r++) s[nf][r] = 0.f;
            #pragma unroll
            for (int ks = 0; ks < 4; ks++) {
                #pragma unroll
                for (int p = 0; p < 4; p++) {
                    uint32_t b0, b1, b2, b3;
                    ldsm4(b0, b1, b2, b3,
                          kbAddr + ((rbase + p * 16 + kLdsmRow) * KS_U
                                    + ks * 8 + kLdsmCol) * 4);
                    mma_f16(s[2*p],   qa[ks][0], qa[ks][1], qa[ks][2], qa[ks][3], b0, b2);
                    mma_f16(s[2*p+1], qa[ks][0], qa[ks][1], qa[ks][2], qa[ks][3], b1, b3);
                }
            }
            int qr0 = qlow + lr, qr1 = qr0 + 8;
            bool fullvis = (k0 + 63 <= qlow);
            int mbase = cur * KT_ROWS + rbase;
            #pragma unroll
            for (int nf = 0; nf < 8; nf++) {
                int kg0 = k0 + nf * 8 + 2 * lc;
                int ms0 = maskS[mbase + nf * 8 + 2 * lc];
                int ms1 = maskS[mbase + nf * 8 + 2 * lc + 1];
                s[nf][0] = (ms0 && (fullvis || kg0     <= qr0)) ? s[nf][0] * ATT_SCALE : -1e30f;
                s[nf][1] = (ms1 && (fullvis || kg0 + 1 <= qr0)) ? s[nf][1] * ATT_SCALE : -1e30f;
                s[nf][2] = (ms0 && (fullvis || kg0     <= qr1)) ? s[nf][2] * ATT_SCALE : -1e30f;
                s[nf][3] = (ms1 && (fullvis || kg0 + 1 <= qr1)) ? s[nf][3] * ATT_SCALE : -1e30f;
            }
            float mt0 = -1e30f, mt1 = -1e30f;
            #pragma unroll
            for (int nf = 0; nf < 8; nf++) {
                mt0 = fmaxf(mt0, fmaxf(s[nf][0], s[nf][1]));
                mt1 = fmaxf(mt1, fmaxf(s[nf][2], s[nf][3]));
            }
            mt0 = fmaxf(mt0, __shfl_xor_sync(0xffffffffu, mt0, 1));
            mt0 = fmaxf(mt0, __shfl_xor_sync(0xffffffffu, mt0, 2));
            mt1 = fmaxf(mt1, __shfl_xor_sync(0xffffffffu, mt1, 1));
            mt1 = fmaxf(mt1, __shfl_xor_sync(0xffffffffu, mt1, 2));
            float mn0 = fmaxf(m0, mt0), mn1 = fmaxf(m1, mt1);
            float rs0 = 0.f, rs1 = 0.f;
            #pragma unroll
            for (int nf = 0; nf < 8; nf++) {
                s[nf][0] = __expf(s[nf][0] - mn0);
                s[nf][1] = __expf(s[nf][1] - mn0);
                s[nf][2] = __expf(s[nf][2] - mn1);
                s[nf][3] = __expf(s[nf][3] - mn1);
                rs0 += s[nf][0] + s[nf][1];
                rs1 += s[nf][2] + s[nf][3];
            }
            rs0 += __shfl_xor_sync(0xffffffffu, rs0, 1);
            rs0 += __shfl_xor_sync(0xffffffffu, rs0, 2);
            rs1 += __shfl_xor_sync(0xffffffffu, rs1, 1);
            rs1 += __shfl_xor_sync(0xffffffffu, rs1, 2);
            float a0 = __expf(m0 - mn0), a1 = __expf(m1 - mn1);
            l0 = l0 * a0 + rs0;  l1 = l1 * a1 + rs1;
            m0 = mn0;  m1 = mn1;
            #pragma unroll
            for (int nf = 0; nf < 8; nf++) {
                o[nf][0] *= a0; o[nf][1] *= a0;
                o[nf][2] *= a1; o[nf][3] *= a1;
            }
            #pragma unroll
            for (int ks = 0; ks < 4; ks++) {
                uint32_t pa0 = pkh2(s[2*ks][0],   s[2*ks][1]);
                uint32_t pa1 = pkh2(s[2*ks][2],   s[2*ks][3]);
                uint32_t pa2 = pkh2(s[2*ks+1][0], s[2*ks+1][1]);
                uint32_t pa3 = pkh2(s[2*ks+1][2], s[2*ks+1][3]);
                #pragma unroll
                for (int nfp = 0; nfp < 4; nfp++) {
                    int key = rbase + ks * 16 + (l & 15);
                    int col = nfp * 8 + ((l >> 4) << 2);
                    col ^= (key & 7) << 2;
                    uint32_t b0, b1, b2, b3;
                    ldsm4t(b0, b1, b2, b3, vsAddr + (key * VS_U + col) * 4);
                    mma_f16(o[2*nfp],   pa0, pa1, pa2, pa3, b0, b1);
                    mma_f16(o[2*nfp+1], pa0, pa1, pa2, pa3, b2, b3);
                }
            }
        }
    }

    float il0 = (l0 > 0.f) ? (1.f / l0) : 0.f;
    float il1 = (l1 > 0.f) ? (1.f / l1) : 0.f;
    int qr0 = q0 + w * 16 + lr;
    __half* d0 = g_attn + (size_t)(b * Ss + qr0) * Dd + h * HDd;
    __half* d1 = g_attn + (size_t)(b * Ss + qr0 + 8) * Dd + h * HDd;
    #pragma unroll
    for (int nf = 0; nf < 8; nf++) {
        int c = nf * 8 + 2 * lc;
        *(uint32_t*)(d0 + c) = pkh2(o[nf][0] * il0, o[nf][1] * il0);
        *(uint32_t*)(d1 + c) = pkh2(o[nf][2] * il1, o[nf][3] * il1);
    }
}

// ---------------- launch ------------------------------------------------------
extern "C" void kernel_launch(void* const* d_in, const int* in_sizes, int n_in,
                              void* d_out, int out_size)
{
    const float* hs   = (const float*)d_in[0];
    const int*   am   = (const int*)  d_in[1];
    const int*   pid  = (const int*)  d_in[2];
    const float* ln1  = (const float*)d_in[4];
    const float* wqkv = (const float*)d_in[5];
    const float* wout = (const float*)d_in[6];
    const float* ln2  = (const float*)d_in[7];
    float* out = (float*)d_out;

    __half *px, *pattn, *pwq, *pwo;
    cudaGetSymbolAddress((void**)&px,    g_x);
    cudaGetSymbolAddress((void**)&pattn, g_attn);
    cudaGetSymbolAddress((void**)&pwq,   g_wqkvh);
    cudaGetSymbolAddress((void**)&pwo,   g_wouth);

    const int ATTN_SMEM = ATT_U32 * 4;
    cudaFuncSetAttribute(attn_kernel,
                         cudaFuncAttributeMaxDynamicSharedMemorySize, ATTN_SMEM);
    const int GEMM_SMEM = NSTG * STAGE_U * 4;
    cudaFuncSetAttribute(gemm_f16_kernel,
                         cudaFuncAttributeMaxDynamicSharedMemorySize, GEMM_SMEM);

    int n1 = Dd * QKVN / 4, n2 = Dd * Dd / 4;
    cvt2_kernel<<<(n1 + n2 + 255) / 256, 256>>>(wqkv, pwq, n1, wout, pwo, n2);
    ln_kernel<<<Mrows, 256>>>(hs, ln1, px, 1);
    rope_table_kernel<<<(Bb * Ss * 32) / 256, 256>>>(pid);
    gemm_f16_kernel<<<dim3(QKVN / BN, Mrows / BM), 256, GEMM_SMEM>>>(
        px, pwq, nullptr, Mrows, QKVN, Dd, 0, nullptr);
    attn_kernel<<<NQT * Hh * Bb, 256, ATTN_SMEM>>>(am);
    gemm_f16_kernel<<<dim3(Dd / BN, Mrows / BM), 256, GEMM_SMEM>>>(
        pattn, pwo, out, Mrows, Dd, Dd, 1, hs);
    ln_kernel<<<Mrows, 256>>>(out, ln2, out + OUTOFF, 0);
}

// round 15
// speedup vs baseline: 18.1975x; 1.0296x over previous
#include <cuda_runtime.h>
#include <cuda_fp16.h>
#include <math.h>
#include <stdint.h>

#define Bb    2
#define Ss    2048
#define Dd    2048
#define Hh    32
#define KVHh  8
#define HDd   64
#define QKVN  3072
#define Mrows (Bb*Ss)
#define OUTOFF ((size_t)Bb*Ss*Dd)
#define ATT_SCALE 0.125f

// ---------------- scratch ----------------------------------------------------
__device__ __half g_x[(size_t)Mrows*Dd];
__device__ __half g_q[(size_t)Bb*Hh*Ss*HDd];
__device__ __half g_k[(size_t)Bb*KVHh*Ss*HDd];
__device__ __half g_v[(size_t)Bb*KVHh*Ss*HDd];
__device__ __half g_attn[(size_t)Mrows*Dd];
__device__ __half g_wqkvh[(size_t)Dd*QKVN];
__device__ __half g_wouth[(size_t)Dd*Dd];
__device__ float g_cos[(size_t)Bb*Ss*32];
__device__ float g_sin[(size_t)Bb*Ss*32];

__device__ __forceinline__ uint32_t pkh2(float x, float y) {
    __half2 h = __floats2half2_rn(x, y);
    return *(uint32_t*)&h;
}
__device__ __forceinline__ void mma_f16(float c[4], uint32_t a0, uint32_t a1,
                                        uint32_t a2, uint32_t a3,
                                        uint32_t b0, uint32_t b1)
{
    asm volatile(
        "mma.sync.aligned.m16n8k16.row.col.f32.f16.f16.f32 "
        "{%0,%1,%2,%3}, {%4,%5,%6,%7}, {%8,%9}, {%0,%1,%2,%3};"
        : "+f"(c[0]), "+f"(c[1]), "+f"(c[2]), "+f"(c[3])
        : "r"(a0), "r"(a1), "r"(a2), "r"(a3), "r"(b0), "r"(b1));
}
__device__ __forceinline__ void ldsm4(uint32_t& r0, uint32_t& r1,
                                      uint32_t& r2, uint32_t& r3, uint32_t saddr)
{
    asm volatile(
        "ldmatrix.sync.aligned.m8n8.x4.shared.b16 {%0,%1,%2,%3}, [%4];"
        : "=r"(r0), "=r"(r1), "=r"(r2), "=r"(r3) : "r"(saddr));
}
__device__ __forceinline__ void ldsm4t(uint32_t& r0, uint32_t& r1,
                                       uint32_t& r2, uint32_t& r3, uint32_t saddr)
{
    asm volatile(
        "ldmatrix.sync.aligned.m8n8.x4.trans.shared.b16 {%0,%1,%2,%3}, [%4];"
        : "=r"(r0), "=r"(r1), "=r"(r2), "=r"(r3) : "r"(saddr));
}
__device__ __forceinline__ void cpa16(uint32_t smem_addr, const void* gptr) {
    asm volatile("cp.async.cg.shared.global [%0], [%1], 16;"
                 :: "r"(smem_addr), "l"(gptr));
}
__device__ __forceinline__ void cpa4(uint32_t smem_addr, const void* gptr) {
    asm volatile("cp.async.ca.shared.global [%0], [%1], 4;"
                 :: "r"(smem_addr), "l"(gptr));
}
__device__ __forceinline__ void cpa_commit() {
    asm volatile("cp.async.commit_group;");
}
template<int N>
__device__ __forceinline__ void cpa_wait() {
    asm volatile("cp.async.wait_group %0;" :: "n"(N));
}
__device__ __forceinline__ float clip8(float v) {
    return fminf(fmaxf(v, -8.f), 8.f);
}

// ---------------- fused prep: LN1 + rope table + weight cvt -------------------
// blocks [0, Mrows)                 : LN1 rows (half out -> g_x)
// blocks [Mrows, Mrows+512)         : rope cos/sin table
// blocks [Mrows+512, Mrows+512+NC)  : weight fp32->fp16 conversion
#define NCVT ((Dd*QKVN/4 + Dd*Dd/4) / 256)   // 10240
__global__ __launch_bounds__(256) void prep_kernel(
    const float* __restrict__ hs, const float* __restrict__ ln1,
    const int* __restrict__ pid,
    const float* __restrict__ wqkv, const float* __restrict__ wout)
{
    int bid = blockIdx.x;
    if (bid < Mrows) {
        // ---- LN1 ----
        int row = bid;
        const float4* x4 = (const float4*)(hs + (size_t)row * Dd);
        float s = 0.f, s2 = 0.f;
        float4 v[2];
        #pragma unroll
        for (int i = 0; i < 2; i++) {
            v[i] = x4[threadIdx.x + i * 256];
            s  += v[i].x + v[i].y + v[i].z + v[i].w;
            s2 += v[i].x*v[i].x + v[i].y*v[i].y + v[i].z*v[i].z + v[i].w*v[i].w;
        }
        #pragma unroll
        for (int o = 16; o; o >>= 1) {
            s  += __shfl_xor_sync(0xffffffffu, s,  o);
            s2 += __shfl_xor_sync(0xffffffffu, s2, o);
        }
        __shared__ float ws[8], ws2[8];
        int w = threadIdx.x >> 5, l = threadIdx.x & 31;
        if (l == 0) { ws[w] = s; ws2[w] = s2; }
        __syncthreads();
        if (threadIdx.x < 32) {
            s  = (l < 8) ? ws[l]  : 0.f;
            s2 = (l < 8) ? ws2[l] : 0.f;
            #pragma unroll
            for (int o = 4; o; o >>= 1) {
                s  += __shfl_xor_sync(0xffffffffu, s,  o);
                s2 += __shfl_xor_sync(0xffffffffu, s2, o);
            }
            if (l == 0) { ws[0] = s; ws2[0] = s2; }
        }
        __syncthreads();
        float mean = ws[0] * (1.f / Dd);
        float var  = ws2[0] * (1.f / Dd) - mean * mean;
        float inv  = rsqrtf(var + 1e-6f);
        __half* o_ = g_x + (size_t)row * Dd;
        #pragma unroll
        for (int i = 0; i < 2; i++) {
            int c = (threadIdx.x + i * 256) * 4;
            const float4 sv = *(const float4*)(ln1 + c);
            uint32_t p0 = pkh2((v[i].x - mean) * inv * sv.x,
                               (v[i].y - mean) * inv * sv.y);
            uint32_t p1 = pkh2((v[i].z - mean) * inv * sv.z,
                               (v[i].w - mean) * inv * sv.w);
            uint2 pk; pk.x = p0; pk.y = p1;
            *(uint2*)(o_ + c) = pk;
        }
    } else if (bid < Mrows + 512) {
        // ---- rope table ----
        __shared__ double sInv[32];
        if (threadIdx.x < 32) {
            int i = threadIdx.x;
            sInv[i] = exp(-((double)(2 * i) / 64.0) * log(500000.0));
        }
        __syncthreads();
        int idx = (bid - Mrows) * 256 + threadIdx.x;
        int i = idx & 31;
        int s = (idx >> 5) & (Ss - 1);
        int b = idx >> 16;
        double pos = (double)pid[b * Ss + s];
        double ang = pos * sInv[i];
        double k = rint(ang * 0.15915494309189535);
        float r = (float)(ang - k * 6.283185307179586);
        g_cos[idx] = cosf(r);
        g_sin[idx] = sinf(r);
    } else {
        // ---- weight conversion ----
        int i = (bid - Mrows - 512) * 256 + threadIdx.x;
        int n1 = Dd * QKVN / 4;
        const float* src; __half* dst;
        if (i < n1) { src = wqkv + (size_t)i * 4; dst = g_wqkvh + (size_t)i * 4; }
        else {
            i -= n1;
            src = wout + (size_t)i * 4; dst = g_wouth + (size_t)i * 4;
        }
        float4 v = *(const float4*)src;
        uint32_t* d = (uint32_t*)dst;
        d[0] = pkh2(v.x, v.y);
        d[1] = pkh2(v.z, v.w);
    }
}

// ---------------- LayerNorm (fp32 out; used for LN2) ---------------------------
__global__ __launch_bounds__(256) void ln_kernel(
    const float* __restrict__ in, const float* __restrict__ sc,
    float* __restrict__ outp)
{
    int row = blockIdx.x;
    const float4* x4 = (const float4*)(in + (size_t)row * Dd);
    float s = 0.f, s2 = 0.f;
    float4 v[2];
    #pragma unroll
    for (int i = 0; i < 2; i++) {
        v[i] = x4[threadIdx.x + i * 256];
        s  += v[i].x + v[i].y + v[i].z + v[i].w;
        s2 += v[i].x*v[i].x + v[i].y*v[i].y + v[i].z*v[i].z + v[i].w*v[i].w;
    }
    #pragma unroll
    for (int o = 16; o; o >>= 1) {
        s  += __shfl_xor_sync(0xffffffffu, s,  o);
        s2 += __shfl_xor_sync(0xffffffffu, s2, o);
    }
    __shared__ float ws[8], ws2[8];
    int w = threadIdx.x >> 5, l = threadIdx.x & 31;
    if (l == 0) { ws[w] = s; ws2[w] = s2; }
    __syncthreads();
    if (threadIdx.x < 32) {
        s  = (l < 8) ? ws[l]  : 0.f;
        s2 = (l < 8) ? ws2[l] : 0.f;
        #pragma unroll
        for (int o = 4; o; o >>= 1) {
            s  += __shfl_xor_sync(0xffffffffu, s,  o);
            s2 += __shfl_xor_sync(0xffffffffu, s2, o);
        }
        if (l == 0) { ws[0] = s; ws2[0] = s2; }
    }
    __syncthreads();
    float mean = ws[0] * (1.f / Dd);
    float var  = ws2[0] * (1.f / Dd) - mean * mean;
    float inv  = rsqrtf(var + 1e-6f);
    #pragma unroll
    for (int i = 0; i < 2; i++) {
        int c = (threadIdx.x + i * 256) * 4;
        const float4 sv = *(const float4*)(sc + c);
        float4 ov;
        ov.x = (v[i].x - mean) * inv * sv.x;
        ov.y = (v[i].y - mean) * inv * sv.y;
        ov.z = (v[i].z - mean) * inv * sv.z;
        ov.w = (v[i].w - mean) * inv * sv.w;
        *(float4*)(outp + (size_t)row * Dd + c) = ov;
    }
}

// ---------------- FP16 GEMM 128x128x64, 3-stage cp.async ----------------------
#define BM 128
#define BN 128
#define BK 64
#define AS_U 36
#define AS_U32S (BM * AS_U)
#define BS_U32S (BK * 64)
#define STAGE_U (AS_U32S + BS_U32S)
#define NSTG 3

__global__ __launch_bounds__(256, 2) void gemm_f16_kernel(
    const __half* __restrict__ A, const __half* __restrict__ Bw,
    void* __restrict__ Cp, int M, int N, int K, int mode,
    const float* __restrict__ resid)
{
    extern __shared__ uint32_t smu[];
    int row0 = blockIdx.y * BM, col0 = blockIdx.x * BN;
    int t = threadIdx.x;
    int w = t >> 5, l = t & 31;
    int warpM = w >> 1, warpN = w & 1;
    int lr = l >> 2, lc = l & 3;

    const uint4* Au = (const uint4*)A;
    const uint4* Bu = (const uint4*)Bw;
    int K8 = K >> 3, N8 = N >> 3;

    uint32_t smuBase = (uint32_t)__cvta_generic_to_shared(smu);
    int bC0 = (col0 >> 3);

    float acc[2][8][4];
    #pragma unroll
    for (int mf = 0; mf < 2; mf++)
        #pragma unroll
        for (int nf = 0; nf < 8; nf++)
            #pragma unroll
            for (int r = 0; r < 4; r++) acc[mf][nf][r] = 0.f;

    int nk = K / BK;
    auto issue = [&](int kt, int stg) {
        if (kt < nk) {
            int k0 = kt * BK;
            uint32_t aBase = smuBase + stg * STAGE_U * 4;
            uint32_t bBase = aBase + AS_U32S * 4;
            #pragma unroll
            for (int i = 0; i < 4; i++) {
                int idx = i * 256 + t;
                int ar = idx >> 3, ac = idx & 7;
                cpa16(aBase + (ar * AS_U + ac * 4) * 4,
                      Au + (size_t)(row0 + ar) * K8 + (k0 >> 3) + ac);
                int bk = idx >> 4, bc = idx & 15;
                cpa16(bBase + (bk * 64 + ((bc * 4) ^ ((bk & 7) << 2))) * 4,
                      Bu + (size_t)(k0 + bk) * N8 + bC0 + bc);
            }
        }
        cpa_commit();
    };

    issue(0, 0);
    issue(1, 1);

    int aLdsmRow = l & 15;
    int aLdsmCol = (l >> 4) << 2;

    for (int kt = 0; kt < nk; kt++) {
        cpa_wait<1>();
        __syncthreads();
        issue(kt + 2, (kt + 2) % NSTG);

        uint32_t asAddr = smuBase + (kt % NSTG) * STAGE_U * 4;
        uint32_t bsAddr = asAddr + AS_U32S * 4;
        #pragma unroll
        for (int ks = 0; ks < 4; ks++) {
            uint32_t af[2][4];
            #pragma unroll
            for (int mf = 0; mf < 2; mf++) {
                int r = warpM * 32 + mf * 16;
                ldsm4(af[mf][0], af[mf][1], af[mf][2], af[mf][3],
                      asAddr + ((r + aLdsmRow) * AS_U + ks * 8 + aLdsmCol) * 4);
            }
            #pragma unroll
            for (int nfp = 0; nfp < 4; nfp++) {
                int krow = ks * 16 + (l & 15);
                int col = warpN * 32 + nfp * 8 + ((l >> 4) << 2);
                col ^= (krow & 7) << 2;
                uint32_t b0, b1, b2, b3;
                ldsm4t(b0, b1, b2, b3, bsAddr + (krow * 64 + col) * 4);
                #pragma unroll
                for (int mf = 0; mf < 2; mf++) {
                    mma_f16(acc[mf][2*nfp],   af[mf][0], af[mf][1], af[mf][2], af[mf][3], b0, b1);
                    mma_f16(acc[mf][2*nfp+1], af[mf][0], af[mf][1], af[mf][2], af[mf][3], b2, b3);
                }
            }
        }
    }

    if (mode == 0) {
        int gcol = col0 + warpN * 64;
        int isV = (gcol >= Dd + KVHh * HDd);
        int isK = (gcol >= Dd) && !isV;
        int headIdx;
        if (isV)      headIdx = (gcol - Dd - KVHh * HDd) >> 6;
        else if (isK) headIdx = (gcol - Dd) >> 6;
        else          headIdx = gcol >> 6;
        #pragma unroll
        for (int mf = 0; mf < 2; mf++) {
            #pragma unroll
            for (int half = 0; half < 2; half++) {
                int row = row0 + warpM * 32 + mf * 16 + lr + half * 8;
                int s_ = row & (Ss - 1), b_ = row >> 11;
                __half* dst;
                if (isV)
                    dst = g_v + ((size_t)(b_ * KVHh + headIdx) * Ss + s_) * HDd;
                else if (isK)
                    dst = g_k + ((size_t)(b_ * KVHh + headIdx) * Ss + s_) * HDd;
                else
                    dst = g_q + ((size_t)(b_ * Hh + headIdx) * Ss + s_) * HDd;
                const float* cosb = g_cos + ((size_t)b_ << 16) + (s_ << 5);
                const float* sinb = g_sin + ((size_t)b_ << 16) + (s_ << 5);
                #pragma unroll
                for (int nf = 0; nf < 4; nf++) {
                    int c0 = nf * 8 + 2 * lc;
                    float x1a = clip8(acc[mf][nf][half * 2 + 0]);
                    float x1b = clip8(acc[mf][nf][half * 2 + 1]);
                    float x2a = clip8(acc[mf][nf + 4][half * 2 + 0]);
                    float x2b = clip8(acc[mf][nf + 4][half * 2 + 1]);
                    if (isV) {
                        *(uint32_t*)(dst + c0)      = pkh2(x1a, x1b);
                        *(uint32_t*)(dst + c0 + 32) = pkh2(x2a, x2b);
                    } else {
                        float ca = cosb[c0], cb = cosb[c0 + 1];
                        float sa = sinb[c0], sb = sinb[c0 + 1];
                        *(uint32_t*)(dst + c0) =
                            pkh2(x1a * ca - x2a * sa, x1b * cb - x2b * sb);
                        *(uint32_t*)(dst + c0 + 32) =
                            pkh2(x2a * ca + x1a * sa, x2b * cb + x1b * sb);
                    }
                }
            }
        }
    } else {
        #pragma unroll
        for (int mf = 0; mf < 2; mf++) {
            #pragma unroll
            for (int half = 0; half < 2; half++) {
                int row = row0 + warpM * 32 + mf * 16 + lr + half * 8;
                #pragma unroll
                for (int nf = 0; nf < 8; nf++) {
                    int col = col0 + warpN * 64 + nf * 8 + 2 * lc;
                    size_t off = (size_t)row * N + col;
                    float2 rv = *(const float2*)(resid + off);
                    float2 v;
                    v.x = acc[mf][nf][half * 2 + 0] + rv.x;
                    v.y = acc[mf][nf][half * 2 + 1] + rv.y;
                    *(float2*)((float*)Cp + off) = v;
                }
            }
        }
    }
}

// ---------------- FP16 flash attention, 128-key macro-tiles, 3 stages ----------
#define KS_U 36
#define VS_U 32
#define NAS  3
#define KT_ROWS 128
#define SM_KS 0
#define SM_VS (NAS * KT_ROWS * KS_U)
#define SM_MASK (SM_VS + NAS * KT_ROWS * VS_U)
#define ATT_U32 (SM_MASK + NAS * KT_ROWS)
#define QP_U 36
#define NQT (Ss / 128)
__global__ __launch_bounds__(256, 2) void attn_kernel(const int* __restrict__ amask)
{
    extern __shared__ uint32_t smu[];
    uint32_t* Ps = smu;
    int* maskS = (int*)(smu + SM_MASK);

    int bid = blockIdx.x;
    int qt = (NQT - 1) - (bid >> 6);
    int rem = bid & 63;
    int h = rem >> 1;
    int b = rem & 1;
    int kvh = h >> 2;
    int q0 = qt * 128;
    int t = threadIdx.x;
    int w = t >> 5, l = t & 31;
    int lr = l >> 2, lc = l & 3;

    const uint4* Qg = (const uint4*)(g_q + ((size_t)(b * Hh + h) * Ss + q0) * HDd);
    const uint4* Kg = (const uint4*)(g_k + (size_t)(b * KVHh + kvh) * Ss * HDd);
    const uint4* Vg = (const uint4*)(g_v + (size_t)(b * KVHh + kvh) * Ss * HDd);
    const int*   Mg = amask + b * Ss;

    uint32_t smuBase = (uint32_t)__cvta_generic_to_shared(smu);

    #pragma unroll
    for (int i = 0; i < 4; i++) {
        int idx = i * 256 + t;
        int row = idx >> 3, c = idx & 7;
        *(uint4*)&Ps[row * QP_U + c * 4] = Qg[row * 8 + c];
    }
    __syncthreads();
    uint32_t qa[4][4];
    {
        int r0 = w * 16 + lr;
        #pragma unroll
        for (int ks = 0; ks < 4; ks++) {
            qa[ks][0] = Ps[r0 * QP_U + ks * 8 + lc];
            qa[ks][1] = Ps[(r0 + 8) * QP_U + ks * 8 + lc];
            qa[ks][2] = Ps[r0 * QP_U + ks * 8 + lc + 4];
            qa[ks][3] = Ps[(r0 + 8) * QP_U + ks * 8 + lc + 4];
        }
    }
    __syncthreads();

    int nkt = qt + 1;
    auto issueKV = [&](int kt, int stg) {
        if (kt < nkt) {
            int k0 = kt * KT_ROWS;
            uint32_t kBase = smuBase + (SM_KS + stg * KT_ROWS * KS_U) * 4;
            uint32_t vBase = smuBase + (SM_VS + stg * KT_ROWS * VS_U) * 4;
            #pragma unroll
            for (int i = 0; i < 4; i++) {
                int idx = i * 256 + t;
                int row = idx >> 3, c = idx & 7;
                cpa16(kBase + (row * KS_U + c * 4) * 4, Kg + (k0 + row) * 8 + c);
                cpa16(vBase + (row * VS_U + ((c * 4) ^ ((row & 7) << 2))) * 4,
                      Vg + (k0 + row) * 8 + c);
            }
            if (t < KT_ROWS)
                cpa4(smuBase + (SM_MASK + stg * KT_ROWS + t) * 4, Mg + k0 + t);
        }
        cpa_commit();
    };

    issueKV(0, 0);
    issueKV(1, 1);

    float m0 = -1e30f, m1 = -1e30f, l0 = 0.f, l1 = 0.f;
    float o[8][4];
    #pragma unroll
    for (int nf = 0; nf < 8; nf++)
        #pragma unroll
        for (int r = 0; r < 4; r++) o[nf][r] = 0.f;

    int kLdsmRow = l & 15;
    int kLdsmCol = (l >> 4) << 2;
    int qlow = q0 + w * 16;

    for (int kt = 0; kt < nkt; kt++) {
        cpa_wait<1>();
        __syncthreads();

        int cur = kt % NAS;
        uint32_t kbAddr = smuBase + (SM_KS + cur * KT_ROWS * KS_U) * 4;
        uint32_t vsAddr = smuBase + (SM_VS + cur * KT_ROWS * VS_U) * 4;

        #pragma unroll
        for (int half = 0; half < 2; half++) {
            // prefetch spread: issue next macro-tile between the two halves
            if (half == 1) issueKV(kt + 2, (kt + 2) % NAS);

            int k0 = kt * KT_ROWS + half * 64;
            if (k0 <= qlow + 15) {
                int rbase = half * 64;
                float s[8][4];
                #pragma unroll
                for (int nf = 0; nf < 8; nf++)
                    #pragma unroll
                    for (int r = 0; r < 4; r++) s[nf][r] = 0.f;
                #pragma unroll
                for (int ks = 0; ks < 4; ks++) {
                    #pragma unroll
                    for (int p = 0; p < 4; p++) {
                        uint32_t b0, b1, b2, b3;
                        ldsm4(b0, b1, b2, b3,
                              kbAddr + ((rbase + p * 16 + kLdsmRow) * KS_U
                                        + ks * 8 + kLdsmCol) * 4);
                        mma_f16(s[2*p],   qa[ks][0], qa[ks][1], qa[ks][2], qa[ks][3], b0, b2);
                        mma_f16(s[2*p+1], qa[ks][0], qa[ks][1], qa[ks][2], qa[ks][3], b1, b3);
                    }
                }
                int qr0 = qlow + lr, qr1 = qr0 + 8;
                bool fullvis = (k0 + 63 <= qlow);
                int mbase = cur * KT_ROWS + rbase;
                #pragma unroll
                for (int nf = 0; nf < 8; nf++) {
                    int kg0 = k0 + nf * 8 + 2 * lc;
                    int ms0 = maskS[mbase + nf * 8 + 2 * lc];
                    int ms1 = maskS[mbase + nf * 8 + 2 * lc + 1];
                    s[nf][0] = (ms0 && (fullvis || kg0     <= qr0)) ? s[nf][0] * ATT_SCALE : -1e30f;
                    s[nf][1] = (ms1 && (fullvis || kg0 + 1 <= qr0)) ? s[nf][1] * ATT_SCALE : -1e30f;
                    s[nf][2] = (ms0 && (fullvis || kg0     <= qr1)) ? s[nf][2] * ATT_SCALE : -1e30f;
                    s[nf][3] = (ms1 && (fullvis || kg0 + 1 <= qr1)) ? s[nf][3] * ATT_SCALE : -1e30f;
                }
                float mt0 = -1e30f, mt1 = -1e30f;
                #pragma unroll
                for (int nf = 0; nf < 8; nf++) {
                    mt0 = fmaxf(mt0, fmaxf(s[nf][0], s[nf][1]));
                    mt1 = fmaxf(mt1, fmaxf(s[nf][2], s[nf][3]));
                }
                mt0 = fmaxf(mt0, __shfl_xor_sync(0xffffffffu, mt0, 1));
                mt0 = fmaxf(mt0, __shfl_xor_sync(0xffffffffu, mt0, 2));
                mt1 = fmaxf(mt1, __shfl_xor_sync(0xffffffffu, mt1, 1));
                mt1 = fmaxf(mt1, __shfl_xor_sync(0xffffffffu, mt1, 2));
                float mn0 = fmaxf(m0, mt0), mn1 = fmaxf(m1, mt1);
                float rs0 = 0.f, rs1 = 0.f;
                #pragma unroll
                for (int nf = 0; nf < 8; nf++) {
                    s[nf][0] = __expf(s[nf][0] - mn0);
                    s[nf][1] = __expf(s[nf][1] - mn0);
                    s[nf][2] = __expf(s[nf][2] - mn1);
                    s[nf][3] = __expf(s[nf][3] - mn1);
                    rs0 += s[nf][0] + s[nf][1];
                    rs1 += s[nf][2] + s[nf][3];
                }
                rs0 += __shfl_xor_sync(0xffffffffu, rs0, 1);
                rs0 += __shfl_xor_sync(0xffffffffu, rs0, 2);
                rs1 += __shfl_xor_sync(0xffffffffu, rs1, 1);
                rs1 += __shfl_xor_sync(0xffffffffu, rs1, 2);
                float a0 = __expf(m0 - mn0), a1 = __expf(m1 - mn1);
                l0 = l0 * a0 + rs0;  l1 = l1 * a1 + rs1;
                m0 = mn0;  m1 = mn1;
                #pragma unroll
                for (int nf = 0; nf < 8; nf++) {
                    o[nf][0] *= a0; o[nf][1] *= a0;
                    o[nf][2] *= a1; o[nf][3] *= a1;
                }
                #pragma unroll
                for (int ks = 0; ks < 4; ks++) {
                    uint32_t pa0 = pkh2(s[2*ks][0],   s[2*ks][1]);
                    uint32_t pa1 = pkh2(s[2*ks][2],   s[2*ks][3]);
                    uint32_t pa2 = pkh2(s[2*ks+1][0], s[2*ks+1][1]);
                    uint32_t pa3 = pkh2(s[2*ks+1][2], s[2*ks+1][3]);
                    #pragma unroll
                    for (int nfp = 0; nfp < 4; nfp++) {
                        int key = rbase + ks * 16 + (l & 15);
                        int col = nfp * 8 + ((l >> 4) << 2);
                        col ^= (key & 7) << 2;
                        uint32_t b0, b1, b2, b3;
                        ldsm4t(b0, b1, b2, b3, vsAddr + (key * VS_U + col) * 4);
                        mma_f16(o[2*nfp],   pa0, pa1, pa2, pa3, b0, b1);
                        mma_f16(o[2*nfp+1], pa0, pa1, pa2, pa3, b2, b3);
                    }
                }
            }
        }
    }

    float il0 = (l0 > 0.f) ? (1.f / l0) : 0.f;
    float il1 = (l1 > 0.f) ? (1.f / l1) : 0.f;
    int qr0 = q0 + w * 16 + lr;
    __half* d0 = g_attn + (size_t)(b * Ss + qr0) * Dd + h * HDd;
    __half* d1 = g_attn + (size_t)(b * Ss + qr0 + 8) * Dd + h * HDd;
    #pragma unroll
    for (int nf = 0; nf < 8; nf++) {
        int c = nf * 8 + 2 * lc;
        *(uint32_t*)(d0 + c) = pkh2(o[nf][0] * il0, o[nf][1] * il0);
        *(uint32_t*)(d1 + c) = pkh2(o[nf][2] * il1, o[nf][3] * il1);
    }
}

// ---------------- launch ------------------------------------------------------
extern "C" void kernel_launch(void* const* d_in, const int* in_sizes, int n_in,
                              void* d_out, int out_size)
{
    const float* hs   = (const float*)d_in[0];
    const int*   am   = (const int*)  d_in[1];
    const int*   pid  = (const int*)  d_in[2];
    const float* ln1  = (const float*)d_in[4];
    const float* wqkv = (const float*)d_in[5];
    const float* wout = (const float*)d_in[6];
    const float* ln2  = (const float*)d_in[7];
    float* out = (float*)d_out;

    __half *px, *pattn, *pwq, *pwo;
    cudaGetSymbolAddress((void**)&px,    g_x);
    cudaGetSymbolAddress((void**)&pattn, g_attn);
    cudaGetSymbolAddress((void**)&pwq,   g_wqkvh);
    cudaGetSymbolAddress((void**)&pwo,   g_wouth);

    const int ATTN_SMEM = ATT_U32 * 4;
    cudaFuncSetAttribute(attn_kernel,
                         cudaFuncAttributeMaxDynamicSharedMemorySize, ATTN_SMEM);
    const int GEMM_SMEM = NSTG * STAGE_U * 4;
    cudaFuncSetAttribute(gemm_f16_kernel,
                         cudaFuncAttributeMaxDynamicSharedMemorySize, GEMM_SMEM);

    // fused LN1 + rope table + weight conversion
    prep_kernel<<<Mrows + 512 + NCVT, 256>>>(hs, ln1, pid, wqkv, wout);
    gemm_f16_kernel<<<dim3(QKVN / BN, Mrows / BM), 256, GEMM_SMEM>>>(
        px, pwq, nullptr, Mrows, QKVN, Dd, 0, nullptr);
    attn_kernel<<<NQT * Hh * Bb, 256, ATTN_SMEM>>>(am);
    gemm_f16_kernel<<<dim3(Dd / BN, Mrows / BM), 256, GEMM_SMEM>>>(
        pattn, pwo, out, Mrows, Dd, Dd, 1, hs);
    ln_kernel<<<Mrows, 256>>>(out, ln2, out + OUTOFF);
}

// round 16
// speedup vs baseline: 18.4336x; 1.0130x over previous
#include <cuda_runtime.h>
#include <cuda_fp16.h>
#include <math.h>
#include <stdint.h>

#define Bb    2
#define Ss    2048
#define Dd    2048
#define Hh    32
#define KVHh  8
#define HDd   64
#define QKVN  3072
#define Mrows (Bb*Ss)
#define OUTOFF ((size_t)Bb*Ss*Dd)
#define ATT_SCALE 0.125f

// ---------------- scratch ----------------------------------------------------
__device__ __half g_x[(size_t)Mrows*Dd];
__device__ __half g_q[(size_t)Bb*Hh*Ss*HDd];
__device__ __half g_k[(size_t)Bb*KVHh*Ss*HDd];
__device__ __half g_v[(size_t)Bb*KVHh*Ss*HDd];
__device__ __half g_attn[(size_t)Mrows*Dd];
__device__ __half g_wqkvh[(size_t)Dd*QKVN];
__device__ __half g_wouth[(size_t)Dd*Dd];
__device__ float g_cos[(size_t)Bb*Ss*32];
__device__ float g_sin[(size_t)Bb*Ss*32];

__device__ __forceinline__ uint32_t pkh2(float x, float y) {
    __half2 h = __floats2half2_rn(x, y);
    return *(uint32_t*)&h;
}
__device__ __forceinline__ void mma_f16(float c[4], uint32_t a0, uint32_t a1,
                                        uint32_t a2, uint32_t a3,
                                        uint32_t b0, uint32_t b1)
{
    asm volatile(
        "mma.sync.aligned.m16n8k16.row.col.f32.f16.f16.f32 "
        "{%0,%1,%2,%3}, {%4,%5,%6,%7}, {%8,%9}, {%0,%1,%2,%3};"
        : "+f"(c[0]), "+f"(c[1]), "+f"(c[2]), "+f"(c[3])
        : "r"(a0), "r"(a1), "r"(a2), "r"(a3), "r"(b0), "r"(b1));
}
__device__ __forceinline__ void ldsm4(uint32_t& r0, uint32_t& r1,
                                      uint32_t& r2, uint32_t& r3, uint32_t saddr)
{
    asm volatile(
        "ldmatrix.sync.aligned.m8n8.x4.shared.b16 {%0,%1,%2,%3}, [%4];"
        : "=r"(r0), "=r"(r1), "=r"(r2), "=r"(r3) : "r"(saddr));
}
__device__ __forceinline__ void ldsm4t(uint32_t& r0, uint32_t& r1,
                                       uint32_t& r2, uint32_t& r3, uint32_t saddr)
{
    asm volatile(
        "ldmatrix.sync.aligned.m8n8.x4.trans.shared.b16 {%0,%1,%2,%3}, [%4];"
        : "=r"(r0), "=r"(r1), "=r"(r2), "=r"(r3) : "r"(saddr));
}
__device__ __forceinline__ void cpa16(uint32_t smem_addr, const void* gptr) {
    asm volatile("cp.async.cg.shared.global [%0], [%1], 16;"
                 :: "r"(smem_addr), "l"(gptr));
}
__device__ __forceinline__ void cpa4(uint32_t smem_addr, const void* gptr) {
    asm volatile("cp.async.ca.shared.global [%0], [%1], 4;"
                 :: "r"(smem_addr), "l"(gptr));
}
__device__ __forceinline__ void cpa_commit() {
    asm volatile("cp.async.commit_group;");
}
template<int N>
__device__ __forceinline__ void cpa_wait() {
    asm volatile("cp.async.wait_group %0;" :: "n"(N));
}
__device__ __forceinline__ float clip8(float v) {
    return fminf(fmaxf(v, -8.f), 8.f);
}

// ---------------- fused prep: LN1 + rope table + weight cvt -------------------
#define NCVT ((Dd*QKVN/4 + Dd*Dd/4) / 256)   // 10240
__global__ __launch_bounds__(256) void prep_kernel(
    const float* __restrict__ hs, const float* __restrict__ ln1,
    const int* __restrict__ pid,
    const float* __restrict__ wqkv, const float* __restrict__ wout)
{
    int bid = blockIdx.x;
    if (bid < Mrows) {
        int row = bid;
        const float4* x4 = (const float4*)(hs + (size_t)row * Dd);
        float s = 0.f, s2 = 0.f;
        float4 v[2];
        #pragma unroll
        for (int i = 0; i < 2; i++) {
            v[i] = x4[threadIdx.x + i * 256];
            s  += v[i].x + v[i].y + v[i].z + v[i].w;
            s2 += v[i].x*v[i].x + v[i].y*v[i].y + v[i].z*v[i].z + v[i].w*v[i].w;
        }
        #pragma unroll
        for (int o = 16; o; o >>= 1) {
            s  += __shfl_xor_sync(0xffffffffu, s,  o);
            s2 += __shfl_xor_sync(0xffffffffu, s2, o);
        }
        __shared__ float ws[8], ws2[8];
        int w = threadIdx.x >> 5, l = threadIdx.x & 31;
        if (l == 0) { ws[w] = s; ws2[w] = s2; }
        __syncthreads();
        if (threadIdx.x < 32) {
            s  = (l < 8) ? ws[l]  : 0.f;
            s2 = (l < 8) ? ws2[l] : 0.f;
            #pragma unroll
            for (int o = 4; o; o >>= 1) {
                s  += __shfl_xor_sync(0xffffffffu, s,  o);
                s2 += __shfl_xor_sync(0xffffffffu, s2, o);
            }
            if (l == 0) { ws[0] = s; ws2[0] = s2; }
        }
        __syncthreads();
        float mean = ws[0] * (1.f / Dd);
        float var  = ws2[0] * (1.f / Dd) - mean * mean;
        float inv  = rsqrtf(var + 1e-6f);
        __half* o_ = g_x + (size_t)row * Dd;
        #pragma unroll
        for (int i = 0; i < 2; i++) {
            int c = (threadIdx.x + i * 256) * 4;
            const float4 sv = *(const float4*)(ln1 + c);
            uint32_t p0 = pkh2((v[i].x - mean) * inv * sv.x,
                               (v[i].y - mean) * inv * sv.y);
            uint32_t p1 = pkh2((v[i].z - mean) * inv * sv.z,
                               (v[i].w - mean) * inv * sv.w);
            uint2 pk; pk.x = p0; pk.y = p1;
            *(uint2*)(o_ + c) = pk;
        }
    } else if (bid < Mrows + 512) {
        __shared__ double sInv[32];
        if (threadIdx.x < 32) {
            int i = threadIdx.x;
            sInv[i] = exp(-((double)(2 * i) / 64.0) * log(500000.0));
        }
        __syncthreads();
        int idx = (bid - Mrows) * 256 + threadIdx.x;
        int i = idx & 31;
        int s = (idx >> 5) & (Ss - 1);
        int b = idx >> 16;
        double pos = (double)pid[b * Ss + s];
        double ang = pos * sInv[i];
        double k = rint(ang * 0.15915494309189535);
        float r = (float)(ang - k * 6.283185307179586);
        g_cos[idx] = cosf(r);
        g_sin[idx] = sinf(r);
    } else {
        int i = (bid - Mrows - 512) * 256 + threadIdx.x;
        int n1 = Dd * QKVN / 4;
        const float* src; __half* dst;
        if (i < n1) { src = wqkv + (size_t)i * 4; dst = g_wqkvh + (size_t)i * 4; }
        else {
            i -= n1;
            src = wout + (size_t)i * 4; dst = g_wouth + (size_t)i * 4;
        }
        float4 v = *(const float4*)src;
        uint32_t* d = (uint32_t*)dst;
        d[0] = pkh2(v.x, v.y);
        d[1] = pkh2(v.z, v.w);
    }
}

// ---------------- LayerNorm (fp32 out; LN2) ------------------------------------
__global__ __launch_bounds__(256) void ln_kernel(
    const float* __restrict__ in, const float* __restrict__ sc,
    float* __restrict__ outp)
{
    int row = blockIdx.x;
    const float4* x4 = (const float4*)(in + (size_t)row * Dd);
    float s = 0.f, s2 = 0.f;
    float4 v[2];
    #pragma unroll
    for (int i = 0; i < 2; i++) {
        v[i] = x4[threadIdx.x + i * 256];
        s  += v[i].x + v[i].y + v[i].z + v[i].w;
        s2 += v[i].x*v[i].x + v[i].y*v[i].y + v[i].z*v[i].z + v[i].w*v[i].w;
    }
    #pragma unroll
    for (int o = 16; o; o >>= 1) {
        s  += __shfl_xor_sync(0xffffffffu, s,  o);
        s2 += __shfl_xor_sync(0xffffffffu, s2, o);
    }
    __shared__ float ws[8], ws2[8];
    int w = threadIdx.x >> 5, l = threadIdx.x & 31;
    if (l == 0) { ws[w] = s; ws2[w] = s2; }
    __syncthreads();
    if (threadIdx.x < 32) {
        s  = (l < 8) ? ws[l]  : 0.f;
        s2 = (l < 8) ? ws2[l] : 0.f;
        #pragma unroll
        for (int o = 4; o; o >>= 1) {
            s  += __shfl_xor_sync(0xffffffffu, s,  o);
            s2 += __shfl_xor_sync(0xffffffffu, s2, o);
        }
        if (l == 0) { ws[0] = s; ws2[0] = s2; }
    }
    __syncthreads();
    float mean = ws[0] * (1.f / Dd);
    float var  = ws2[0] * (1.f / Dd) - mean * mean;
    float inv  = rsqrtf(var + 1e-6f);
    #pragma unroll
    for (int i = 0; i < 2; i++) {
        int c = (threadIdx.x + i * 256) * 4;
        const float4 sv = *(const float4*)(sc + c);
        float4 ov;
        ov.x = (v[i].x - mean) * inv * sv.x;
        ov.y = (v[i].y - mean) * inv * sv.y;
        ov.z = (v[i].z - mean) * inv * sv.z;
        ov.w = (v[i].w - mean) * inv * sv.w;
        *(float4*)(outp + (size_t)row * Dd + c) = ov;
    }
}

// ---------------- FP16 GEMM 128x128x64, 3-stage cp.async ----------------------
#define BM 128
#define BN 128
#define BK 64
#define AS_U 36
#define AS_U32S (BM * AS_U)
#define BS_U32S (BK * 64)
#define STAGE_U (AS_U32S + BS_U32S)
#define NSTG 3

__global__ __launch_bounds__(256, 2) void gemm_f16_kernel(
    const __half* __restrict__ A, const __half* __restrict__ Bw,
    void* __restrict__ Cp, int M, int N, int K, int mode,
    const float* __restrict__ resid)
{
    extern __shared__ uint32_t smu[];
    int row0 = blockIdx.y * BM, col0 = blockIdx.x * BN;
    int t = threadIdx.x;
    int w = t >> 5, l = t & 31;
    int warpM = w >> 1, warpN = w & 1;
    int lr = l >> 2, lc = l & 3;

    const uint4* Au = (const uint4*)A;
    const uint4* Bu = (const uint4*)Bw;
    int K8 = K >> 3, N8 = N >> 3;

    uint32_t smuBase = (uint32_t)__cvta_generic_to_shared(smu);
    int bC0 = (col0 >> 3);

    float acc[2][8][4];
    #pragma unroll
    for (int mf = 0; mf < 2; mf++)
        #pragma unroll
        for (int nf = 0; nf < 8; nf++)
            #pragma unroll
            for (int r = 0; r < 4; r++) acc[mf][nf][r] = 0.f;

    int nk = K / BK;
    // issue copies for chunk range [i0,i1) of tile kt into stage stg (no commit)
    auto issuePart = [&](int kt, int stg, int i0, int i1) {
        if (kt < nk) {
            int k0 = kt * BK;
            uint32_t aBase = smuBase + stg * STAGE_U * 4;
            uint32_t bBase = aBase + AS_U32S * 4;
            #pragma unroll
            for (int i = 0; i < 4; i++) {
                if (i < i0 || i >= i1) continue;
                int idx = i * 256 + t;
                int ar = idx >> 3, ac = idx & 7;
                cpa16(aBase + (ar * AS_U + ac * 4) * 4,
                      Au + (size_t)(row0 + ar) * K8 + (k0 >> 3) + ac);
                int bk = idx >> 4, bc = idx & 15;
                cpa16(bBase + (bk * 64 + ((bc * 4) ^ ((bk & 7) << 2))) * 4,
                      Bu + (size_t)(k0 + bk) * N8 + bC0 + bc);
            }
        }
    };

    issuePart(0, 0, 0, 4); cpa_commit();
    issuePart(1, 1, 0, 4); cpa_commit();

    int aLdsmRow = l & 15;
    int aLdsmCol = (l >> 4) << 2;

    for (int kt = 0; kt < nk; kt++) {
        cpa_wait<1>();
        __syncthreads();

        uint32_t asAddr = smuBase + (kt % NSTG) * STAGE_U * 4;
        uint32_t bsAddr = asAddr + AS_U32S * 4;
        #pragma unroll
        for (int ks = 0; ks < 4; ks++) {
            // spread prefetch of tile kt+2 across the ks loop (commit once)
            if (ks == 1) issuePart(kt + 2, (kt + 2) % NSTG, 0, 2);
            if (ks == 2) { issuePart(kt + 2, (kt + 2) % NSTG, 2, 4); cpa_commit(); }

            uint32_t af[2][4];
            #pragma unroll
            for (int mf = 0; mf < 2; mf++) {
                int r = warpM * 32 + mf * 16;
                ldsm4(af[mf][0], af[mf][1], af[mf][2], af[mf][3],
                      asAddr + ((r + aLdsmRow) * AS_U + ks * 8 + aLdsmCol) * 4);
            }
            #pragma unroll
            for (int nfp = 0; nfp < 4; nfp++) {
                int krow = ks * 16 + (l & 15);
                int col = warpN * 32 + nfp * 8 + ((l >> 4) << 2);
                col ^= (krow & 7) << 2;
                uint32_t b0, b1, b2, b3;
                ldsm4t(b0, b1, b2, b3, bsAddr + (krow * 64 + col) * 4);
                #pragma unroll
                for (int mf = 0; mf < 2; mf++) {
                    mma_f16(acc[mf][2*nfp],   af[mf][0], af[mf][1], af[mf][2], af[mf][3], b0, b1);
                    mma_f16(acc[mf][2*nfp+1], af[mf][0], af[mf][1], af[mf][2], af[mf][3], b2, b3);
                }
            }
        }
    }

    if (mode == 0) {
        int gcol = col0 + warpN * 64;
        int isV = (gcol >= Dd + KVHh * HDd);
        int isK = (gcol >= Dd) && !isV;
        int headIdx;
        if (isV)      headIdx = (gcol - Dd - KVHh * HDd) >> 6;
        else if (isK) headIdx = (gcol - Dd) >> 6;
        else          headIdx = gcol >> 6;
        #pragma unroll
        for (int mf = 0; mf < 2; mf++) {
            #pragma unroll
            for (int half = 0; half < 2; half++) {
                int row = row0 + warpM * 32 + mf * 16 + lr + half * 8;
                int s_ = row & (Ss - 1), b_ = row >> 11;
                __half* dst;
                if (isV)
                    dst = g_v + ((size_t)(b_ * KVHh + headIdx) * Ss + s_) * HDd;
                else if (isK)
                    dst = g_k + ((size_t)(b_ * KVHh + headIdx) * Ss + s_) * HDd;
                else
                    dst = g_q + ((size_t)(b_ * Hh + headIdx) * Ss + s_) * HDd;
                const float* cosb = g_cos + ((size_t)b_ << 16) + (s_ << 5);
                const float* sinb = g_sin + ((size_t)b_ << 16) + (s_ << 5);
                #pragma unroll
                for (int nf = 0; nf < 4; nf++) {
                    int c0 = nf * 8 + 2 * lc;
                    float x1a = clip8(acc[mf][nf][half * 2 + 0]);
                    float x1b = clip8(acc[mf][nf][half * 2 + 1]);
                    float x2a = clip8(acc[mf][nf + 4][half * 2 + 0]);
                    float x2b = clip8(acc[mf][nf + 4][half * 2 + 1]);
                    if (isV) {
                        *(uint32_t*)(dst + c0)      = pkh2(x1a, x1b);
                        *(uint32_t*)(dst + c0 + 32) = pkh2(x2a, x2b);
                    } else {
                        float ca = cosb[c0], cb = cosb[c0 + 1];
                        float sa = sinb[c0], sb = sinb[c0 + 1];
                        *(uint32_t*)(dst + c0) =
                            pkh2(x1a * ca - x2a * sa, x1b * cb - x2b * sb);
                        *(uint32_t*)(dst + c0 + 32) =
                            pkh2(x2a * ca + x1a * sa, x2b * cb + x1b * sb);
                    }
                }
            }
        }
    } else {
        #pragma unroll
        for (int mf = 0; mf < 2; mf++) {
            #pragma unroll
            for (int half = 0; half < 2; half++) {
                int row = row0 + warpM * 32 + mf * 16 + lr + half * 8;
                #pragma unroll
                for (int nf = 0; nf < 8; nf++) {
                    int col = col0 + warpN * 64 + nf * 8 + 2 * lc;
                    size_t off = (size_t)row * N + col;
                    float2 rv = *(const float2*)(resid + off);
                    float2 v;
                    v.x = acc[mf][nf][half * 2 + 0] + rv.x;
                    v.y = acc[mf][nf][half * 2 + 1] + rv.y;
                    *(float2*)((float*)Cp + off) = v;
                }
            }
        }
    }
}

// ---------------- FP16 flash attention, 128-key macro-tiles, 3 stages ----------
#define KS_U 36
#define VS_U 32
#define NAS  3
#define KT_ROWS 128
#define SM_KS 0
#define SM_VS (NAS * KT_ROWS * KS_U)
#define SM_MASK (SM_VS + NAS * KT_ROWS * VS_U)
#define ATT_U32 (SM_MASK + NAS * KT_ROWS)
#define QP_U 36
#define NQT (Ss / 128)
__global__ __launch_bounds__(256, 2) void attn_kernel(const int* __restrict__ amask)
{
    extern __shared__ uint32_t smu[];
    uint32_t* Ps = smu;
    int* maskS = (int*)(smu + SM_MASK);

    int bid = blockIdx.x;
    int qt = (NQT - 1) - (bid >> 6);
    int rem = bid & 63;
    int h = rem >> 1;
    int b = rem & 1;
    int kvh = h >> 2;
    int q0 = qt * 128;
    int t = threadIdx.x;
    int w = t >> 5, l = t & 31;
    int lr = l >> 2, lc = l & 3;

    const uint4* Qg = (const uint4*)(g_q + ((size_t)(b * Hh + h) * Ss + q0) * HDd);
    const uint4* Kg = (const uint4*)(g_k + (size_t)(b * KVHh + kvh) * Ss * HDd);
    const uint4* Vg = (const uint4*)(g_v + (size_t)(b * KVHh + kvh) * Ss * HDd);
    const int*   Mg = amask + b * Ss;

    uint32_t smuBase = (uint32_t)__cvta_generic_to_shared(smu);

    #pragma unroll
    for (int i = 0; i < 4; i++) {
        int idx = i * 256 + t;
        int row = idx >> 3, c = idx & 7;
        *(uint4*)&Ps[row * QP_U + c * 4] = Qg[row * 8 + c];
    }
    __syncthreads();
    uint32_t qa[4][4];
    {
        int r0 = w * 16 + lr;
        #pragma unroll
        for (int ks = 0; ks < 4; ks++) {
            qa[ks][0] = Ps[r0 * QP_U + ks * 8 + lc];
            qa[ks][1] = Ps[(r0 + 8) * QP_U + ks * 8 + lc];
            qa[ks][2] = Ps[r0 * QP_U + ks * 8 + lc + 4];
            qa[ks][3] = Ps[(r0 + 8) * QP_U + ks * 8 + lc + 4];
        }
    }
    __syncthreads();

    int nkt = qt + 1;
    auto issueKV = [&](int kt, int stg) {
        if (kt < nkt) {
            int k0 = kt * KT_ROWS;
            uint32_t kBase = smuBase + (SM_KS + stg * KT_ROWS * KS_U) * 4;
            uint32_t vBase = smuBase + (SM_VS + stg * KT_ROWS * VS_U) * 4;
            #pragma unroll
            for (int i = 0; i < 4; i++) {
                int idx = i * 256 + t;
                int row = idx >> 3, c = idx & 7;
                cpa16(kBase + (row * KS_U + c * 4) * 4, Kg + (k0 + row) * 8 + c);
                cpa16(vBase + (row * VS_U + ((c * 4) ^ ((row & 7) << 2))) * 4,
                      Vg + (k0 + row) * 8 + c);
            }
            if (t < KT_ROWS)
                cpa4(smuBase + (SM_MASK + stg * KT_ROWS + t) * 4, Mg + k0 + t);
        }
        cpa_commit();
    };

    issueKV(0, 0);
    issueKV(1, 1);

    float m0 = -1e30f, m1 = -1e30f, l0 = 0.f, l1 = 0.f;
    float o[8][4];
    #pragma unroll
    for (int nf = 0; nf < 8; nf++)
        #pragma unroll
        for (int r = 0; r < 4; r++) o[nf][r] = 0.f;

    int kLdsmRow = l & 15;
    int kLdsmCol = (l >> 4) << 2;
    int qlow = q0 + w * 16;

    for (int kt = 0; kt < nkt; kt++) {
        cpa_wait<1>();
        __syncthreads();

        int cur = kt % NAS;
        uint32_t kbAddr = smuBase + (SM_KS + cur * KT_ROWS * KS_U) * 4;
        uint32_t vsAddr = smuBase + (SM_VS + cur * KT_ROWS * VS_U) * 4;

        #pragma unroll
        for (int half = 0; half < 2; half++) {
            if (half == 1) issueKV(kt + 2, (kt + 2) % NAS);

            int k0 = kt * KT_ROWS + half * 64;
            if (k0 <= qlow + 15) {
                int rbase = half * 64;
                float s[8][4];
                #pragma unroll
                for (int nf = 0; nf < 8; nf++)
                    #pragma unroll
                    for (int r = 0; r < 4; r++) s[nf][r] = 0.f;
                #pragma unroll
                for (int ks = 0; ks < 4; ks++) {
                    #pragma unroll
                    for (int p = 0; p < 4; p++) {
                        uint32_t b0, b1, b2, b3;
                        ldsm4(b0, b1, b2, b3,
                              kbAddr + ((rbase + p * 16 + kLdsmRow) * KS_U
                                        + ks * 8 + kLdsmCol) * 4);
                        mma_f16(s[2*p],   qa[ks][0], qa[ks][1], qa[ks][2], qa[ks][3], b0, b2);
                        mma_f16(s[2*p+1], qa[ks][0], qa[ks][1], qa[ks][2], qa[ks][3], b1, b3);
                    }
                }
                int qr0 = qlow + lr, qr1 = qr0 + 8;
                bool fullvis = (k0 + 63 <= qlow);
                int mbase = cur * KT_ROWS + rbase;
                #pragma unroll
                for (int nf = 0; nf < 8; nf++) {
                    int kg0 = k0 + nf * 8 + 2 * lc;
                    int ms0 = maskS[mbase + nf * 8 + 2 * lc];
                    int ms1 = maskS[mbase + nf * 8 + 2 * lc + 1];
                    s[nf][0] = (ms0 && (fullvis || kg0     <= qr0)) ? s[nf][0] * ATT_SCALE : -1e30f;
                    s[nf][1] = (ms1 && (fullvis || kg0 + 1 <= qr0)) ? s[nf][1] * ATT_SCALE : -1e30f;
                    s[nf][2] = (ms0 && (fullvis || kg0     <= qr1)) ? s[nf][2] * ATT_SCALE : -1e30f;
                    s[nf][3] = (ms1 && (fullvis || kg0 + 1 <= qr1)) ? s[nf][3] * ATT_SCALE : -1e30f;
                }
                float mt0 = -1e30f, mt1 = -1e30f;
                #pragma unroll
                for (int nf = 0; nf < 8; nf++) {
                    mt0 = fmaxf(mt0, fmaxf(s[nf][0], s[nf][1]));
                    mt1 = fmaxf(mt1, fmaxf(s[nf][2], s[nf][3]));
                }
                mt0 = fmaxf(mt0, __shfl_xor_sync(0xffffffffu, mt0, 1));
                mt0 = fmaxf(mt0, __shfl_xor_sync(0xffffffffu, mt0, 2));
                mt1 = fmaxf(mt1, __shfl_xor_sync(0xffffffffu, mt1, 1));
                mt1 = fmaxf(mt1, __shfl_xor_sync(0xffffffffu, mt1, 2));
                float mn0 = fmaxf(m0, mt0), mn1 = fmaxf(m1, mt1);
                float rs0 = 0.f, rs1 = 0.f;
                #pragma unroll
                for (int nf = 0; nf < 8; nf++) {
                    s[nf][0] = __expf(s[nf][0] - mn0);
                    s[nf][1] = __expf(s[nf][1] - mn0);
                    s[nf][2] = __expf(s[nf][2] - mn1);
                    s[nf][3] = __expf(s[nf][3] - mn1);
                    rs0 += s[nf][0] + s[nf][1];
                    rs1 += s[nf][2] + s[nf][3];
                }
                rs0 += __shfl_xor_sync(0xffffffffu, rs0, 1);
                rs0 += __shfl_xor_sync(0xffffffffu, rs0, 2);
                rs1 += __shfl_xor_sync(0xffffffffu, rs1, 1);
                rs1 += __shfl_xor_sync(0xffffffffu, rs1, 2);
                float a0 = __expf(m0 - mn0), a1 = __expf(m1 - mn1);
                l0 = l0 * a0 + rs0;  l1 = l1 * a1 + rs1;
                m0 = mn0;  m1 = mn1;
                #pragma unroll
                for (int nf = 0; nf < 8; nf++) {
                    o[nf][0] *= a0; o[nf][1] *= a0;
                    o[nf][2] *= a1; o[nf][3] *= a1;
                }
                #pragma unroll
                for (int ks = 0; ks < 4; ks++) {
                    uint32_t pa0 = pkh2(s[2*ks][0],   s[2*ks][1]);
                    uint32_t pa1 = pkh2(s[2*ks][2],   s[2*ks][3]);
                    uint32_t pa2 = pkh2(s[2*ks+1][0], s[2*ks+1][1]);
                    uint32_t pa3 = pkh2(s[2*ks+1][2], s[2*ks+1][3]);
                    #pragma unroll
                    for (int nfp = 0; nfp < 4; nfp++) {
                        int key = rbase + ks * 16 + (l & 15);
                        int col = nfp * 8 + ((l >> 4) << 2);
                        col ^= (key & 7) << 2;
                        uint32_t b0, b1, b2, b3;
                        ldsm4t(b0, b1, b2, b3, vsAddr + (key * VS_U + col) * 4);
                        mma_f16(o[2*nfp],   pa0, pa1, pa2, pa3, b0, b1);
                        mma_f16(o[2*nfp+1], pa0, pa1, pa2, pa3, b2, b3);
                    }
                }
            }
        }
    }

    float il0 = (l0 > 0.f) ? (1.f / l0) : 0.f;
    float il1 = (l1 > 0.f) ? (1.f / l1) : 0.f;
    int qr0 = q0 + w * 16 + lr;
    __half* d0 = g_attn + (size_t)(b * Ss + qr0) * Dd + h * HDd;
    __half* d1 = g_attn + (size_t)(b * Ss + qr0 + 8) * Dd + h * HDd;
    #pragma unroll
    for (int nf = 0; nf < 8; nf++) {
        int c = nf * 8 + 2 * lc;
        *(uint32_t*)(d0 + c) = pkh2(o[nf][0] * il0, o[nf][1] * il0);
        *(uint32_t*)(d1 + c) = pkh2(o[nf][2] * il1, o[nf][3] * il1);
    }
}

// ---------------- launch ------------------------------------------------------
extern "C" void kernel_launch(void* const* d_in, const int* in_sizes, int n_in,
                              void* d_out, int out_size)
{
    const float* hs   = (const float*)d_in[0];
    const int*   am   = (const int*)  d_in[1];
    const int*   pid  = (const int*)  d_in[2];
    const float* ln1  = (const float*)d_in[4];
    const float* wqkv = (const float*)d_in[5];
    const float* wout = (const float*)d_in[6];
    const float* ln2  = (const float*)d_in[7];
    float* out = (float*)d_out;

    __half *px, *pattn, *pwq, *pwo;
    cudaGetSymbolAddress((void**)&px,    g_x);
    cudaGetSymbolAddress((void**)&pattn, g_attn);
    cudaGetSymbolAddress((void**)&pwq,   g_wqkvh);
    cudaGetSymbolAddress((void**)&pwo,   g_wouth);

    const int ATTN_SMEM = ATT_U32 * 4;
    cudaFuncSetAttribute(attn_kernel,
                         cudaFuncAttributeMaxDynamicSharedMemorySize, ATTN_SMEM);
    const int GEMM_SMEM = NSTG * STAGE_U * 4;
    cudaFuncSetAttribute(gemm_f16_kernel,
                         cudaFuncAttributeMaxDynamicSharedMemorySize, GEMM_SMEM);

    prep_kernel<<<Mrows + 512 + NCVT, 256>>>(hs, ln1, pid, wqkv, wout);
    gemm_f16_kernel<<<dim3(QKVN / BN, Mrows / BM), 256, GEMM_SMEM>>>(
        px, pwq, nullptr, Mrows, QKVN, Dd, 0, nullptr);
    attn_kernel<<<NQT * Hh * Bb, 256, ATTN_SMEM>>>(am);
    gemm_f16_kernel<<<dim3(Dd / BN, Mrows / BM), 256, GEMM_SMEM>>>(
        pattn, pwo, out, Mrows, Dd, Dd, 1, hs);
    ln_kernel<<<Mrows, 256>>>(out, ln2, out + OUTOFF);
}